// round 8
// baseline (speedup 1.0000x reference)
#include <cuda_runtime.h>
#include <cuda_bf16.h>
#include <cstdint>

// Problem shape (fixed by the dataset)
#define BATCH 2
#define SEQ   2048
#define DIM   1024
#define NHEAD 16
#define DHEAD 64
#define MROWS (BATCH * SEQ)          // 4096
#define NQKV  (3 * DIM)              // 3072
#define KTOT  1024

// ---------------------------------------------------------------------------
// Scratch (allocation-free rule: __device__ globals), all bf16 split-2 pairs
// ---------------------------------------------------------------------------
__device__ __nv_bfloat16 s_a_hi[MROWS * KTOT];   // GEMM A: x, then attention out
__device__ __nv_bfloat16 s_a_lo[MROWS * KTOT];
__device__ __nv_bfloat16 s_wq_hi[NQKV * KTOT];   // w_attn^T [3072,1024]
__device__ __nv_bfloat16 s_wq_lo[NQKV * KTOT];
__device__ __nv_bfloat16 s_wp_hi[DIM * KTOT];    // w_proj^T [1024,1024]
__device__ __nv_bfloat16 s_wp_lo[DIM * KTOT];
// attention operands, written by QKV epilogue
__device__ __nv_bfloat16 s_q_hi[BATCH * NHEAD * SEQ * DHEAD];  // [bh,s,dh], q*0.125
__device__ __nv_bfloat16 s_q_lo[BATCH * NHEAD * SEQ * DHEAD];
__device__ __nv_bfloat16 s_k_hi[BATCH * NHEAD * SEQ * DHEAD];  // [bh,s,dh]
__device__ __nv_bfloat16 s_k_lo[BATCH * NHEAD * SEQ * DHEAD];
__device__ __nv_bfloat16 s_vt_hi[BATCH * NHEAD * DHEAD * SEQ]; // [bh,dh,s]
__device__ __nv_bfloat16 s_vt_lo[BATCH * NHEAD * DHEAD * SEQ];

// ---------------------------------------------------------------------------
// PTX helpers (baseline ISA — compiles for sm_103)
// ---------------------------------------------------------------------------
__device__ __forceinline__ uint32_t smem_u32(const void* p) {
    uint32_t a;
    asm("{ .reg .u64 t; cvta.to.shared.u64 t, %1; cvt.u32.u64 %0, t; }"
        : "=r"(a) : "l"(p));
    return a;
}
__device__ __forceinline__ void ldsm4(uint32_t addr, uint32_t& r0, uint32_t& r1,
                                      uint32_t& r2, uint32_t& r3) {
    asm volatile("ldmatrix.sync.aligned.m8n8.x4.shared.b16 {%0,%1,%2,%3}, [%4];"
                 : "=r"(r0), "=r"(r1), "=r"(r2), "=r"(r3) : "r"(addr));
}
__device__ __forceinline__ void mma_bf16(float& c0, float& c1, float& c2, float& c3,
                                         uint32_t a0, uint32_t a1, uint32_t a2, uint32_t a3,
                                         uint32_t b0, uint32_t b1) {
    asm volatile("mma.sync.aligned.m16n8k16.row.col.f32.bf16.bf16.f32 "
                 "{%0,%1,%2,%3}, {%4,%5,%6,%7}, {%8,%9}, {%0,%1,%2,%3};"
                 : "+f"(c0), "+f"(c1), "+f"(c2), "+f"(c3)
                 : "r"(a0), "r"(a1), "r"(a2), "r"(a3), "r"(b0), "r"(b1));
}
__device__ __forceinline__ void cp16(uint32_t saddr, const void* g) {
    asm volatile("cp.async.cg.shared.global [%0], [%1], 16;"
                 :: "r"(saddr), "l"(g) : "memory");
}
__device__ __forceinline__ void cp_commit() {
    asm volatile("cp.async.commit_group;" ::: "memory");
}
template <int N>
__device__ __forceinline__ void cp_wait() {
    asm volatile("cp.async.wait_group %0;" :: "n"(N) : "memory");
}
__device__ __forceinline__ void split2(float v, __nv_bfloat16& h, __nv_bfloat16& l) {
    h = __float2bfloat16_rn(v);
    l = __float2bfloat16_rn(v - __bfloat162float(h));
}
__device__ __forceinline__ uint32_t packbf(__nv_bfloat16 a, __nv_bfloat16 b) {
    return (uint32_t)__bfloat16_as_ushort(a) | ((uint32_t)__bfloat16_as_ushort(b) << 16);
}

// ---------------------------------------------------------------------------
// Prep kernels
// ---------------------------------------------------------------------------
__global__ __launch_bounds__(256) void split_kernel(
    const float* __restrict__ src, __nv_bfloat16* __restrict__ hi,
    __nv_bfloat16* __restrict__ lo, int n4)
{
    int i = blockIdx.x * 256 + threadIdx.x;
    if (i >= n4) return;
    float4 v = ((const float4*)src)[i];
    __nv_bfloat16 h0, l0, h1, l1, h2, l2, h3, l3;
    split2(v.x, h0, l0); split2(v.y, h1, l1);
    split2(v.z, h2, l2); split2(v.w, h3, l3);
    uint2 uh = make_uint2(packbf(h0, h1), packbf(h2, h3));
    uint2 ul = make_uint2(packbf(l0, l1), packbf(l2, l3));
    *(uint2*)(hi + (size_t)i * 4) = uh;
    *(uint2*)(lo + (size_t)i * 4) = ul;
}

__global__ __launch_bounds__(256) void transp_split_kernel(
    const float* __restrict__ w, int K, int N,
    __nv_bfloat16* __restrict__ out_hi, __nv_bfloat16* __restrict__ out_lo)
{
    __shared__ float t[32][33];
    const int tx = threadIdx.x, ty = threadIdx.y;
    const int n0 = blockIdx.x * 32, k0 = blockIdx.y * 32;
#pragma unroll
    for (int i = 0; i < 4; ++i)
        t[ty + i * 8][tx] = w[(size_t)(k0 + ty + i * 8) * N + n0 + tx];
    __syncthreads();
#pragma unroll
    for (int i = 0; i < 4; ++i) {
        const int n = n0 + ty + i * 8;
        float v = t[tx][ty + i * 8];
        __nv_bfloat16 h, l;
        split2(v, h, l);
        out_hi[(size_t)n * K + k0 + tx] = h;
        out_lo[(size_t)n * K + k0 + tx] = l;
    }
}

// ---------------------------------------------------------------------------
// HMMA GEMM, 512 threads, 3-stage cp.async pipeline, 1 barrier/iter.
// D[M,N] = A @ B^T + bias, bf16 split-2 (3 products, fp32 accum).
// 16 warps (4x4), warp tile 32x32.
// mode 0: QKV epilogue -> bf16 split q/k (k-major) and vt (transposed)
// mode 1: plain fp32 out
// ---------------------------------------------------------------------------
#define BM 128
#define BN 128
#define BK 32
#define ROWB 80
#define NKT (KTOT / BK)          // 32
#define OFF_ALO 10240
#define OFF_BHI 20480
#define OFF_BLO 30720
#define STG_BYTES 40960
#define NSTAGE 3
#define GSM_BYTES (NSTAGE * STG_BYTES)   // 122880

__global__ __launch_bounds__(512, 1) void tc_gemm_kernel(
    const __nv_bfloat16* __restrict__ Ahi, const __nv_bfloat16* __restrict__ Alo,
    const __nv_bfloat16* __restrict__ Bhi, const __nv_bfloat16* __restrict__ Blo,
    const float* __restrict__ bias, float* __restrict__ outp, int mode)
{
    extern __shared__ char gsm[];
    const uint32_t sb = smem_u32(gsm);

    const int tid  = threadIdx.x;
    const int w    = tid >> 5;
    const int lane = tid & 31;
    const int m0 = blockIdx.y * BM;
    const int n0 = blockIdx.x * BN;
    const int wm = (w >> 2) * 32;      // 4 warp-rows x 32
    const int wn = (w & 3) * 32;       // 4 warp-cols x 32

    // global staging: 512 threads, each thread one 16B seg of one row per buffer
    const int srow = tid >> 2;         // 0..127
    const int sseg = tid & 3;          // 0..3
    const size_t gA = (size_t)(m0 + srow) * KTOT + sseg * 8;
    const size_t gB = (size_t)(n0 + srow) * KTOT + sseg * 8;
    const uint32_t soff = (uint32_t)(srow * ROWB + sseg * 16);

    auto load_stage = [&](int kt, int stg) {
        const uint32_t s0 = sb + stg * STG_BYTES;
        cp16(s0 + soff,           Ahi + gA + (size_t)kt * BK);
        cp16(s0 + OFF_ALO + soff, Alo + gA + (size_t)kt * BK);
        cp16(s0 + OFF_BHI + soff, Bhi + gB + (size_t)kt * BK);
        cp16(s0 + OFF_BLO + soff, Blo + gB + (size_t)kt * BK);
    };

    float acc[2][4][4];
#pragma unroll
    for (int i = 0; i < 2; ++i)
#pragma unroll
        for (int j = 0; j < 4; ++j)
#pragma unroll
            for (int e = 0; e < 4; ++e) acc[i][j][e] = 0.f;

    const int ar = lane & 15, ah = lane >> 4;
    const uint32_t aoffb = (uint32_t)((wm + ar) * ROWB + ah * 16);
    const int grp = lane >> 3, l8 = lane & 7;
    const uint32_t boffb = (uint32_t)((wn + ((grp >> 1) << 3) + l8) * ROWB + (grp & 1) * 16);

    load_stage(0, 0);
    cp_commit();
    load_stage(1, 1);
    cp_commit();

    int stg = 0;
    for (int kt = 0; kt < NKT; ++kt) {
        if (kt + 1 < NKT) cp_wait<1>(); else cp_wait<0>();
        __syncthreads();

        if (kt + 2 < NKT) {
            int s2 = stg + 2; if (s2 >= NSTAGE) s2 -= NSTAGE;
            load_stage(kt + 2, s2);
            cp_commit();
        }

        const uint32_t s0 = sb + stg * STG_BYTES;
#pragma unroll
        for (int ks = 0; ks < 2; ++ks) {
            const uint32_t akoff = s0 + aoffb + ks * 32;
            const uint32_t bkoff = s0 + OFF_BHI + boffb + ks * 32;

            uint32_t fah[2][4], fal[2][4];
#pragma unroll
            for (int mt = 0; mt < 2; ++mt) {
                ldsm4(akoff + mt * 16 * ROWB,
                      fah[mt][0], fah[mt][1], fah[mt][2], fah[mt][3]);
                ldsm4(akoff + OFF_ALO + mt * 16 * ROWB,
                      fal[mt][0], fal[mt][1], fal[mt][2], fal[mt][3]);
            }
            uint32_t fbh[8], fbl[8];
            ldsm4(bkoff,                         fbh[0], fbh[1], fbh[2], fbh[3]);
            ldsm4(bkoff + 16 * ROWB,             fbh[4], fbh[5], fbh[6], fbh[7]);
            ldsm4(bkoff + (OFF_BLO - OFF_BHI),   fbl[0], fbl[1], fbl[2], fbl[3]);
            ldsm4(bkoff + (OFF_BLO - OFF_BHI) + 16 * ROWB,
                                                 fbl[4], fbl[5], fbl[6], fbl[7]);

#pragma unroll
            for (int mt = 0; mt < 2; ++mt) {
#pragma unroll
                for (int nt = 0; nt < 4; ++nt) {
                    float* c = acc[mt][nt];
                    mma_bf16(c[0], c[1], c[2], c[3],
                             fah[mt][0], fah[mt][1], fah[mt][2], fah[mt][3],
                             fbh[nt * 2], fbh[nt * 2 + 1]);
                    mma_bf16(c[0], c[1], c[2], c[3],
                             fah[mt][0], fah[mt][1], fah[mt][2], fah[mt][3],
                             fbl[nt * 2], fbl[nt * 2 + 1]);
                    mma_bf16(c[0], c[1], c[2], c[3],
                             fal[mt][0], fal[mt][1], fal[mt][2], fal[mt][3],
                             fbh[nt * 2], fbh[nt * 2 + 1]);
                }
            }
        }
        if (++stg >= NSTAGE) stg = 0;
    }

    // epilogue
    const int erow = (lane >> 2);
    const int ecol = (lane & 3) * 2;
#pragma unroll
    for (int mt = 0; mt < 2; ++mt) {
#pragma unroll
        for (int nt = 0; nt < 4; ++nt) {
#pragma unroll
            for (int half = 0; half < 2; ++half) {
                const int row = m0 + wm + mt * 16 + erow + half * 8;
                const int col = n0 + wn + nt * 8 + ecol;
                float v0 = acc[mt][nt][half * 2 + 0] + bias[col];
                float v1 = acc[mt][nt][half * 2 + 1] + bias[col + 1];
                if (mode == 0) {
                    const int bb = row >> 11, s = row & 2047;
                    const int part = col >> 10;
                    const int dd = col & 1023;
                    const int h = dd >> 6, hd = dd & 63;
                    const int bh = (bb << 4) + h;
                    if (part == 0) { v0 *= 0.125f; v1 *= 0.125f; }
                    __nv_bfloat16 h0, l0, h1, l1;
                    split2(v0, h0, l0); split2(v1, h1, l1);
                    if (part == 2) {
                        const size_t base = ((size_t)bh * DHEAD + hd) * SEQ + s;
                        s_vt_hi[base] = h0;       s_vt_lo[base] = l0;
                        s_vt_hi[base + SEQ] = h1; s_vt_lo[base + SEQ] = l1;
                    } else {
                        const size_t base = ((size_t)bh * SEQ + s) * DHEAD + hd;
                        __nv_bfloat16* dh_ = (part == 0) ? s_q_hi : s_k_hi;
                        __nv_bfloat16* dl_ = (part == 0) ? s_q_lo : s_k_lo;
                        *(uint32_t*)(dh_ + base) = packbf(h0, h1);
                        *(uint32_t*)(dl_ + base) = packbf(l0, l1);
                    }
                } else {
                    *(float2*)(outp + (size_t)row * DIM + col) = make_float2(v0, v1);
                }
            }
        }
    }
}

// ---------------------------------------------------------------------------
// Tensor-core flash attention (bf16 split-2, fp32 softmax) with cp.async
// 2-stage KV pipeline. CTA: 128 q rows x one (b,h); 4 warps; KV tiles of 64.
// R8 change: allow 2 CTAs/SM.
// ---------------------------------------------------------------------------
#define AROWB 144
#define AQ_H 0
#define AQ_L 18432
#define AKV0 36864
#define AKV_STG 36864
#define AK_L 9216
#define AV_H 18432
#define AV_L 27648
#define ASM_BYTES (AKV0 + 2 * AKV_STG)   // 110592

__global__ __launch_bounds__(128, 2) void attn_tc_kernel()
{
    extern __shared__ char asmem[];
    const uint32_t sb = smem_u32(asmem);
    const int tid  = threadIdx.x;
    const int w    = tid >> 5;
    const int lane = tid & 31;
    const int qt   = blockIdx.x;
    const int bh   = blockIdx.y;
    const int q0   = qt * 128;

    const __nv_bfloat16* Qh = s_q_hi + (size_t)bh * SEQ * DHEAD;
    const __nv_bfloat16* Ql = s_q_lo + (size_t)bh * SEQ * DHEAD;
    const __nv_bfloat16* Kh = s_k_hi + (size_t)bh * SEQ * DHEAD;
    const __nv_bfloat16* Kl = s_k_lo + (size_t)bh * SEQ * DHEAD;
    const __nv_bfloat16* Vh = s_vt_hi + (size_t)bh * DHEAD * SEQ;
    const __nv_bfloat16* Vl = s_vt_lo + (size_t)bh * DHEAD * SEQ;

    auto load_kv = [&](int kt, int stg) {
        const uint32_t s0 = sb + AKV0 + stg * AKV_STG;
        const int kv0 = kt * 64;
#pragma unroll
        for (int i = 0; i < 4; ++i) {
            const int c = tid + i * 128;
            const int row = c >> 3, seg = c & 7;
            const uint32_t so = row * AROWB + seg * 16;
            const size_t gk = (size_t)(kv0 + row) * DHEAD + seg * 8;
            const size_t gv = (size_t)row * SEQ + kv0 + seg * 8;
            cp16(s0 + so, Kh + gk);
            cp16(s0 + AK_L + so, Kl + gk);
            cp16(s0 + AV_H + so, Vh + gv);
            cp16(s0 + AV_L + so, Vl + gv);
        }
    };

    // Q tile (128 rows x 64 bf16) hi/lo — plain stores, covered by first barrier
#pragma unroll
    for (int i = 0; i < 8; ++i) {
        const int c = tid + i * 128;
        const int row = c >> 3, seg = c & 7;
        const uint32_t so = row * AROWB + seg * 16;
        const size_t go = (size_t)(q0 + row) * DHEAD + seg * 8;
        *(uint4*)(asmem + AQ_H + so) = *(const uint4*)(Qh + go);
        *(uint4*)(asmem + AQ_L + so) = *(const uint4*)(Ql + go);
    }

    const int ar = lane & 15, ahh = lane >> 4;
    const int grp = lane >> 3, l8 = lane & 7;
    const int row0 = lane >> 2, coll = (lane & 3) * 2;

    float m_run[4], l_run[4];
#pragma unroll
    for (int i = 0; i < 4; ++i) { m_run[i] = -1e30f; l_run[i] = 0.f; }
    float oacc[2][8][4];
#pragma unroll
    for (int mt = 0; mt < 2; ++mt)
#pragma unroll
        for (int nt = 0; nt < 8; ++nt)
#pragma unroll
            for (int e = 0; e < 4; ++e) oacc[mt][nt][e] = 0.f;

    const int ntiles = qt * 2 + 2;
    load_kv(0, 0);
    cp_commit();

    for (int kt = 0; kt < ntiles; ++kt) {
        if (kt + 1 < ntiles) {
            load_kv(kt + 1, (kt + 1) & 1);
            cp_commit();
            cp_wait<1>();
        } else {
            cp_wait<0>();
        }
        __syncthreads();

        const uint32_t kvb = sb + AKV0 + (kt & 1) * AKV_STG;
        const int kv0 = kt * 64;

        // ---- scores: S = Q K^T (split-2) ----
        float s[2][8][4];
#pragma unroll
        for (int mt = 0; mt < 2; ++mt)
#pragma unroll
            for (int nt = 0; nt < 8; ++nt)
#pragma unroll
                for (int e = 0; e < 4; ++e) s[mt][nt][e] = 0.f;

#pragma unroll
        for (int ks = 0; ks < 4; ++ks) {
            uint32_t kbh[4][4], kbl[4][4];
#pragma unroll
            for (int nb = 0; nb < 4; ++nb) {
                const uint32_t bo = (uint32_t)(((grp >> 1) * 8 + l8 + nb * 16) * AROWB +
                                               (grp & 1) * 16 + ks * 32);
                ldsm4(kvb + bo, kbh[nb][0], kbh[nb][1], kbh[nb][2], kbh[nb][3]);
                ldsm4(kvb + AK_L + bo, kbl[nb][0], kbl[nb][1], kbl[nb][2], kbl[nb][3]);
            }
#pragma unroll
            for (int mt = 0; mt < 2; ++mt) {
                const uint32_t ao = (uint32_t)((w * 32 + mt * 16 + ar) * AROWB +
                                               ahh * 16 + ks * 32);
                uint32_t qh0, qh1, qh2, qh3, ql0, ql1, ql2, ql3;
                ldsm4(sb + AQ_H + ao, qh0, qh1, qh2, qh3);
                ldsm4(sb + AQ_L + ao, ql0, ql1, ql2, ql3);
#pragma unroll
                for (int nt = 0; nt < 8; ++nt) {
                    float* c = s[mt][nt];
                    const int nb = nt >> 1, p = nt & 1;
                    mma_bf16(c[0], c[1], c[2], c[3], qh0, qh1, qh2, qh3,
                             kbh[nb][p * 2], kbh[nb][p * 2 + 1]);
                    mma_bf16(c[0], c[1], c[2], c[3], qh0, qh1, qh2, qh3,
                             kbl[nb][p * 2], kbl[nb][p * 2 + 1]);
                    mma_bf16(c[0], c[1], c[2], c[3], ql0, ql1, ql2, ql3,
                             kbh[nb][p * 2], kbh[nb][p * 2 + 1]);
                }
            }
        }

        // ---- causal mask ----
        if (kt >= qt * 2) {
#pragma unroll
            for (int mt = 0; mt < 2; ++mt) {
                const int rbase = q0 + w * 32 + mt * 16 + row0;
#pragma unroll
                for (int nt = 0; nt < 8; ++nt) {
                    const int cb = kv0 + nt * 8 + coll;
                    if (cb > rbase)     s[mt][nt][0] = -10000.f;
                    if (cb + 1 > rbase) s[mt][nt][1] = -10000.f;
                    if (cb > rbase + 8)     s[mt][nt][2] = -10000.f;
                    if (cb + 1 > rbase + 8) s[mt][nt][3] = -10000.f;
                }
            }
        }

        // ---- online softmax ----
        float corr[4];
#pragma unroll
        for (int slot = 0; slot < 4; ++slot) {
            const int mt = slot >> 1, h2 = slot & 1;
            float tm = -1e30f;
#pragma unroll
            for (int nt = 0; nt < 8; ++nt)
                tm = fmaxf(tm, fmaxf(s[mt][nt][h2 * 2], s[mt][nt][h2 * 2 + 1]));
            tm = fmaxf(tm, __shfl_xor_sync(0xffffffffu, tm, 1));
            tm = fmaxf(tm, __shfl_xor_sync(0xffffffffu, tm, 2));
            const float mnew = fmaxf(m_run[slot], tm);
            corr[slot] = __expf(m_run[slot] - mnew);
            m_run[slot] = mnew;
            l_run[slot] *= corr[slot];
        }
#pragma unroll
        for (int mt = 0; mt < 2; ++mt)
#pragma unroll
            for (int nt = 0; nt < 8; ++nt) {
                oacc[mt][nt][0] *= corr[mt * 2];
                oacc[mt][nt][1] *= corr[mt * 2];
                oacc[mt][nt][2] *= corr[mt * 2 + 1];
                oacc[mt][nt][3] *= corr[mt * 2 + 1];
            }

        // ---- P = exp(S - m), split-2 pack into A fragments ----
        uint32_t ph[2][8][2], pl[2][8][2];
#pragma unroll
        for (int mt = 0; mt < 2; ++mt)
#pragma unroll
            for (int nt = 0; nt < 8; ++nt) {
                const float p0 = __expf(s[mt][nt][0] - m_run[mt * 2]);
                const float p1 = __expf(s[mt][nt][1] - m_run[mt * 2]);
                const float p2 = __expf(s[mt][nt][2] - m_run[mt * 2 + 1]);
                const float p3 = __expf(s[mt][nt][3] - m_run[mt * 2 + 1]);
                l_run[mt * 2]     += p0 + p1;
                l_run[mt * 2 + 1] += p2 + p3;
                __nv_bfloat16 h0, lo0, h1, lo1, h2, lo2, h3, lo3;
                split2(p0, h0, lo0); split2(p1, h1, lo1);
                split2(p2, h2, lo2); split2(p3, h3, lo3);
                ph[mt][nt][0] = packbf(h0, h1);   ph[mt][nt][1] = packbf(h2, h3);
                pl[mt][nt][0] = packbf(lo0, lo1); pl[mt][nt][1] = packbf(lo2, lo3);
            }

        // ---- O += P V (split-2) ----
#pragma unroll
        for (int ks = 0; ks < 4; ++ks) {
            uint32_t vbh[4][4], vbl[4][4];
#pragma unroll
            for (int nb = 0; nb < 4; ++nb) {
                const uint32_t bo = (uint32_t)(((grp >> 1) * 8 + l8 + nb * 16) * AROWB +
                                               (grp & 1) * 16 + ks * 32);
                ldsm4(kvb + AV_H + bo, vbh[nb][0], vbh[nb][1], vbh[nb][2], vbh[nb][3]);
                ldsm4(kvb + AV_L + bo, vbl[nb][0], vbl[nb][1], vbl[nb][2], vbl[nb][3]);
            }
#pragma unroll
            for (int mt = 0; mt < 2; ++mt) {
                const uint32_t a0h = ph[mt][ks * 2][0],     a1h = ph[mt][ks * 2][1];
                const uint32_t a2h = ph[mt][ks * 2 + 1][0], a3h = ph[mt][ks * 2 + 1][1];
                const uint32_t a0l = pl[mt][ks * 2][0],     a1l = pl[mt][ks * 2][1];
                const uint32_t a2l = pl[mt][ks * 2 + 1][0], a3l = pl[mt][ks * 2 + 1][1];
#pragma unroll
                for (int nt = 0; nt < 8; ++nt) {
                    float* c = oacc[mt][nt];
                    const int nb = nt >> 1, p = nt & 1;
                    mma_bf16(c[0], c[1], c[2], c[3], a0h, a1h, a2h, a3h,
                             vbh[nb][p * 2], vbh[nb][p * 2 + 1]);
                    mma_bf16(c[0], c[1], c[2], c[3], a0h, a1h, a2h, a3h,
                             vbl[nb][p * 2], vbl[nb][p * 2 + 1]);
                    mma_bf16(c[0], c[1], c[2], c[3], a0l, a1l, a2l, a3l,
                             vbh[nb][p * 2], vbh[nb][p * 2 + 1]);
                }
            }
        }
        __syncthreads();
    }

    // ---- finalize ----
    float inv[4];
#pragma unroll
    for (int slot = 0; slot < 4; ++slot) {
        float lt = l_run[slot];
        lt += __shfl_xor_sync(0xffffffffu, lt, 1);
        lt += __shfl_xor_sync(0xffffffffu, lt, 2);
        inv[slot] = 1.f / lt;
    }
    const int b = bh >> 4, h = bh & 15;
#pragma unroll
    for (int mt = 0; mt < 2; ++mt) {
#pragma unroll
        for (int half = 0; half < 2; ++half) {
            const size_t orow = (size_t)b * SEQ + q0 + w * 32 + mt * 16 + row0 + half * 8;
            const float iv = inv[mt * 2 + half];
#pragma unroll
            for (int nt = 0; nt < 8; ++nt) {
                const int col = h * DHEAD + nt * 8 + coll;
                const float v0 = oacc[mt][nt][half * 2 + 0] * iv;
                const float v1 = oacc[mt][nt][half * 2 + 1] * iv;
                __nv_bfloat16 h0, l0, h1, l1;
                split2(v0, h0, l0); split2(v1, h1, l1);
                *(uint32_t*)(s_a_hi + orow * DIM + col) = packbf(h0, h1);
                *(uint32_t*)(s_a_lo + orow * DIM + col) = packbf(l0, l1);
            }
        }
    }
}

// ---------------------------------------------------------------------------
extern "C" void kernel_launch(void* const* d_in, const int* in_sizes, int n_in,
                              void* d_out, int out_size)
{
    const float* x      = (const float*)d_in[0];
    const float* w_attn = (const float*)d_in[1];
    const float* b_attn = (const float*)d_in[2];
    const float* w_proj = (const float*)d_in[3];
    const float* b_proj = (const float*)d_in[4];
    float* out = (float*)d_out;

    __nv_bfloat16 *xa_hi, *xa_lo, *wq_hi, *wq_lo, *wp_hi, *wp_lo;
    cudaGetSymbolAddress((void**)&xa_hi, s_a_hi);
    cudaGetSymbolAddress((void**)&xa_lo, s_a_lo);
    cudaGetSymbolAddress((void**)&wq_hi, s_wq_hi);
    cudaGetSymbolAddress((void**)&wq_lo, s_wq_lo);
    cudaGetSymbolAddress((void**)&wp_hi, s_wp_hi);
    cudaGetSymbolAddress((void**)&wp_lo, s_wp_lo);

    cudaFuncSetAttribute(tc_gemm_kernel,
                         cudaFuncAttributeMaxDynamicSharedMemorySize, GSM_BYTES);
    cudaFuncSetAttribute(attn_tc_kernel,
                         cudaFuncAttributeMaxDynamicSharedMemorySize, ASM_BYTES);

    // 1) split x -> bf16 hi/lo
    split_kernel<<<(MROWS * KTOT / 4 + 255) / 256, 256>>>(x, xa_hi, xa_lo, MROWS * KTOT / 4);
    // 2) transpose+split weights
    transp_split_kernel<<<dim3(NQKV / 32, KTOT / 32), dim3(32, 8)>>>(w_attn, KTOT, NQKV, wq_hi, wq_lo);
    transp_split_kernel<<<dim3(DIM / 32, KTOT / 32), dim3(32, 8)>>>(w_proj, KTOT, DIM, wp_hi, wp_lo);
    // 3) QKV GEMM -> bf16 split q/k/vt
    tc_gemm_kernel<<<dim3(NQKV / BN, MROWS / BM), 512, GSM_BYTES>>>(
        xa_hi, xa_lo, wq_hi, wq_lo, b_attn, nullptr, 0);
    // 4) tensor-core flash attention -> writes s_a_hi/s_a_lo
    attn_tc_kernel<<<dim3(SEQ / 128, BATCH * NHEAD), 128, ASM_BYTES>>>();
    // 5) output projection
    tc_gemm_kernel<<<dim3(DIM / BN, MROWS / BM), 512, GSM_BYTES>>>(
        xa_hi, xa_lo, wp_hi, wp_lo, b_proj, out, 1);
}

// round 9
// speedup vs baseline: 1.0557x; 1.0557x over previous
#include <cuda_runtime.h>
#include <cuda_bf16.h>
#include <cstdint>

// Problem shape (fixed by the dataset)
#define BATCH 2
#define SEQ   2048
#define DIM   1024
#define NHEAD 16
#define DHEAD 64
#define MROWS (BATCH * SEQ)          // 4096
#define NQKV  (3 * DIM)              // 3072
#define KTOT  1024

// ---------------------------------------------------------------------------
// Scratch (allocation-free rule: __device__ globals), all bf16 split-2 pairs
// ---------------------------------------------------------------------------
__device__ __nv_bfloat16 s_a_hi[MROWS * KTOT];   // GEMM A: x, then attention out
__device__ __nv_bfloat16 s_a_lo[MROWS * KTOT];
__device__ __nv_bfloat16 s_wq_hi[NQKV * KTOT];   // w_attn^T [3072,1024]
__device__ __nv_bfloat16 s_wq_lo[NQKV * KTOT];
__device__ __nv_bfloat16 s_wp_hi[DIM * KTOT];    // w_proj^T [1024,1024]
__device__ __nv_bfloat16 s_wp_lo[DIM * KTOT];
// attention operands, written by QKV epilogue
__device__ __nv_bfloat16 s_q_hi[BATCH * NHEAD * SEQ * DHEAD];  // [bh,s,dh], q*0.125
__device__ __nv_bfloat16 s_q_lo[BATCH * NHEAD * SEQ * DHEAD];
__device__ __nv_bfloat16 s_k_hi[BATCH * NHEAD * SEQ * DHEAD];  // [bh,s,dh]
__device__ __nv_bfloat16 s_k_lo[BATCH * NHEAD * SEQ * DHEAD];
__device__ __nv_bfloat16 s_vt_hi[BATCH * NHEAD * DHEAD * SEQ]; // [bh,dh,s]
__device__ __nv_bfloat16 s_vt_lo[BATCH * NHEAD * DHEAD * SEQ];

// ---------------------------------------------------------------------------
// PTX helpers (baseline ISA — compiles for sm_103)
// ---------------------------------------------------------------------------
__device__ __forceinline__ uint32_t smem_u32(const void* p) {
    uint32_t a;
    asm("{ .reg .u64 t; cvta.to.shared.u64 t, %1; cvt.u32.u64 %0, t; }"
        : "=r"(a) : "l"(p));
    return a;
}
__device__ __forceinline__ void ldsm4(uint32_t addr, uint32_t& r0, uint32_t& r1,
                                      uint32_t& r2, uint32_t& r3) {
    asm volatile("ldmatrix.sync.aligned.m8n8.x4.shared.b16 {%0,%1,%2,%3}, [%4];"
                 : "=r"(r0), "=r"(r1), "=r"(r2), "=r"(r3) : "r"(addr));
}
__device__ __forceinline__ void mma_bf16(float& c0, float& c1, float& c2, float& c3,
                                         uint32_t a0, uint32_t a1, uint32_t a2, uint32_t a3,
                                         uint32_t b0, uint32_t b1) {
    asm volatile("mma.sync.aligned.m16n8k16.row.col.f32.bf16.bf16.f32 "
                 "{%0,%1,%2,%3}, {%4,%5,%6,%7}, {%8,%9}, {%0,%1,%2,%3};"
                 : "+f"(c0), "+f"(c1), "+f"(c2), "+f"(c3)
                 : "r"(a0), "r"(a1), "r"(a2), "r"(a3), "r"(b0), "r"(b1));
}
__device__ __forceinline__ void cp16(uint32_t saddr, const void* g) {
    asm volatile("cp.async.cg.shared.global [%0], [%1], 16;"
                 :: "r"(saddr), "l"(g) : "memory");
}
__device__ __forceinline__ void cp_commit() {
    asm volatile("cp.async.commit_group;" ::: "memory");
}
template <int N>
__device__ __forceinline__ void cp_wait() {
    asm volatile("cp.async.wait_group %0;" :: "n"(N) : "memory");
}
__device__ __forceinline__ void split2(float v, __nv_bfloat16& h, __nv_bfloat16& l) {
    h = __float2bfloat16_rn(v);
    l = __float2bfloat16_rn(v - __bfloat162float(h));
}
__device__ __forceinline__ uint32_t packbf(__nv_bfloat16 a, __nv_bfloat16 b) {
    return (uint32_t)__bfloat16_as_ushort(a) | ((uint32_t)__bfloat16_as_ushort(b) << 16);
}

// ---------------------------------------------------------------------------
// Prep kernels
// ---------------------------------------------------------------------------
__global__ __launch_bounds__(256) void split_kernel(
    const float* __restrict__ src, __nv_bfloat16* __restrict__ hi,
    __nv_bfloat16* __restrict__ lo, int n4)
{
    int i = blockIdx.x * 256 + threadIdx.x;
    if (i >= n4) return;
    float4 v = ((const float4*)src)[i];
    __nv_bfloat16 h0, l0, h1, l1, h2, l2, h3, l3;
    split2(v.x, h0, l0); split2(v.y, h1, l1);
    split2(v.z, h2, l2); split2(v.w, h3, l3);
    uint2 uh = make_uint2(packbf(h0, h1), packbf(h2, h3));
    uint2 ul = make_uint2(packbf(l0, l1), packbf(l2, l3));
    *(uint2*)(hi + (size_t)i * 4) = uh;
    *(uint2*)(lo + (size_t)i * 4) = ul;
}

__global__ __launch_bounds__(256) void transp_split_kernel(
    const float* __restrict__ w, int K, int N,
    __nv_bfloat16* __restrict__ out_hi, __nv_bfloat16* __restrict__ out_lo)
{
    __shared__ float t[32][33];
    const int tx = threadIdx.x, ty = threadIdx.y;
    const int n0 = blockIdx.x * 32, k0 = blockIdx.y * 32;
#pragma unroll
    for (int i = 0; i < 4; ++i)
        t[ty + i * 8][tx] = w[(size_t)(k0 + ty + i * 8) * N + n0 + tx];
    __syncthreads();
#pragma unroll
    for (int i = 0; i < 4; ++i) {
        const int n = n0 + ty + i * 8;
        float v = t[tx][ty + i * 8];
        __nv_bfloat16 h, l;
        split2(v, h, l);
        out_hi[(size_t)n * K + k0 + tx] = h;
        out_lo[(size_t)n * K + k0 + tx] = l;
    }
}

// ---------------------------------------------------------------------------
// HMMA GEMM (R7 config: 256 thr, 2-stage cp.async, 2 CTAs/SM).
// R9 change: product-major MMA order — no accumulator RAW chains.
// D[M,N] = A @ B^T + bias, bf16 split-2 (3 products, fp32 accum).
// mode 0: QKV epilogue -> bf16 split q/k (k-major) and vt (transposed)
// mode 1: plain fp32 out
// ---------------------------------------------------------------------------
#define BM 128
#define BN 128
#define BK 32
#define ROWB 80
#define NKT (KTOT / BK)          // 32
#define OFF_ALO 10240
#define OFF_BHI 20480
#define OFF_BLO 30720
#define STG_BYTES 40960
#define GSM_BYTES (2 * STG_BYTES)   // 81920 per CTA; x2 CTAs = 160KB/SM

__global__ __launch_bounds__(256, 2) void tc_gemm_kernel(
    const __nv_bfloat16* __restrict__ Ahi, const __nv_bfloat16* __restrict__ Alo,
    const __nv_bfloat16* __restrict__ Bhi, const __nv_bfloat16* __restrict__ Blo,
    const float* __restrict__ bias, float* __restrict__ outp, int mode)
{
    extern __shared__ char gsm[];
    const uint32_t sb = smem_u32(gsm);

    const int tid  = threadIdx.x;
    const int w    = tid >> 5;
    const int lane = tid & 31;
    const int m0 = blockIdx.y * BM;
    const int n0 = blockIdx.x * BN;
    const int wm = (w >> 2) * 64;
    const int wn = (w & 3) * 32;

    const int srow = tid >> 2;
    const int sseg = tid & 3;
    const size_t gA = (size_t)(m0 + srow) * KTOT + sseg * 8;
    const size_t gB = (size_t)(n0 + srow) * KTOT + sseg * 8;
    const size_t rstep = (size_t)64 * KTOT;
    const uint32_t soff0 = (uint32_t)(srow * ROWB + sseg * 16);
    const uint32_t soff1 = soff0 + 64 * ROWB;

    auto load_stage = [&](int kt, int stg) {
        const uint32_t s0 = sb + stg * STG_BYTES;
        const __nv_bfloat16* pa  = Ahi + gA + (size_t)kt * BK;
        const __nv_bfloat16* pal = Alo + gA + (size_t)kt * BK;
        const __nv_bfloat16* pb  = Bhi + gB + (size_t)kt * BK;
        const __nv_bfloat16* pbl = Blo + gB + (size_t)kt * BK;
        cp16(s0 + soff0, pa);             cp16(s0 + soff1, pa + rstep);
        cp16(s0 + OFF_ALO + soff0, pal);  cp16(s0 + OFF_ALO + soff1, pal + rstep);
        cp16(s0 + OFF_BHI + soff0, pb);   cp16(s0 + OFF_BHI + soff1, pb + rstep);
        cp16(s0 + OFF_BLO + soff0, pbl);  cp16(s0 + OFF_BLO + soff1, pbl + rstep);
    };

    float acc[4][4][4];
#pragma unroll
    for (int i = 0; i < 4; ++i)
#pragma unroll
        for (int j = 0; j < 4; ++j)
#pragma unroll
            for (int e = 0; e < 4; ++e) acc[i][j][e] = 0.f;

    const int ar = lane & 15, ah = lane >> 4;
    const uint32_t aoffb = (uint32_t)((wm + ar) * ROWB + ah * 16);
    const int grp = lane >> 3, l8 = lane & 7;
    const uint32_t boffb = (uint32_t)((wn + ((grp >> 1) << 3) + l8) * ROWB + (grp & 1) * 16);

    load_stage(0, 0);
    cp_commit();

    for (int kt = 0; kt < NKT; ++kt) {
        if (kt + 1 < NKT) {
            load_stage(kt + 1, (kt + 1) & 1);
            cp_commit();
            cp_wait<1>();
        } else {
            cp_wait<0>();
        }
        __syncthreads();

        const uint32_t s0 = sb + (kt & 1) * STG_BYTES;
#pragma unroll
        for (int ks = 0; ks < 2; ++ks) {
            const uint32_t akoff = s0 + aoffb + ks * 32;
            const uint32_t bkoff = s0 + OFF_BHI + boffb + ks * 32;

            uint32_t fah[4][4], fal[4][4];
#pragma unroll
            for (int mt = 0; mt < 4; ++mt) {
                ldsm4(akoff + mt * 16 * ROWB,
                      fah[mt][0], fah[mt][1], fah[mt][2], fah[mt][3]);
                ldsm4(akoff + OFF_ALO + mt * 16 * ROWB,
                      fal[mt][0], fal[mt][1], fal[mt][2], fal[mt][3]);
            }
            uint32_t fbh[8], fbl[8];
            ldsm4(bkoff,                         fbh[0], fbh[1], fbh[2], fbh[3]);
            ldsm4(bkoff + 16 * ROWB,             fbh[4], fbh[5], fbh[6], fbh[7]);
            ldsm4(bkoff + (OFF_BLO - OFF_BHI),   fbl[0], fbl[1], fbl[2], fbl[3]);
            ldsm4(bkoff + (OFF_BLO - OFF_BHI) + 16 * ROWB,
                                                 fbl[4], fbl[5], fbl[6], fbl[7]);

            // product-major: 16 independent accumulators per pass (no RAW chains)
#pragma unroll
            for (int mt = 0; mt < 4; ++mt)
#pragma unroll
                for (int nt = 0; nt < 4; ++nt)
                    mma_bf16(acc[mt][nt][0], acc[mt][nt][1], acc[mt][nt][2], acc[mt][nt][3],
                             fah[mt][0], fah[mt][1], fah[mt][2], fah[mt][3],
                             fbh[nt * 2], fbh[nt * 2 + 1]);
#pragma unroll
            for (int mt = 0; mt < 4; ++mt)
#pragma unroll
                for (int nt = 0; nt < 4; ++nt)
                    mma_bf16(acc[mt][nt][0], acc[mt][nt][1], acc[mt][nt][2], acc[mt][nt][3],
                             fah[mt][0], fah[mt][1], fah[mt][2], fah[mt][3],
                             fbl[nt * 2], fbl[nt * 2 + 1]);
#pragma unroll
            for (int mt = 0; mt < 4; ++mt)
#pragma unroll
                for (int nt = 0; nt < 4; ++nt)
                    mma_bf16(acc[mt][nt][0], acc[mt][nt][1], acc[mt][nt][2], acc[mt][nt][3],
                             fal[mt][0], fal[mt][1], fal[mt][2], fal[mt][3],
                             fbh[nt * 2], fbh[nt * 2 + 1]);
        }
        __syncthreads();
    }

    // epilogue
    const int erow = (lane >> 2);
    const int ecol = (lane & 3) * 2;
#pragma unroll
    for (int mt = 0; mt < 4; ++mt) {
#pragma unroll
        for (int nt = 0; nt < 4; ++nt) {
#pragma unroll
            for (int half = 0; half < 2; ++half) {
                const int row = m0 + wm + mt * 16 + erow + half * 8;
                const int col = n0 + wn + nt * 8 + ecol;
                float v0 = acc[mt][nt][half * 2 + 0] + bias[col];
                float v1 = acc[mt][nt][half * 2 + 1] + bias[col + 1];
                if (mode == 0) {
                    const int bb = row >> 11, s = row & 2047;
                    const int part = col >> 10;
                    const int dd = col & 1023;
                    const int h = dd >> 6, hd = dd & 63;
                    const int bh = (bb << 4) + h;
                    if (part == 0) { v0 *= 0.125f; v1 *= 0.125f; }
                    __nv_bfloat16 h0, l0, h1, l1;
                    split2(v0, h0, l0); split2(v1, h1, l1);
                    if (part == 2) {
                        const size_t base = ((size_t)bh * DHEAD + hd) * SEQ + s;
                        s_vt_hi[base] = h0;       s_vt_lo[base] = l0;
                        s_vt_hi[base + SEQ] = h1; s_vt_lo[base + SEQ] = l1;
                    } else {
                        const size_t base = ((size_t)bh * SEQ + s) * DHEAD + hd;
                        __nv_bfloat16* dh_ = (part == 0) ? s_q_hi : s_k_hi;
                        __nv_bfloat16* dl_ = (part == 0) ? s_q_lo : s_k_lo;
                        *(uint32_t*)(dh_ + base) = packbf(h0, h1);
                        *(uint32_t*)(dl_ + base) = packbf(l0, l1);
                    }
                } else {
                    *(float2*)(outp + (size_t)row * DIM + col) = make_float2(v0, v1);
                }
            }
        }
    }
}

// ---------------------------------------------------------------------------
// Tensor-core flash attention (bf16 split-2, fp32 softmax), cp.async 2-stage,
// 2 CTAs/SM. R9 change: product-major MMA order in QK and PV blocks.
// ---------------------------------------------------------------------------
#define AROWB 144
#define AQ_H 0
#define AQ_L 18432
#define AKV0 36864
#define AKV_STG 36864
#define AK_L 9216
#define AV_H 18432
#define AV_L 27648
#define ASM_BYTES (AKV0 + 2 * AKV_STG)   // 110592

__global__ __launch_bounds__(128, 2) void attn_tc_kernel()
{
    extern __shared__ char asmem[];
    const uint32_t sb = smem_u32(asmem);
    const int tid  = threadIdx.x;
    const int w    = tid >> 5;
    const int lane = tid & 31;
    const int qt   = blockIdx.x;
    const int bh   = blockIdx.y;
    const int q0   = qt * 128;

    const __nv_bfloat16* Qh = s_q_hi + (size_t)bh * SEQ * DHEAD;
    const __nv_bfloat16* Ql = s_q_lo + (size_t)bh * SEQ * DHEAD;
    const __nv_bfloat16* Kh = s_k_hi + (size_t)bh * SEQ * DHEAD;
    const __nv_bfloat16* Kl = s_k_lo + (size_t)bh * SEQ * DHEAD;
    const __nv_bfloat16* Vh = s_vt_hi + (size_t)bh * DHEAD * SEQ;
    const __nv_bfloat16* Vl = s_vt_lo + (size_t)bh * DHEAD * SEQ;

    auto load_kv = [&](int kt, int stg) {
        const uint32_t s0 = sb + AKV0 + stg * AKV_STG;
        const int kv0 = kt * 64;
#pragma unroll
        for (int i = 0; i < 4; ++i) {
            const int c = tid + i * 128;
            const int row = c >> 3, seg = c & 7;
            const uint32_t so = row * AROWB + seg * 16;
            const size_t gk = (size_t)(kv0 + row) * DHEAD + seg * 8;
            const size_t gv = (size_t)row * SEQ + kv0 + seg * 8;
            cp16(s0 + so, Kh + gk);
            cp16(s0 + AK_L + so, Kl + gk);
            cp16(s0 + AV_H + so, Vh + gv);
            cp16(s0 + AV_L + so, Vl + gv);
        }
    };

    // Q tile (128 rows x 64 bf16) hi/lo — plain stores, covered by first barrier
#pragma unroll
    for (int i = 0; i < 8; ++i) {
        const int c = tid + i * 128;
        const int row = c >> 3, seg = c & 7;
        const uint32_t so = row * AROWB + seg * 16;
        const size_t go = (size_t)(q0 + row) * DHEAD + seg * 8;
        *(uint4*)(asmem + AQ_H + so) = *(const uint4*)(Qh + go);
        *(uint4*)(asmem + AQ_L + so) = *(const uint4*)(Ql + go);
    }

    const int ar = lane & 15, ahh = lane >> 4;
    const int grp = lane >> 3, l8 = lane & 7;
    const int row0 = lane >> 2, coll = (lane & 3) * 2;

    float m_run[4], l_run[4];
#pragma unroll
    for (int i = 0; i < 4; ++i) { m_run[i] = -1e30f; l_run[i] = 0.f; }
    float oacc[2][8][4];
#pragma unroll
    for (int mt = 0; mt < 2; ++mt)
#pragma unroll
        for (int nt = 0; nt < 8; ++nt)
#pragma unroll
            for (int e = 0; e < 4; ++e) oacc[mt][nt][e] = 0.f;

    const int ntiles = qt * 2 + 2;
    load_kv(0, 0);
    cp_commit();

    for (int kt = 0; kt < ntiles; ++kt) {
        if (kt + 1 < ntiles) {
            load_kv(kt + 1, (kt + 1) & 1);
            cp_commit();
            cp_wait<1>();
        } else {
            cp_wait<0>();
        }
        __syncthreads();

        const uint32_t kvb = sb + AKV0 + (kt & 1) * AKV_STG;
        const int kv0 = kt * 64;

        // ---- scores: S = Q K^T (split-2, product-major) ----
        float s[2][8][4];
#pragma unroll
        for (int mt = 0; mt < 2; ++mt)
#pragma unroll
            for (int nt = 0; nt < 8; ++nt)
#pragma unroll
                for (int e = 0; e < 4; ++e) s[mt][nt][e] = 0.f;

#pragma unroll
        for (int ks = 0; ks < 4; ++ks) {
            uint32_t kbh[4][4], kbl[4][4];
#pragma unroll
            for (int nb = 0; nb < 4; ++nb) {
                const uint32_t bo = (uint32_t)(((grp >> 1) * 8 + l8 + nb * 16) * AROWB +
                                               (grp & 1) * 16 + ks * 32);
                ldsm4(kvb + bo, kbh[nb][0], kbh[nb][1], kbh[nb][2], kbh[nb][3]);
                ldsm4(kvb + AK_L + bo, kbl[nb][0], kbl[nb][1], kbl[nb][2], kbl[nb][3]);
            }
            uint32_t qh[2][4], ql[2][4];
#pragma unroll
            for (int mt = 0; mt < 2; ++mt) {
                const uint32_t ao = (uint32_t)((w * 32 + mt * 16 + ar) * AROWB +
                                               ahh * 16 + ks * 32);
                ldsm4(sb + AQ_H + ao, qh[mt][0], qh[mt][1], qh[mt][2], qh[mt][3]);
                ldsm4(sb + AQ_L + ao, ql[mt][0], ql[mt][1], ql[mt][2], ql[mt][3]);
            }
            // product-major passes over 16 independent accumulators
#pragma unroll
            for (int mt = 0; mt < 2; ++mt)
#pragma unroll
                for (int nt = 0; nt < 8; ++nt) {
                    const int nb = nt >> 1, p = nt & 1;
                    mma_bf16(s[mt][nt][0], s[mt][nt][1], s[mt][nt][2], s[mt][nt][3],
                             qh[mt][0], qh[mt][1], qh[mt][2], qh[mt][3],
                             kbh[nb][p * 2], kbh[nb][p * 2 + 1]);
                }
#pragma unroll
            for (int mt = 0; mt < 2; ++mt)
#pragma unroll
                for (int nt = 0; nt < 8; ++nt) {
                    const int nb = nt >> 1, p = nt & 1;
                    mma_bf16(s[mt][nt][0], s[mt][nt][1], s[mt][nt][2], s[mt][nt][3],
                             qh[mt][0], qh[mt][1], qh[mt][2], qh[mt][3],
                             kbl[nb][p * 2], kbl[nb][p * 2 + 1]);
                }
#pragma unroll
            for (int mt = 0; mt < 2; ++mt)
#pragma unroll
                for (int nt = 0; nt < 8; ++nt) {
                    const int nb = nt >> 1, p = nt & 1;
                    mma_bf16(s[mt][nt][0], s[mt][nt][1], s[mt][nt][2], s[mt][nt][3],
                             ql[mt][0], ql[mt][1], ql[mt][2], ql[mt][3],
                             kbh[nb][p * 2], kbh[nb][p * 2 + 1]);
                }
        }

        // ---- causal mask ----
        if (kt >= qt * 2) {
#pragma unroll
            for (int mt = 0; mt < 2; ++mt) {
                const int rbase = q0 + w * 32 + mt * 16 + row0;
#pragma unroll
                for (int nt = 0; nt < 8; ++nt) {
                    const int cb = kv0 + nt * 8 + coll;
                    if (cb > rbase)     s[mt][nt][0] = -10000.f;
                    if (cb + 1 > rbase) s[mt][nt][1] = -10000.f;
                    if (cb > rbase + 8)     s[mt][nt][2] = -10000.f;
                    if (cb + 1 > rbase + 8) s[mt][nt][3] = -10000.f;
                }
            }
        }

        // ---- online softmax ----
        float corr[4];
#pragma unroll
        for (int slot = 0; slot < 4; ++slot) {
            const int mt = slot >> 1, h2 = slot & 1;
            float tm = -1e30f;
#pragma unroll
            for (int nt = 0; nt < 8; ++nt)
                tm = fmaxf(tm, fmaxf(s[mt][nt][h2 * 2], s[mt][nt][h2 * 2 + 1]));
            tm = fmaxf(tm, __shfl_xor_sync(0xffffffffu, tm, 1));
            tm = fmaxf(tm, __shfl_xor_sync(0xffffffffu, tm, 2));
            const float mnew = fmaxf(m_run[slot], tm);
            corr[slot] = __expf(m_run[slot] - mnew);
            m_run[slot] = mnew;
            l_run[slot] *= corr[slot];
        }
#pragma unroll
        for (int mt = 0; mt < 2; ++mt)
#pragma unroll
            for (int nt = 0; nt < 8; ++nt) {
                oacc[mt][nt][0] *= corr[mt * 2];
                oacc[mt][nt][1] *= corr[mt * 2];
                oacc[mt][nt][2] *= corr[mt * 2 + 1];
                oacc[mt][nt][3] *= corr[mt * 2 + 1];
            }

        // ---- P = exp(S - m), split-2 pack into A fragments ----
        uint32_t ph[2][8][2], pl[2][8][2];
#pragma unroll
        for (int mt = 0; mt < 2; ++mt)
#pragma unroll
            for (int nt = 0; nt < 8; ++nt) {
                const float p0 = __expf(s[mt][nt][0] - m_run[mt * 2]);
                const float p1 = __expf(s[mt][nt][1] - m_run[mt * 2]);
                const float p2 = __expf(s[mt][nt][2] - m_run[mt * 2 + 1]);
                const float p3 = __expf(s[mt][nt][3] - m_run[mt * 2 + 1]);
                l_run[mt * 2]     += p0 + p1;
                l_run[mt * 2 + 1] += p2 + p3;
                __nv_bfloat16 h0, lo0, h1, lo1, h2, lo2, h3, lo3;
                split2(p0, h0, lo0); split2(p1, h1, lo1);
                split2(p2, h2, lo2); split2(p3, h3, lo3);
                ph[mt][nt][0] = packbf(h0, h1);   ph[mt][nt][1] = packbf(h2, h3);
                pl[mt][nt][0] = packbf(lo0, lo1); pl[mt][nt][1] = packbf(lo2, lo3);
            }

        // ---- O += P V (split-2, product-major) ----
#pragma unroll
        for (int ks = 0; ks < 4; ++ks) {
            uint32_t vbh[4][4], vbl[4][4];
#pragma unroll
            for (int nb = 0; nb < 4; ++nb) {
                const uint32_t bo = (uint32_t)(((grp >> 1) * 8 + l8 + nb * 16) * AROWB +
                                               (grp & 1) * 16 + ks * 32);
                ldsm4(kvb + AV_H + bo, vbh[nb][0], vbh[nb][1], vbh[nb][2], vbh[nb][3]);
                ldsm4(kvb + AV_L + bo, vbl[nb][0], vbl[nb][1], vbl[nb][2], vbl[nb][3]);
            }
#pragma unroll
            for (int mt = 0; mt < 2; ++mt)
#pragma unroll
                for (int nt = 0; nt < 8; ++nt) {
                    const int nb = nt >> 1, p = nt & 1;
                    mma_bf16(oacc[mt][nt][0], oacc[mt][nt][1], oacc[mt][nt][2], oacc[mt][nt][3],
                             ph[mt][ks * 2][0], ph[mt][ks * 2][1],
                             ph[mt][ks * 2 + 1][0], ph[mt][ks * 2 + 1][1],
                             vbh[nb][p * 2], vbh[nb][p * 2 + 1]);
                }
#pragma unroll
            for (int mt = 0; mt < 2; ++mt)
#pragma unroll
                for (int nt = 0; nt < 8; ++nt) {
                    const int nb = nt >> 1, p = nt & 1;
                    mma_bf16(oacc[mt][nt][0], oacc[mt][nt][1], oacc[mt][nt][2], oacc[mt][nt][3],
                             ph[mt][ks * 2][0], ph[mt][ks * 2][1],
                             ph[mt][ks * 2 + 1][0], ph[mt][ks * 2 + 1][1],
                             vbl[nb][p * 2], vbl[nb][p * 2 + 1]);
                }
#pragma unroll
            for (int mt = 0; mt < 2; ++mt)
#pragma unroll
                for (int nt = 0; nt < 8; ++nt) {
                    const int nb = nt >> 1, p = nt & 1;
                    mma_bf16(oacc[mt][nt][0], oacc[mt][nt][1], oacc[mt][nt][2], oacc[mt][nt][3],
                             pl[mt][ks * 2][0], pl[mt][ks * 2][1],
                             pl[mt][ks * 2 + 1][0], pl[mt][ks * 2 + 1][1],
                             vbh[nb][p * 2], vbh[nb][p * 2 + 1]);
                }
        }
        __syncthreads();
    }

    // ---- finalize ----
    float inv[4];
#pragma unroll
    for (int slot = 0; slot < 4; ++slot) {
        float lt = l_run[slot];
        lt += __shfl_xor_sync(0xffffffffu, lt, 1);
        lt += __shfl_xor_sync(0xffffffffu, lt, 2);
        inv[slot] = 1.f / lt;
    }
    const int b = bh >> 4, h = bh & 15;
#pragma unroll
    for (int mt = 0; mt < 2; ++mt) {
#pragma unroll
        for (int half = 0; half < 2; ++half) {
            const size_t orow = (size_t)b * SEQ + q0 + w * 32 + mt * 16 + row0 + half * 8;
            const float iv = inv[mt * 2 + half];
#pragma unroll
            for (int nt = 0; nt < 8; ++nt) {
                const int col = h * DHEAD + nt * 8 + coll;
                const float v0 = oacc[mt][nt][half * 2 + 0] * iv;
                const float v1 = oacc[mt][nt][half * 2 + 1] * iv;
                __nv_bfloat16 h0, l0, h1, l1;
                split2(v0, h0, l0); split2(v1, h1, l1);
                *(uint32_t*)(s_a_hi + orow * DIM + col) = packbf(h0, h1);
                *(uint32_t*)(s_a_lo + orow * DIM + col) = packbf(l0, l1);
            }
        }
    }
}

// ---------------------------------------------------------------------------
extern "C" void kernel_launch(void* const* d_in, const int* in_sizes, int n_in,
                              void* d_out, int out_size)
{
    const float* x      = (const float*)d_in[0];
    const float* w_attn = (const float*)d_in[1];
    const float* b_attn = (const float*)d_in[2];
    const float* w_proj = (const float*)d_in[3];
    const float* b_proj = (const float*)d_in[4];
    float* out = (float*)d_out;

    __nv_bfloat16 *xa_hi, *xa_lo, *wq_hi, *wq_lo, *wp_hi, *wp_lo;
    cudaGetSymbolAddress((void**)&xa_hi, s_a_hi);
    cudaGetSymbolAddress((void**)&xa_lo, s_a_lo);
    cudaGetSymbolAddress((void**)&wq_hi, s_wq_hi);
    cudaGetSymbolAddress((void**)&wq_lo, s_wq_lo);
    cudaGetSymbolAddress((void**)&wp_hi, s_wp_hi);
    cudaGetSymbolAddress((void**)&wp_lo, s_wp_lo);

    cudaFuncSetAttribute(tc_gemm_kernel,
                         cudaFuncAttributeMaxDynamicSharedMemorySize, GSM_BYTES);
    cudaFuncSetAttribute(attn_tc_kernel,
                         cudaFuncAttributeMaxDynamicSharedMemorySize, ASM_BYTES);

    // 1) split x -> bf16 hi/lo
    split_kernel<<<(MROWS * KTOT / 4 + 255) / 256, 256>>>(x, xa_hi, xa_lo, MROWS * KTOT / 4);
    // 2) transpose+split weights
    transp_split_kernel<<<dim3(NQKV / 32, KTOT / 32), dim3(32, 8)>>>(w_attn, KTOT, NQKV, wq_hi, wq_lo);
    transp_split_kernel<<<dim3(DIM / 32, KTOT / 32), dim3(32, 8)>>>(w_proj, KTOT, DIM, wp_hi, wp_lo);
    // 3) QKV GEMM -> bf16 split q/k/vt
    tc_gemm_kernel<<<dim3(NQKV / BN, MROWS / BM), 256, GSM_BYTES>>>(
        xa_hi, xa_lo, wq_hi, wq_lo, b_attn, nullptr, 0);
    // 4) tensor-core flash attention -> writes s_a_hi/s_a_lo
    attn_tc_kernel<<<dim3(SEQ / 128, BATCH * NHEAD), 128, ASM_BYTES>>>();
    // 5) output projection
    tc_gemm_kernel<<<dim3(DIM / BN, MROWS / BM), 256, GSM_BYTES>>>(
        xa_hi, xa_lo, wp_hi, wp_lo, b_proj, out, 1);
}

// round 10
// speedup vs baseline: 1.6588x; 1.5713x over previous
#include <cuda_runtime.h>
#include <cuda_fp16.h>
#include <cstdint>

// Problem shape (fixed by the dataset)
#define BATCH 2
#define SEQ   2048
#define DIM   1024
#define NHEAD 16
#define DHEAD 64
#define MROWS (BATCH * SEQ)          // 4096
#define NQKV  (3 * DIM)              // 3072
#define KTOT  1024

// ---------------------------------------------------------------------------
// Scratch (allocation-free rule: __device__ globals), fp16 scheme:
// A operands split-2 (hi/lo), B operands single.
// ---------------------------------------------------------------------------
__device__ __half s_a_hi[MROWS * KTOT];   // GEMM A: x, then attention out
__device__ __half s_a_lo[MROWS * KTOT];
__device__ __half s_wq[NQKV * KTOT];      // w_attn^T [3072,1024] single fp16
__device__ __half s_wp[DIM * KTOT];       // w_proj^T [1024,1024] single fp16
// attention operands, written by QKV epilogue
__device__ __half s_q_hi[BATCH * NHEAD * SEQ * DHEAD];  // [bh,s,dh], q*0.125
__device__ __half s_q_lo[BATCH * NHEAD * SEQ * DHEAD];
__device__ __half s_k [BATCH * NHEAD * SEQ * DHEAD];    // [bh,s,dh] single
__device__ __half s_vt[BATCH * NHEAD * DHEAD * SEQ];    // [bh,dh,s] single

// ---------------------------------------------------------------------------
// PTX helpers (baseline ISA — compiles for sm_103)
// ---------------------------------------------------------------------------
__device__ __forceinline__ uint32_t smem_u32(const void* p) {
    uint32_t a;
    asm("{ .reg .u64 t; cvta.to.shared.u64 t, %1; cvt.u32.u64 %0, t; }"
        : "=r"(a) : "l"(p));
    return a;
}
__device__ __forceinline__ void ldsm4(uint32_t addr, uint32_t& r0, uint32_t& r1,
                                      uint32_t& r2, uint32_t& r3) {
    asm volatile("ldmatrix.sync.aligned.m8n8.x4.shared.b16 {%0,%1,%2,%3}, [%4];"
                 : "=r"(r0), "=r"(r1), "=r"(r2), "=r"(r3) : "r"(addr));
}
__device__ __forceinline__ void mma_f16(float& c0, float& c1, float& c2, float& c3,
                                        uint32_t a0, uint32_t a1, uint32_t a2, uint32_t a3,
                                        uint32_t b0, uint32_t b1) {
    asm volatile("mma.sync.aligned.m16n8k16.row.col.f32.f16.f16.f32 "
                 "{%0,%1,%2,%3}, {%4,%5,%6,%7}, {%8,%9}, {%0,%1,%2,%3};"
                 : "+f"(c0), "+f"(c1), "+f"(c2), "+f"(c3)
                 : "r"(a0), "r"(a1), "r"(a2), "r"(a3), "r"(b0), "r"(b1));
}
__device__ __forceinline__ void cp16(uint32_t saddr, const void* g) {
    asm volatile("cp.async.cg.shared.global [%0], [%1], 16;"
                 :: "r"(saddr), "l"(g) : "memory");
}
__device__ __forceinline__ void cp_commit() {
    asm volatile("cp.async.commit_group;" ::: "memory");
}
template <int N>
__device__ __forceinline__ void cp_wait() {
    asm volatile("cp.async.wait_group %0;" :: "n"(N) : "memory");
}
__device__ __forceinline__ void split2h(float v, __half& h, __half& l) {
    h = __float2half_rn(v);
    l = __float2half_rn(v - __half2float(h));
}
__device__ __forceinline__ uint32_t packh(__half a, __half b) {
    __half2 p = __halves2half2(a, b);
    return *(uint32_t*)&p;
}
__device__ __forceinline__ uint32_t packh_f(float a, float b) {
    __half2 p = __floats2half2_rn(a, b);
    return *(uint32_t*)&p;
}

// ---------------------------------------------------------------------------
// Prep kernels
// ---------------------------------------------------------------------------
__global__ __launch_bounds__(256) void split_kernel(
    const float* __restrict__ src, __half* __restrict__ hi,
    __half* __restrict__ lo, int n4)
{
    int i = blockIdx.x * 256 + threadIdx.x;
    if (i >= n4) return;
    float4 v = ((const float4*)src)[i];
    __half h0, l0, h1, l1, h2, l2, h3, l3;
    split2h(v.x, h0, l0); split2h(v.y, h1, l1);
    split2h(v.z, h2, l2); split2h(v.w, h3, l3);
    uint2 uh = make_uint2(packh(h0, h1), packh(h2, h3));
    uint2 ul = make_uint2(packh(l0, l1), packh(l2, l3));
    *(uint2*)(hi + (size_t)i * 4) = uh;
    *(uint2*)(lo + (size_t)i * 4) = ul;
}

__global__ __launch_bounds__(256) void transp_half_kernel(
    const float* __restrict__ w, int K, int N, __half* __restrict__ outp)
{
    __shared__ float t[32][33];
    const int tx = threadIdx.x, ty = threadIdx.y;
    const int n0 = blockIdx.x * 32, k0 = blockIdx.y * 32;
#pragma unroll
    for (int i = 0; i < 4; ++i)
        t[ty + i * 8][tx] = w[(size_t)(k0 + ty + i * 8) * N + n0 + tx];
    __syncthreads();
#pragma unroll
    for (int i = 0; i < 4; ++i) {
        const int n = n0 + ty + i * 8;
        outp[(size_t)n * K + k0 + tx] = __float2half_rn(t[tx][ty + i * 8]);
    }
}

// ---------------------------------------------------------------------------
// HMMA GEMM, fp16: A split-2, B single (2 products), 256 thr, 2-stage
// cp.async, 2 CTAs/SM. D[M,N] = A @ B^T + bias.
// mode 0: QKV epilogue -> q split-2, k single, vt single (transposed)
// mode 1: plain fp32 out
// ---------------------------------------------------------------------------
#define BM 128
#define BN 128
#define BK 32
#define ROWB 80
#define NKT (KTOT / BK)          // 32
#define OFF_ALO 10240
#define OFF_B   20480
#define STG_BYTES 30720
#define GSM_BYTES (2 * STG_BYTES)   // 61440 per CTA; x2 CTAs = 120KB/SM

__global__ __launch_bounds__(256, 2) void tc_gemm_kernel(
    const __half* __restrict__ Ahi, const __half* __restrict__ Alo,
    const __half* __restrict__ B,
    const float* __restrict__ bias, float* __restrict__ outp, int mode)
{
    extern __shared__ char gsm[];
    const uint32_t sb = smem_u32(gsm);

    const int tid  = threadIdx.x;
    const int w    = tid >> 5;
    const int lane = tid & 31;
    const int m0 = blockIdx.y * BM;
    const int n0 = blockIdx.x * BN;
    const int wm = (w >> 2) * 64;
    const int wn = (w & 3) * 32;

    const int srow = tid >> 2;
    const int sseg = tid & 3;
    const size_t gA = (size_t)(m0 + srow) * KTOT + sseg * 8;
    const size_t gB = (size_t)(n0 + srow) * KTOT + sseg * 8;
    const size_t rstep = (size_t)64 * KTOT;
    const uint32_t soff0 = (uint32_t)(srow * ROWB + sseg * 16);
    const uint32_t soff1 = soff0 + 64 * ROWB;

    auto load_stage = [&](int kt, int stg) {
        const uint32_t s0 = sb + stg * STG_BYTES;
        const __half* pa  = Ahi + gA + (size_t)kt * BK;
        const __half* pal = Alo + gA + (size_t)kt * BK;
        const __half* pb  = B   + gB + (size_t)kt * BK;
        cp16(s0 + soff0, pa);             cp16(s0 + soff1, pa + rstep);
        cp16(s0 + OFF_ALO + soff0, pal);  cp16(s0 + OFF_ALO + soff1, pal + rstep);
        cp16(s0 + OFF_B + soff0, pb);     cp16(s0 + OFF_B + soff1, pb + rstep);
    };

    float acc[4][4][4];
#pragma unroll
    for (int i = 0; i < 4; ++i)
#pragma unroll
        for (int j = 0; j < 4; ++j)
#pragma unroll
            for (int e = 0; e < 4; ++e) acc[i][j][e] = 0.f;

    const int ar = lane & 15, ah = lane >> 4;
    const uint32_t aoffb = (uint32_t)((wm + ar) * ROWB + ah * 16);
    const int grp = lane >> 3, l8 = lane & 7;
    const uint32_t boffb = (uint32_t)((wn + ((grp >> 1) << 3) + l8) * ROWB + (grp & 1) * 16);

    load_stage(0, 0);
    cp_commit();

    for (int kt = 0; kt < NKT; ++kt) {
        if (kt + 1 < NKT) {
            load_stage(kt + 1, (kt + 1) & 1);
            cp_commit();
            cp_wait<1>();
        } else {
            cp_wait<0>();
        }
        __syncthreads();

        const uint32_t s0 = sb + (kt & 1) * STG_BYTES;
#pragma unroll
        for (int ks = 0; ks < 2; ++ks) {
            const uint32_t akoff = s0 + aoffb + ks * 32;
            const uint32_t bkoff = s0 + OFF_B + boffb + ks * 32;

            uint32_t fah[4][4], fal[4][4];
#pragma unroll
            for (int mt = 0; mt < 4; ++mt) {
                ldsm4(akoff + mt * 16 * ROWB,
                      fah[mt][0], fah[mt][1], fah[mt][2], fah[mt][3]);
                ldsm4(akoff + OFF_ALO + mt * 16 * ROWB,
                      fal[mt][0], fal[mt][1], fal[mt][2], fal[mt][3]);
            }
            uint32_t fb[8];
            ldsm4(bkoff,             fb[0], fb[1], fb[2], fb[3]);
            ldsm4(bkoff + 16 * ROWB, fb[4], fb[5], fb[6], fb[7]);

#pragma unroll
            for (int mt = 0; mt < 4; ++mt)
#pragma unroll
                for (int nt = 0; nt < 4; ++nt)
                    mma_f16(acc[mt][nt][0], acc[mt][nt][1], acc[mt][nt][2], acc[mt][nt][3],
                            fah[mt][0], fah[mt][1], fah[mt][2], fah[mt][3],
                            fb[nt * 2], fb[nt * 2 + 1]);
#pragma unroll
            for (int mt = 0; mt < 4; ++mt)
#pragma unroll
                for (int nt = 0; nt < 4; ++nt)
                    mma_f16(acc[mt][nt][0], acc[mt][nt][1], acc[mt][nt][2], acc[mt][nt][3],
                            fal[mt][0], fal[mt][1], fal[mt][2], fal[mt][3],
                            fb[nt * 2], fb[nt * 2 + 1]);
        }
        __syncthreads();
    }

    // epilogue
    const int erow = (lane >> 2);
    const int ecol = (lane & 3) * 2;
#pragma unroll
    for (int mt = 0; mt < 4; ++mt) {
#pragma unroll
        for (int nt = 0; nt < 4; ++nt) {
#pragma unroll
            for (int half = 0; half < 2; ++half) {
                const int row = m0 + wm + mt * 16 + erow + half * 8;
                const int col = n0 + wn + nt * 8 + ecol;
                float v0 = acc[mt][nt][half * 2 + 0] + bias[col];
                float v1 = acc[mt][nt][half * 2 + 1] + bias[col + 1];
                if (mode == 0) {
                    const int bb = row >> 11, s = row & 2047;
                    const int part = col >> 10;
                    const int dd = col & 1023;
                    const int h = dd >> 6, hd = dd & 63;
                    const int bh = (bb << 4) + h;
                    if (part == 0) {
                        v0 *= 0.125f; v1 *= 0.125f;
                        const size_t base = ((size_t)bh * SEQ + s) * DHEAD + hd;
                        __half h0, l0, h1, l1;
                        split2h(v0, h0, l0); split2h(v1, h1, l1);
                        *(uint32_t*)(s_q_hi + base) = packh(h0, h1);
                        *(uint32_t*)(s_q_lo + base) = packh(l0, l1);
                    } else if (part == 1) {
                        const size_t base = ((size_t)bh * SEQ + s) * DHEAD + hd;
                        *(uint32_t*)(s_k + base) = packh_f(v0, v1);
                    } else {
                        const size_t base = ((size_t)bh * DHEAD + hd) * SEQ + s;
                        s_vt[base]       = __float2half_rn(v0);
                        s_vt[base + SEQ] = __float2half_rn(v1);
                    }
                } else {
                    *(float2*)(outp + (size_t)row * DIM + col) = make_float2(v0, v1);
                }
            }
        }
    }
}

// ---------------------------------------------------------------------------
// Tensor-core flash attention, fp16: QK = Qsplit2 x Ksingle (2 products),
// PV = Psingle x Vsingle (1 product). fp32 softmax. cp.async 2-stage KV,
// 2 CTAs/SM. CTA: 128 q rows x one (b,h); 4 warps; KV tiles of 64.
// ---------------------------------------------------------------------------
#define AROWB 144
#define AQ_H 0
#define AQ_L 18432
#define AKV0 36864
#define AKV_STG 18432          // K (9216) + VT (9216)
#define AV_OFF 9216
#define ASM_BYTES (AKV0 + 2 * AKV_STG)   // 73728; x2 CTAs = 144KB/SM

__global__ __launch_bounds__(128, 2) void attn_tc_kernel()
{
    extern __shared__ char asmem[];
    const uint32_t sb = smem_u32(asmem);
    const int tid  = threadIdx.x;
    const int w    = tid >> 5;
    const int lane = tid & 31;
    const int qt   = blockIdx.x;
    const int bh   = blockIdx.y;
    const int q0   = qt * 128;

    const __half* Qh = s_q_hi + (size_t)bh * SEQ * DHEAD;
    const __half* Ql = s_q_lo + (size_t)bh * SEQ * DHEAD;
    const __half* Kg = s_k    + (size_t)bh * SEQ * DHEAD;
    const __half* Vg = s_vt   + (size_t)bh * DHEAD * SEQ;

    auto load_kv = [&](int kt, int stg) {
        const uint32_t s0 = sb + AKV0 + stg * AKV_STG;
        const int kv0 = kt * 64;
#pragma unroll
        for (int i = 0; i < 4; ++i) {
            const int c = tid + i * 128;          // 0..511
            const int row = c >> 3, seg = c & 7;
            const uint32_t so = row * AROWB + seg * 16;
            const size_t gk = (size_t)(kv0 + row) * DHEAD + seg * 8;
            const size_t gv = (size_t)row * SEQ + kv0 + seg * 8;
            cp16(s0 + so, Kg + gk);
            cp16(s0 + AV_OFF + so, Vg + gv);
        }
    };

    // Q tile (128 rows x 64 fp16) hi/lo — plain stores, covered by first barrier
#pragma unroll
    for (int i = 0; i < 8; ++i) {
        const int c = tid + i * 128;
        const int row = c >> 3, seg = c & 7;
        const uint32_t so = row * AROWB + seg * 16;
        const size_t go = (size_t)(q0 + row) * DHEAD + seg * 8;
        *(uint4*)(asmem + AQ_H + so) = *(const uint4*)(Qh + go);
        *(uint4*)(asmem + AQ_L + so) = *(const uint4*)(Ql + go);
    }

    const int ar = lane & 15, ahh = lane >> 4;
    const int grp = lane >> 3, l8 = lane & 7;
    const int row0 = lane >> 2, coll = (lane & 3) * 2;

    float m_run[4], l_run[4];
#pragma unroll
    for (int i = 0; i < 4; ++i) { m_run[i] = -1e30f; l_run[i] = 0.f; }
    float oacc[2][8][4];
#pragma unroll
    for (int mt = 0; mt < 2; ++mt)
#pragma unroll
        for (int nt = 0; nt < 8; ++nt)
#pragma unroll
            for (int e = 0; e < 4; ++e) oacc[mt][nt][e] = 0.f;

    const int ntiles = qt * 2 + 2;
    load_kv(0, 0);
    cp_commit();

    for (int kt = 0; kt < ntiles; ++kt) {
        if (kt + 1 < ntiles) {
            load_kv(kt + 1, (kt + 1) & 1);
            cp_commit();
            cp_wait<1>();
        } else {
            cp_wait<0>();
        }
        __syncthreads();

        const uint32_t kvb = sb + AKV0 + (kt & 1) * AKV_STG;
        const int kv0 = kt * 64;

        // ---- scores: S = Q K^T (Q split-2, K single) ----
        float s[2][8][4];
#pragma unroll
        for (int mt = 0; mt < 2; ++mt)
#pragma unroll
            for (int nt = 0; nt < 8; ++nt)
#pragma unroll
                for (int e = 0; e < 4; ++e) s[mt][nt][e] = 0.f;

#pragma unroll
        for (int ks = 0; ks < 4; ++ks) {
            uint32_t kb[4][4];
#pragma unroll
            for (int nb = 0; nb < 4; ++nb) {
                const uint32_t bo = (uint32_t)(((grp >> 1) * 8 + l8 + nb * 16) * AROWB +
                                               (grp & 1) * 16 + ks * 32);
                ldsm4(kvb + bo, kb[nb][0], kb[nb][1], kb[nb][2], kb[nb][3]);
            }
            uint32_t qh[2][4], ql[2][4];
#pragma unroll
            for (int mt = 0; mt < 2; ++mt) {
                const uint32_t ao = (uint32_t)((w * 32 + mt * 16 + ar) * AROWB +
                                               ahh * 16 + ks * 32);
                ldsm4(sb + AQ_H + ao, qh[mt][0], qh[mt][1], qh[mt][2], qh[mt][3]);
                ldsm4(sb + AQ_L + ao, ql[mt][0], ql[mt][1], ql[mt][2], ql[mt][3]);
            }
#pragma unroll
            for (int mt = 0; mt < 2; ++mt)
#pragma unroll
                for (int nt = 0; nt < 8; ++nt) {
                    const int nb = nt >> 1, p = nt & 1;
                    mma_f16(s[mt][nt][0], s[mt][nt][1], s[mt][nt][2], s[mt][nt][3],
                            qh[mt][0], qh[mt][1], qh[mt][2], qh[mt][3],
                            kb[nb][p * 2], kb[nb][p * 2 + 1]);
                }
#pragma unroll
            for (int mt = 0; mt < 2; ++mt)
#pragma unroll
                for (int nt = 0; nt < 8; ++nt) {
                    const int nb = nt >> 1, p = nt & 1;
                    mma_f16(s[mt][nt][0], s[mt][nt][1], s[mt][nt][2], s[mt][nt][3],
                            ql[mt][0], ql[mt][1], ql[mt][2], ql[mt][3],
                            kb[nb][p * 2], kb[nb][p * 2 + 1]);
                }
        }

        // ---- causal mask ----
        if (kt >= qt * 2) {
#pragma unroll
            for (int mt = 0; mt < 2; ++mt) {
                const int rbase = q0 + w * 32 + mt * 16 + row0;
#pragma unroll
                for (int nt = 0; nt < 8; ++nt) {
                    const int cb = kv0 + nt * 8 + coll;
                    if (cb > rbase)     s[mt][nt][0] = -10000.f;
                    if (cb + 1 > rbase) s[mt][nt][1] = -10000.f;
                    if (cb > rbase + 8)     s[mt][nt][2] = -10000.f;
                    if (cb + 1 > rbase + 8) s[mt][nt][3] = -10000.f;
                }
            }
        }

        // ---- online softmax ----
        float corr[4];
#pragma unroll
        for (int slot = 0; slot < 4; ++slot) {
            const int mt = slot >> 1, h2 = slot & 1;
            float tm = -1e30f;
#pragma unroll
            for (int nt = 0; nt < 8; ++nt)
                tm = fmaxf(tm, fmaxf(s[mt][nt][h2 * 2], s[mt][nt][h2 * 2 + 1]));
            tm = fmaxf(tm, __shfl_xor_sync(0xffffffffu, tm, 1));
            tm = fmaxf(tm, __shfl_xor_sync(0xffffffffu, tm, 2));
            const float mnew = fmaxf(m_run[slot], tm);
            corr[slot] = __expf(m_run[slot] - mnew);
            m_run[slot] = mnew;
            l_run[slot] *= corr[slot];
        }
#pragma unroll
        for (int mt = 0; mt < 2; ++mt)
#pragma unroll
            for (int nt = 0; nt < 8; ++nt) {
                oacc[mt][nt][0] *= corr[mt * 2];
                oacc[mt][nt][1] *= corr[mt * 2];
                oacc[mt][nt][2] *= corr[mt * 2 + 1];
                oacc[mt][nt][3] *= corr[mt * 2 + 1];
            }

        // ---- P = exp(S - m), single fp16 pack into A fragments ----
        uint32_t pf[2][8][2];
#pragma unroll
        for (int mt = 0; mt < 2; ++mt)
#pragma unroll
            for (int nt = 0; nt < 8; ++nt) {
                const float p0 = __expf(s[mt][nt][0] - m_run[mt * 2]);
                const float p1 = __expf(s[mt][nt][1] - m_run[mt * 2]);
                const float p2 = __expf(s[mt][nt][2] - m_run[mt * 2 + 1]);
                const float p3 = __expf(s[mt][nt][3] - m_run[mt * 2 + 1]);
                l_run[mt * 2]     += p0 + p1;
                l_run[mt * 2 + 1] += p2 + p3;
                pf[mt][nt][0] = packh_f(p0, p1);
                pf[mt][nt][1] = packh_f(p2, p3);
            }

        // ---- O += P V (single product) ----
#pragma unroll
        for (int ks = 0; ks < 4; ++ks) {
            uint32_t vb[4][4];
#pragma unroll
            for (int nb = 0; nb < 4; ++nb) {
                const uint32_t bo = (uint32_t)(((grp >> 1) * 8 + l8 + nb * 16) * AROWB +
                                               (grp & 1) * 16 + ks * 32);
                ldsm4(kvb + AV_OFF + bo, vb[nb][0], vb[nb][1], vb[nb][2], vb[nb][3]);
            }
#pragma unroll
            for (int mt = 0; mt < 2; ++mt)
#pragma unroll
                for (int nt = 0; nt < 8; ++nt) {
                    const int nb = nt >> 1, p = nt & 1;
                    mma_f16(oacc[mt][nt][0], oacc[mt][nt][1], oacc[mt][nt][2], oacc[mt][nt][3],
                            pf[mt][ks * 2][0], pf[mt][ks * 2][1],
                            pf[mt][ks * 2 + 1][0], pf[mt][ks * 2 + 1][1],
                            vb[nb][p * 2], vb[nb][p * 2 + 1]);
                }
        }
        __syncthreads();
    }

    // ---- finalize: divide by row sums, split-2, write proj A operand ----
    float inv[4];
#pragma unroll
    for (int slot = 0; slot < 4; ++slot) {
        float lt = l_run[slot];
        lt += __shfl_xor_sync(0xffffffffu, lt, 1);
        lt += __shfl_xor_sync(0xffffffffu, lt, 2);
        inv[slot] = 1.f / lt;
    }
    const int b = bh >> 4, h = bh & 15;
#pragma unroll
    for (int mt = 0; mt < 2; ++mt) {
#pragma unroll
        for (int half = 0; half < 2; ++half) {
            const size_t orow = (size_t)b * SEQ + q0 + w * 32 + mt * 16 + row0 + half * 8;
            const float iv = inv[mt * 2 + half];
#pragma unroll
            for (int nt = 0; nt < 8; ++nt) {
                const int col = h * DHEAD + nt * 8 + coll;
                const float v0 = oacc[mt][nt][half * 2 + 0] * iv;
                const float v1 = oacc[mt][nt][half * 2 + 1] * iv;
                __half h0, l0, h1, l1;
                split2h(v0, h0, l0); split2h(v1, h1, l1);
                *(uint32_t*)(s_a_hi + orow * DIM + col) = packh(h0, h1);
                *(uint32_t*)(s_a_lo + orow * DIM + col) = packh(l0, l1);
            }
        }
    }
}

// ---------------------------------------------------------------------------
extern "C" void kernel_launch(void* const* d_in, const int* in_sizes, int n_in,
                              void* d_out, int out_size)
{
    const float* x      = (const float*)d_in[0];
    const float* w_attn = (const float*)d_in[1];
    const float* b_attn = (const float*)d_in[2];
    const float* w_proj = (const float*)d_in[3];
    const float* b_proj = (const float*)d_in[4];
    float* out = (float*)d_out;

    __half *xa_hi, *xa_lo, *wq, *wp;
    cudaGetSymbolAddress((void**)&xa_hi, s_a_hi);
    cudaGetSymbolAddress((void**)&xa_lo, s_a_lo);
    cudaGetSymbolAddress((void**)&wq, s_wq);
    cudaGetSymbolAddress((void**)&wp, s_wp);

    cudaFuncSetAttribute(tc_gemm_kernel,
                         cudaFuncAttributeMaxDynamicSharedMemorySize, GSM_BYTES);
    cudaFuncSetAttribute(attn_tc_kernel,
                         cudaFuncAttributeMaxDynamicSharedMemorySize, ASM_BYTES);

    // 1) split x -> fp16 hi/lo (A operand of QKV GEMM)
    split_kernel<<<(MROWS * KTOT / 4 + 255) / 256, 256>>>(x, xa_hi, xa_lo, MROWS * KTOT / 4);
    // 2) transpose weights -> single fp16
    transp_half_kernel<<<dim3(NQKV / 32, KTOT / 32), dim3(32, 8)>>>(w_attn, KTOT, NQKV, wq);
    transp_half_kernel<<<dim3(DIM / 32, KTOT / 32), dim3(32, 8)>>>(w_proj, KTOT, DIM, wp);
    // 3) QKV GEMM -> q split-2, k single, vt single
    tc_gemm_kernel<<<dim3(NQKV / BN, MROWS / BM), 256, GSM_BYTES>>>(
        xa_hi, xa_lo, wq, b_attn, nullptr, 0);
    // 4) tensor-core flash attention -> writes s_a_hi/s_a_lo
    attn_tc_kernel<<<dim3(SEQ / 128, BATCH * NHEAD), 128, ASM_BYTES>>>();
    // 5) output projection
    tc_gemm_kernel<<<dim3(DIM / BN, MROWS / BM), 256, GSM_BYTES>>>(
        xa_hi, xa_lo, wp, b_proj, out, 1);
}

// round 11
// speedup vs baseline: 1.8359x; 1.1068x over previous
#include <cuda_runtime.h>
#include <cuda_fp16.h>
#include <cstdint>

// Problem shape (fixed by the dataset)
#define BATCH 2
#define SEQ   2048
#define DIM   1024
#define NHEAD 16
#define DHEAD 64
#define MROWS (BATCH * SEQ)          // 4096
#define NQKV  (3 * DIM)              // 3072
#define KTOT  1024

// ---------------------------------------------------------------------------
// Scratch (allocation-free rule: __device__ globals)
// ---------------------------------------------------------------------------
__device__ __half s_a_hi[MROWS * KTOT];   // GEMM A: x(hi), then attn out (single)
__device__ __half s_a_lo[MROWS * KTOT];   // x(lo) only
__device__ __half s_wq[NQKV * KTOT];      // w_attn^T [3072,1024] single fp16
__device__ __half s_wp[DIM * KTOT];       // w_proj^T [1024,1024] single fp16
// attention operands, written by QKV epilogue
__device__ __half s_q_hi[BATCH * NHEAD * SEQ * DHEAD];  // [bh,s,dh], q*0.125
__device__ __half s_q_lo[BATCH * NHEAD * SEQ * DHEAD];
__device__ __half s_k [BATCH * NHEAD * SEQ * DHEAD];    // [bh,s,dh] single
__device__ __half s_vt[BATCH * NHEAD * DHEAD * SEQ];    // [bh,dh,s] single

// ---------------------------------------------------------------------------
// PTX helpers (baseline ISA — compiles for sm_103)
// ---------------------------------------------------------------------------
__device__ __forceinline__ uint32_t smem_u32(const void* p) {
    uint32_t a;
    asm("{ .reg .u64 t; cvta.to.shared.u64 t, %1; cvt.u32.u64 %0, t; }"
        : "=r"(a) : "l"(p));
    return a;
}
__device__ __forceinline__ void ldsm4(uint32_t addr, uint32_t& r0, uint32_t& r1,
                                      uint32_t& r2, uint32_t& r3) {
    asm volatile("ldmatrix.sync.aligned.m8n8.x4.shared.b16 {%0,%1,%2,%3}, [%4];"
                 : "=r"(r0), "=r"(r1), "=r"(r2), "=r"(r3) : "r"(addr));
}
__device__ __forceinline__ void mma_f16(float& c0, float& c1, float& c2, float& c3,
                                        uint32_t a0, uint32_t a1, uint32_t a2, uint32_t a3,
                                        uint32_t b0, uint32_t b1) {
    asm volatile("mma.sync.aligned.m16n8k16.row.col.f32.f16.f16.f32 "
                 "{%0,%1,%2,%3}, {%4,%5,%6,%7}, {%8,%9}, {%0,%1,%2,%3};"
                 : "+f"(c0), "+f"(c1), "+f"(c2), "+f"(c3)
                 : "r"(a0), "r"(a1), "r"(a2), "r"(a3), "r"(b0), "r"(b1));
}
__device__ __forceinline__ void cp16(uint32_t saddr, const void* g) {
    asm volatile("cp.async.cg.shared.global [%0], [%1], 16;"
                 :: "r"(saddr), "l"(g) : "memory");
}
__device__ __forceinline__ void cp_commit() {
    asm volatile("cp.async.commit_group;" ::: "memory");
}
template <int N>
__device__ __forceinline__ void cp_wait() {
    asm volatile("cp.async.wait_group %0;" :: "n"(N) : "memory");
}
__device__ __forceinline__ void split2h(float v, __half& h, __half& l) {
    h = __float2half_rn(v);
    l = __float2half_rn(v - __half2float(h));
}
__device__ __forceinline__ uint32_t packh(__half a, __half b) {
    __half2 p = __halves2half2(a, b);
    return *(uint32_t*)&p;
}
__device__ __forceinline__ uint32_t packh_f(float a, float b) {
    __half2 p = __floats2half2_rn(a, b);
    return *(uint32_t*)&p;
}

// ---------------------------------------------------------------------------
// Prep kernels
// ---------------------------------------------------------------------------
__global__ __launch_bounds__(256) void split_kernel(
    const float* __restrict__ src, __half* __restrict__ hi,
    __half* __restrict__ lo, int n4)
{
    int i = blockIdx.x * 256 + threadIdx.x;
    if (i >= n4) return;
    float4 v = ((const float4*)src)[i];
    __half h0, l0, h1, l1, h2, l2, h3, l3;
    split2h(v.x, h0, l0); split2h(v.y, h1, l1);
    split2h(v.z, h2, l2); split2h(v.w, h3, l3);
    uint2 uh = make_uint2(packh(h0, h1), packh(h2, h3));
    uint2 ul = make_uint2(packh(l0, l1), packh(l2, l3));
    *(uint2*)(hi + (size_t)i * 4) = uh;
    *(uint2*)(lo + (size_t)i * 4) = ul;
}

__global__ __launch_bounds__(256) void transp_half_kernel(
    const float* __restrict__ w, int K, int N, __half* __restrict__ outp)
{
    __shared__ float t[32][33];
    const int tx = threadIdx.x, ty = threadIdx.y;
    const int n0 = blockIdx.x * 32, k0 = blockIdx.y * 32;
#pragma unroll
    for (int i = 0; i < 4; ++i)
        t[ty + i * 8][tx] = w[(size_t)(k0 + ty + i * 8) * N + n0 + tx];
    __syncthreads();
#pragma unroll
    for (int i = 0; i < 4; ++i) {
        const int n = n0 + ty + i * 8;
        outp[(size_t)n * K + k0 + tx] = __float2half_rn(t[tx][ty + i * 8]);
    }
}

// ---------------------------------------------------------------------------
// HMMA GEMM, fp16, 3-stage cp.async, ONE barrier per K-iter, 2 CTAs/SM.
// D[M,N] = A @ B^T + bias. ASPLIT: A = hi + lo (2 products) vs single.
// MODE 0: QKV epilogue -> q split-2, k single, vt single (transposed)
// MODE 1: plain fp32 out
// ---------------------------------------------------------------------------
#define BM 128
#define BN 128
#define BK 32
#define ROWB 80
#define NKT (KTOT / BK)          // 32
#define OFF_ALO 10240
#define OFF_B   20480
#define STG_BYTES 30720
#define NSTAGE 3
#define GSM_BYTES (NSTAGE * STG_BYTES)   // 92160/CTA; x2 CTAs = 184KB/SM

template <int ASPLIT, int MODE>
__global__ __launch_bounds__(256, 2) void tc_gemm_kernel(
    const __half* __restrict__ Ahi, const __half* __restrict__ Alo,
    const __half* __restrict__ B,
    const float* __restrict__ bias, float* __restrict__ outp)
{
    extern __shared__ char gsm[];
    const uint32_t sb = smem_u32(gsm);

    const int tid  = threadIdx.x;
    const int w    = tid >> 5;
    const int lane = tid & 31;
    const int m0 = blockIdx.y * BM;
    const int n0 = blockIdx.x * BN;
    const int wm = (w >> 2) * 64;
    const int wn = (w & 3) * 32;

    const int srow = tid >> 2;
    const int sseg = tid & 3;
    const size_t gA = (size_t)(m0 + srow) * KTOT + sseg * 8;
    const size_t gB = (size_t)(n0 + srow) * KTOT + sseg * 8;
    const size_t rstep = (size_t)64 * KTOT;
    const uint32_t soff0 = (uint32_t)(srow * ROWB + sseg * 16);
    const uint32_t soff1 = soff0 + 64 * ROWB;

    auto load_stage = [&](int kt, int stg) {
        const uint32_t s0 = sb + stg * STG_BYTES;
        const __half* pa = Ahi + gA + (size_t)kt * BK;
        const __half* pb = B   + gB + (size_t)kt * BK;
        cp16(s0 + soff0, pa);           cp16(s0 + soff1, pa + rstep);
        if (ASPLIT) {
            const __half* pal = Alo + gA + (size_t)kt * BK;
            cp16(s0 + OFF_ALO + soff0, pal);
            cp16(s0 + OFF_ALO + soff1, pal + rstep);
        }
        cp16(s0 + OFF_B + soff0, pb);   cp16(s0 + OFF_B + soff1, pb + rstep);
    };

    float acc[4][4][4];
#pragma unroll
    for (int i = 0; i < 4; ++i)
#pragma unroll
        for (int j = 0; j < 4; ++j)
#pragma unroll
            for (int e = 0; e < 4; ++e) acc[i][j][e] = 0.f;

    const int ar = lane & 15, ah = lane >> 4;
    const uint32_t aoffb = (uint32_t)((wm + ar) * ROWB + ah * 16);
    const int grp = lane >> 3, l8 = lane & 7;
    const uint32_t boffb = (uint32_t)((wn + ((grp >> 1) << 3) + l8) * ROWB + (grp & 1) * 16);

    load_stage(0, 0);
    cp_commit();
    load_stage(1, 1);
    cp_commit();

    int stg = 0;
    for (int kt = 0; kt < NKT; ++kt) {
        if (kt + 1 < NKT) cp_wait<1>(); else cp_wait<0>();
        // Single barrier: warps arrive having finished compute kt-1, so
        // stage (kt-1)%3 == (kt+2)%3 is free for the load issued below.
        __syncthreads();

        if (kt + 2 < NKT) {
            int s2 = stg + 2; if (s2 >= NSTAGE) s2 -= NSTAGE;
            load_stage(kt + 2, s2);
            cp_commit();
        }

        const uint32_t s0 = sb + stg * STG_BYTES;
#pragma unroll
        for (int ks = 0; ks < 2; ++ks) {
            const uint32_t akoff = s0 + aoffb + ks * 32;
            const uint32_t bkoff = s0 + OFF_B + boffb + ks * 32;

            uint32_t fah[4][4];
#pragma unroll
            for (int mt = 0; mt < 4; ++mt)
                ldsm4(akoff + mt * 16 * ROWB,
                      fah[mt][0], fah[mt][1], fah[mt][2], fah[mt][3]);
            uint32_t fb[8];
            ldsm4(bkoff,             fb[0], fb[1], fb[2], fb[3]);
            ldsm4(bkoff + 16 * ROWB, fb[4], fb[5], fb[6], fb[7]);

#pragma unroll
            for (int mt = 0; mt < 4; ++mt)
#pragma unroll
                for (int nt = 0; nt < 4; ++nt)
                    mma_f16(acc[mt][nt][0], acc[mt][nt][1], acc[mt][nt][2], acc[mt][nt][3],
                            fah[mt][0], fah[mt][1], fah[mt][2], fah[mt][3],
                            fb[nt * 2], fb[nt * 2 + 1]);
            if (ASPLIT) {
                uint32_t fal[4][4];
#pragma unroll
                for (int mt = 0; mt < 4; ++mt)
                    ldsm4(akoff + OFF_ALO + mt * 16 * ROWB,
                          fal[mt][0], fal[mt][1], fal[mt][2], fal[mt][3]);
#pragma unroll
                for (int mt = 0; mt < 4; ++mt)
#pragma unroll
                    for (int nt = 0; nt < 4; ++nt)
                        mma_f16(acc[mt][nt][0], acc[mt][nt][1], acc[mt][nt][2], acc[mt][nt][3],
                                fal[mt][0], fal[mt][1], fal[mt][2], fal[mt][3],
                                fb[nt * 2], fb[nt * 2 + 1]);
            }
        }
        if (++stg >= NSTAGE) stg = 0;
    }

    // epilogue
    const int erow = (lane >> 2);
    const int ecol = (lane & 3) * 2;
#pragma unroll
    for (int mt = 0; mt < 4; ++mt) {
#pragma unroll
        for (int nt = 0; nt < 4; ++nt) {
#pragma unroll
            for (int half = 0; half < 2; ++half) {
                const int row = m0 + wm + mt * 16 + erow + half * 8;
                const int col = n0 + wn + nt * 8 + ecol;
                float v0 = acc[mt][nt][half * 2 + 0] + bias[col];
                float v1 = acc[mt][nt][half * 2 + 1] + bias[col + 1];
                if (MODE == 0) {
                    const int bb = row >> 11, s = row & 2047;
                    const int part = col >> 10;
                    const int dd = col & 1023;
                    const int h = dd >> 6, hd = dd & 63;
                    const int bh = (bb << 4) + h;
                    if (part == 0) {
                        v0 *= 0.125f; v1 *= 0.125f;
                        const size_t base = ((size_t)bh * SEQ + s) * DHEAD + hd;
                        __half h0, l0, h1, l1;
                        split2h(v0, h0, l0); split2h(v1, h1, l1);
                        *(uint32_t*)(s_q_hi + base) = packh(h0, h1);
                        *(uint32_t*)(s_q_lo + base) = packh(l0, l1);
                    } else if (part == 1) {
                        const size_t base = ((size_t)bh * SEQ + s) * DHEAD + hd;
                        *(uint32_t*)(s_k + base) = packh_f(v0, v1);
                    } else {
                        const size_t base = ((size_t)bh * DHEAD + hd) * SEQ + s;
                        s_vt[base]       = __float2half_rn(v0);
                        s_vt[base + SEQ] = __float2half_rn(v1);
                    }
                } else {
                    *(float2*)(outp + (size_t)row * DIM + col) = make_float2(v0, v1);
                }
            }
        }
    }
}

// ---------------------------------------------------------------------------
// Tensor-core flash attention, fp16: QK = Qsplit2 x Ksingle (2 products),
// PV = Psingle x Vsingle (1 product). fp32 softmax. cp.async 2-stage KV,
// 2 CTAs/SM. Finalize writes SINGLE fp16 into s_a_hi (proj uses single A).
// ---------------------------------------------------------------------------
#define AROWB 144
#define AQ_H 0
#define AQ_L 18432
#define AKV0 36864
#define AKV_STG 18432          // K (9216) + VT (9216)
#define AV_OFF 9216
#define ASM_BYTES (AKV0 + 2 * AKV_STG)   // 73728; x2 CTAs = 144KB/SM

__global__ __launch_bounds__(128, 2) void attn_tc_kernel()
{
    extern __shared__ char asmem[];
    const uint32_t sb = smem_u32(asmem);
    const int tid  = threadIdx.x;
    const int w    = tid >> 5;
    const int lane = tid & 31;
    const int qt   = blockIdx.x;
    const int bh   = blockIdx.y;
    const int q0   = qt * 128;

    const __half* Qh = s_q_hi + (size_t)bh * SEQ * DHEAD;
    const __half* Ql = s_q_lo + (size_t)bh * SEQ * DHEAD;
    const __half* Kg = s_k    + (size_t)bh * SEQ * DHEAD;
    const __half* Vg = s_vt   + (size_t)bh * DHEAD * SEQ;

    auto load_kv = [&](int kt, int stg) {
        const uint32_t s0 = sb + AKV0 + stg * AKV_STG;
        const int kv0 = kt * 64;
#pragma unroll
        for (int i = 0; i < 4; ++i) {
            const int c = tid + i * 128;
            const int row = c >> 3, seg = c & 7;
            const uint32_t so = row * AROWB + seg * 16;
            const size_t gk = (size_t)(kv0 + row) * DHEAD + seg * 8;
            const size_t gv = (size_t)row * SEQ + kv0 + seg * 8;
            cp16(s0 + so, Kg + gk);
            cp16(s0 + AV_OFF + so, Vg + gv);
        }
    };

    // Q tile (128 rows x 64 fp16) hi/lo
#pragma unroll
    for (int i = 0; i < 8; ++i) {
        const int c = tid + i * 128;
        const int row = c >> 3, seg = c & 7;
        const uint32_t so = row * AROWB + seg * 16;
        const size_t go = (size_t)(q0 + row) * DHEAD + seg * 8;
        *(uint4*)(asmem + AQ_H + so) = *(const uint4*)(Qh + go);
        *(uint4*)(asmem + AQ_L + so) = *(const uint4*)(Ql + go);
    }

    const int ar = lane & 15, ahh = lane >> 4;
    const int grp = lane >> 3, l8 = lane & 7;
    const int row0 = lane >> 2, coll = (lane & 3) * 2;

    float m_run[4], l_run[4];
#pragma unroll
    for (int i = 0; i < 4; ++i) { m_run[i] = -1e30f; l_run[i] = 0.f; }
    float oacc[2][8][4];
#pragma unroll
    for (int mt = 0; mt < 2; ++mt)
#pragma unroll
        for (int nt = 0; nt < 8; ++nt)
#pragma unroll
            for (int e = 0; e < 4; ++e) oacc[mt][nt][e] = 0.f;

    const int ntiles = qt * 2 + 2;
    load_kv(0, 0);
    cp_commit();

    for (int kt = 0; kt < ntiles; ++kt) {
        if (kt + 1 < ntiles) {
            load_kv(kt + 1, (kt + 1) & 1);
            cp_commit();
            cp_wait<1>();
        } else {
            cp_wait<0>();
        }
        __syncthreads();

        const uint32_t kvb = sb + AKV0 + (kt & 1) * AKV_STG;
        const int kv0 = kt * 64;

        // ---- scores: S = Q K^T (Q split-2, K single) ----
        float s[2][8][4];
#pragma unroll
        for (int mt = 0; mt < 2; ++mt)
#pragma unroll
            for (int nt = 0; nt < 8; ++nt)
#pragma unroll
                for (int e = 0; e < 4; ++e) s[mt][nt][e] = 0.f;

#pragma unroll
        for (int ks = 0; ks < 4; ++ks) {
            uint32_t kb[4][4];
#pragma unroll
            for (int nb = 0; nb < 4; ++nb) {
                const uint32_t bo = (uint32_t)(((grp >> 1) * 8 + l8 + nb * 16) * AROWB +
                                               (grp & 1) * 16 + ks * 32);
                ldsm4(kvb + bo, kb[nb][0], kb[nb][1], kb[nb][2], kb[nb][3]);
            }
            uint32_t qh[2][4], ql[2][4];
#pragma unroll
            for (int mt = 0; mt < 2; ++mt) {
                const uint32_t ao = (uint32_t)((w * 32 + mt * 16 + ar) * AROWB +
                                               ahh * 16 + ks * 32);
                ldsm4(sb + AQ_H + ao, qh[mt][0], qh[mt][1], qh[mt][2], qh[mt][3]);
                ldsm4(sb + AQ_L + ao, ql[mt][0], ql[mt][1], ql[mt][2], ql[mt][3]);
            }
#pragma unroll
            for (int mt = 0; mt < 2; ++mt)
#pragma unroll
                for (int nt = 0; nt < 8; ++nt) {
                    const int nb = nt >> 1, p = nt & 1;
                    mma_f16(s[mt][nt][0], s[mt][nt][1], s[mt][nt][2], s[mt][nt][3],
                            qh[mt][0], qh[mt][1], qh[mt][2], qh[mt][3],
                            kb[nb][p * 2], kb[nb][p * 2 + 1]);
                }
#pragma unroll
            for (int mt = 0; mt < 2; ++mt)
#pragma unroll
                for (int nt = 0; nt < 8; ++nt) {
                    const int nb = nt >> 1, p = nt & 1;
                    mma_f16(s[mt][nt][0], s[mt][nt][1], s[mt][nt][2], s[mt][nt][3],
                            ql[mt][0], ql[mt][1], ql[mt][2], ql[mt][3],
                            kb[nb][p * 2], kb[nb][p * 2 + 1]);
                }
        }

        // ---- causal mask ----
        if (kt >= qt * 2) {
#pragma unroll
            for (int mt = 0; mt < 2; ++mt) {
                const int rbase = q0 + w * 32 + mt * 16 + row0;
#pragma unroll
                for (int nt = 0; nt < 8; ++nt) {
                    const int cb = kv0 + nt * 8 + coll;
                    if (cb > rbase)     s[mt][nt][0] = -10000.f;
                    if (cb + 1 > rbase) s[mt][nt][1] = -10000.f;
                    if (cb > rbase + 8)     s[mt][nt][2] = -10000.f;
                    if (cb + 1 > rbase + 8) s[mt][nt][3] = -10000.f;
                }
            }
        }

        // ---- online softmax ----
        float corr[4];
#pragma unroll
        for (int slot = 0; slot < 4; ++slot) {
            const int mt = slot >> 1, h2 = slot & 1;
            float tm = -1e30f;
#pragma unroll
            for (int nt = 0; nt < 8; ++nt)
                tm = fmaxf(tm, fmaxf(s[mt][nt][h2 * 2], s[mt][nt][h2 * 2 + 1]));
            tm = fmaxf(tm, __shfl_xor_sync(0xffffffffu, tm, 1));
            tm = fmaxf(tm, __shfl_xor_sync(0xffffffffu, tm, 2));
            const float mnew = fmaxf(m_run[slot], tm);
            corr[slot] = __expf(m_run[slot] - mnew);
            m_run[slot] = mnew;
            l_run[slot] *= corr[slot];
        }
#pragma unroll
        for (int mt = 0; mt < 2; ++mt)
#pragma unroll
            for (int nt = 0; nt < 8; ++nt) {
                oacc[mt][nt][0] *= corr[mt * 2];
                oacc[mt][nt][1] *= corr[mt * 2];
                oacc[mt][nt][2] *= corr[mt * 2 + 1];
                oacc[mt][nt][3] *= corr[mt * 2 + 1];
            }

        // ---- P = exp(S - m), single fp16 pack ----
        uint32_t pf[2][8][2];
#pragma unroll
        for (int mt = 0; mt < 2; ++mt)
#pragma unroll
            for (int nt = 0; nt < 8; ++nt) {
                const float p0 = __expf(s[mt][nt][0] - m_run[mt * 2]);
                const float p1 = __expf(s[mt][nt][1] - m_run[mt * 2]);
                const float p2 = __expf(s[mt][nt][2] - m_run[mt * 2 + 1]);
                const float p3 = __expf(s[mt][nt][3] - m_run[mt * 2 + 1]);
                l_run[mt * 2]     += p0 + p1;
                l_run[mt * 2 + 1] += p2 + p3;
                pf[mt][nt][0] = packh_f(p0, p1);
                pf[mt][nt][1] = packh_f(p2, p3);
            }

        // ---- O += P V (single product) ----
#pragma unroll
        for (int ks = 0; ks < 4; ++ks) {
            uint32_t vb[4][4];
#pragma unroll
            for (int nb = 0; nb < 4; ++nb) {
                const uint32_t bo = (uint32_t)(((grp >> 1) * 8 + l8 + nb * 16) * AROWB +
                                               (grp & 1) * 16 + ks * 32);
                ldsm4(kvb + AV_OFF + bo, vb[nb][0], vb[nb][1], vb[nb][2], vb[nb][3]);
            }
#pragma unroll
            for (int mt = 0; mt < 2; ++mt)
#pragma unroll
                for (int nt = 0; nt < 8; ++nt) {
                    const int nb = nt >> 1, p = nt & 1;
                    mma_f16(oacc[mt][nt][0], oacc[mt][nt][1], oacc[mt][nt][2], oacc[mt][nt][3],
                            pf[mt][ks * 2][0], pf[mt][ks * 2][1],
                            pf[mt][ks * 2 + 1][0], pf[mt][ks * 2 + 1][1],
                            vb[nb][p * 2], vb[nb][p * 2 + 1]);
                }
        }
        __syncthreads();
    }

    // ---- finalize: divide by row sums, write SINGLE fp16 proj A operand ----
    float inv[4];
#pragma unroll
    for (int slot = 0; slot < 4; ++slot) {
        float lt = l_run[slot];
        lt += __shfl_xor_sync(0xffffffffu, lt, 1);
        lt += __shfl_xor_sync(0xffffffffu, lt, 2);
        inv[slot] = 1.f / lt;
    }
    const int b = bh >> 4, h = bh & 15;
#pragma unroll
    for (int mt = 0; mt < 2; ++mt) {
#pragma unroll
        for (int half = 0; half < 2; ++half) {
            const size_t orow = (size_t)b * SEQ + q0 + w * 32 + mt * 16 + row0 + half * 8;
            const float iv = inv[mt * 2 + half];
#pragma unroll
            for (int nt = 0; nt < 8; ++nt) {
                const int col = h * DHEAD + nt * 8 + coll;
                const float v0 = oacc[mt][nt][half * 2 + 0] * iv;
                const float v1 = oacc[mt][nt][half * 2 + 1] * iv;
                *(uint32_t*)(s_a_hi + orow * DIM + col) = packh_f(v0, v1);
            }
        }
    }
}

// ---------------------------------------------------------------------------
extern "C" void kernel_launch(void* const* d_in, const int* in_sizes, int n_in,
                              void* d_out, int out_size)
{
    const float* x      = (const float*)d_in[0];
    const float* w_attn = (const float*)d_in[1];
    const float* b_attn = (const float*)d_in[2];
    const float* w_proj = (const float*)d_in[3];
    const float* b_proj = (const float*)d_in[4];
    float* out = (float*)d_out;

    __half *xa_hi, *xa_lo, *wq, *wp;
    cudaGetSymbolAddress((void**)&xa_hi, s_a_hi);
    cudaGetSymbolAddress((void**)&xa_lo, s_a_lo);
    cudaGetSymbolAddress((void**)&wq, s_wq);
    cudaGetSymbolAddress((void**)&wp, s_wp);

    cudaFuncSetAttribute(tc_gemm_kernel<1, 0>,
                         cudaFuncAttributeMaxDynamicSharedMemorySize, GSM_BYTES);
    cudaFuncSetAttribute(tc_gemm_kernel<0, 1>,
                         cudaFuncAttributeMaxDynamicSharedMemorySize, GSM_BYTES);
    cudaFuncSetAttribute(attn_tc_kernel,
                         cudaFuncAttributeMaxDynamicSharedMemorySize, ASM_BYTES);

    // 1) split x -> fp16 hi/lo (A operand of QKV GEMM)
    split_kernel<<<(MROWS * KTOT / 4 + 255) / 256, 256>>>(x, xa_hi, xa_lo, MROWS * KTOT / 4);
    // 2) transpose weights -> single fp16
    transp_half_kernel<<<dim3(NQKV / 32, KTOT / 32), dim3(32, 8)>>>(w_attn, KTOT, NQKV, wq);
    transp_half_kernel<<<dim3(DIM / 32, KTOT / 32), dim3(32, 8)>>>(w_proj, KTOT, DIM, wp);
    // 3) QKV GEMM (A split-2) -> q split-2, k single, vt single
    tc_gemm_kernel<1, 0><<<dim3(NQKV / BN, MROWS / BM), 256, GSM_BYTES>>>(
        xa_hi, xa_lo, wq, b_attn, nullptr);
    // 4) tensor-core flash attention -> writes s_a_hi (single fp16)
    attn_tc_kernel<<<dim3(SEQ / 128, BATCH * NHEAD), 128, ASM_BYTES>>>();
    // 5) output projection (A single fp16)
    tc_gemm_kernel<0, 1><<<dim3(DIM / BN, MROWS / BM), 256, GSM_BYTES>>>(
        xa_hi, xa_lo, wp, b_proj, out);
}

// round 12
// speedup vs baseline: 2.2673x; 1.2350x over previous
#include <cuda_runtime.h>
#include <cuda_fp16.h>
#include <cstdint>

// Problem shape (fixed by the dataset)
#define BATCH 2
#define SEQ   2048
#define DIM   1024
#define NHEAD 16
#define DHEAD 64
#define MROWS (BATCH * SEQ)          // 4096
#define NQKV  (3 * DIM)              // 3072
#define KTOT  1024

// ---------------------------------------------------------------------------
// Scratch (allocation-free rule: __device__ globals)
// ---------------------------------------------------------------------------
__device__ __half s_a_hi[MROWS * KTOT];   // GEMM A: x (single), then attn out (single)
__device__ __half s_a_lo[MROWS * KTOT];   // unused for x now; kept for layout
__device__ __half s_wq[NQKV * KTOT];      // w_attn^T [3072,1024] single fp16
__device__ __half s_wp[DIM * KTOT];       // w_proj^T [1024,1024] single fp16
// attention operands, written by QKV epilogue
__device__ __half s_q_hi[BATCH * NHEAD * SEQ * DHEAD];  // [bh,s,dh], q*0.125
__device__ __half s_q_lo[BATCH * NHEAD * SEQ * DHEAD];
__device__ __half s_k [BATCH * NHEAD * SEQ * DHEAD];    // [bh,s,dh] single
__device__ __half s_vt[BATCH * NHEAD * DHEAD * SEQ];    // [bh,dh,s] single

// ---------------------------------------------------------------------------
// PTX helpers (baseline ISA — compiles for sm_103)
// ---------------------------------------------------------------------------
__device__ __forceinline__ uint32_t smem_u32(const void* p) {
    uint32_t a;
    asm("{ .reg .u64 t; cvta.to.shared.u64 t, %1; cvt.u32.u64 %0, t; }"
        : "=r"(a) : "l"(p));
    return a;
}
__device__ __forceinline__ void ldsm4(uint32_t addr, uint32_t& r0, uint32_t& r1,
                                      uint32_t& r2, uint32_t& r3) {
    asm volatile("ldmatrix.sync.aligned.m8n8.x4.shared.b16 {%0,%1,%2,%3}, [%4];"
                 : "=r"(r0), "=r"(r1), "=r"(r2), "=r"(r3) : "r"(addr));
}
__device__ __forceinline__ void mma_f16(float& c0, float& c1, float& c2, float& c3,
                                        uint32_t a0, uint32_t a1, uint32_t a2, uint32_t a3,
                                        uint32_t b0, uint32_t b1) {
    asm volatile("mma.sync.aligned.m16n8k16.row.col.f32.f16.f16.f32 "
                 "{%0,%1,%2,%3}, {%4,%5,%6,%7}, {%8,%9}, {%0,%1,%2,%3};"
                 : "+f"(c0), "+f"(c1), "+f"(c2), "+f"(c3)
                 : "r"(a0), "r"(a1), "r"(a2), "r"(a3), "r"(b0), "r"(b1));
}
__device__ __forceinline__ void cp16(uint32_t saddr, const void* g) {
    asm volatile("cp.async.cg.shared.global [%0], [%1], 16;"
                 :: "r"(saddr), "l"(g) : "memory");
}
__device__ __forceinline__ void cp_commit() {
    asm volatile("cp.async.commit_group;" ::: "memory");
}
template <int N>
__device__ __forceinline__ void cp_wait() {
    asm volatile("cp.async.wait_group %0;" :: "n"(N) : "memory");
}
__device__ __forceinline__ void split2h(float v, __half& h, __half& l) {
    h = __float2half_rn(v);
    l = __float2half_rn(v - __half2float(h));
}
__device__ __forceinline__ uint32_t packh(__half a, __half b) {
    __half2 p = __halves2half2(a, b);
    return *(uint32_t*)&p;
}
__device__ __forceinline__ uint32_t packh_f(float a, float b) {
    __half2 p = __floats2half2_rn(a, b);
    return *(uint32_t*)&p;
}

// ---------------------------------------------------------------------------
// Prep kernels
// ---------------------------------------------------------------------------
__global__ __launch_bounds__(256) void convert_half_kernel(
    const float* __restrict__ src, __half* __restrict__ dst, int n4)
{
    int i = blockIdx.x * 256 + threadIdx.x;
    if (i >= n4) return;
    float4 v = ((const float4*)src)[i];
    uint2 u = make_uint2(packh_f(v.x, v.y), packh_f(v.z, v.w));
    *(uint2*)(dst + (size_t)i * 4) = u;
}

__global__ __launch_bounds__(256) void transp_half_kernel(
    const float* __restrict__ w, int K, int N, __half* __restrict__ outp)
{
    __shared__ float t[32][33];
    const int tx = threadIdx.x, ty = threadIdx.y;
    const int n0 = blockIdx.x * 32, k0 = blockIdx.y * 32;
#pragma unroll
    for (int i = 0; i < 4; ++i)
        t[ty + i * 8][tx] = w[(size_t)(k0 + ty + i * 8) * N + n0 + tx];
    __syncthreads();
#pragma unroll
    for (int i = 0; i < 4; ++i) {
        const int n = n0 + ty + i * 8;
        outp[(size_t)n * K + k0 + tx] = __float2half_rn(t[tx][ty + i * 8]);
    }
}

// ---------------------------------------------------------------------------
// HMMA GEMM, fp16, 3-stage cp.async, ONE barrier per K-iter, 2 CTAs/SM.
// D[M,N] = A @ B^T + bias. ASPLIT: A = hi + lo (2 products) vs single.
// MODE 0: QKV epilogue -> q split-2, k single, vt single (transposed)
// MODE 1: plain fp32 out
// ---------------------------------------------------------------------------
#define BM 128
#define BN 128
#define BK 32
#define ROWB 80
#define NKT (KTOT / BK)          // 32
#define OFF_ALO 10240
#define OFF_B   20480
#define STG_BYTES 30720
#define NSTAGE 3
#define GSM_BYTES (NSTAGE * STG_BYTES)   // 92160/CTA; x2 CTAs = 184KB/SM

template <int ASPLIT, int MODE>
__global__ __launch_bounds__(256, 2) void tc_gemm_kernel(
    const __half* __restrict__ Ahi, const __half* __restrict__ Alo,
    const __half* __restrict__ B,
    const float* __restrict__ bias, float* __restrict__ outp)
{
    extern __shared__ char gsm[];
    const uint32_t sb = smem_u32(gsm);

    const int tid  = threadIdx.x;
    const int w    = tid >> 5;
    const int lane = tid & 31;
    const int m0 = blockIdx.y * BM;
    const int n0 = blockIdx.x * BN;
    const int wm = (w >> 2) * 64;
    const int wn = (w & 3) * 32;

    const int srow = tid >> 2;
    const int sseg = tid & 3;
    const size_t gA = (size_t)(m0 + srow) * KTOT + sseg * 8;
    const size_t gB = (size_t)(n0 + srow) * KTOT + sseg * 8;
    const size_t rstep = (size_t)64 * KTOT;
    const uint32_t soff0 = (uint32_t)(srow * ROWB + sseg * 16);
    const uint32_t soff1 = soff0 + 64 * ROWB;

    auto load_stage = [&](int kt, int stg) {
        const uint32_t s0 = sb + stg * STG_BYTES;
        const __half* pa = Ahi + gA + (size_t)kt * BK;
        const __half* pb = B   + gB + (size_t)kt * BK;
        cp16(s0 + soff0, pa);           cp16(s0 + soff1, pa + rstep);
        if (ASPLIT) {
            const __half* pal = Alo + gA + (size_t)kt * BK;
            cp16(s0 + OFF_ALO + soff0, pal);
            cp16(s0 + OFF_ALO + soff1, pal + rstep);
        }
        cp16(s0 + OFF_B + soff0, pb);   cp16(s0 + OFF_B + soff1, pb + rstep);
    };

    float acc[4][4][4];
#pragma unroll
    for (int i = 0; i < 4; ++i)
#pragma unroll
        for (int j = 0; j < 4; ++j)
#pragma unroll
            for (int e = 0; e < 4; ++e) acc[i][j][e] = 0.f;

    const int ar = lane & 15, ah = lane >> 4;
    const uint32_t aoffb = (uint32_t)((wm + ar) * ROWB + ah * 16);
    const int grp = lane >> 3, l8 = lane & 7;
    const uint32_t boffb = (uint32_t)((wn + ((grp >> 1) << 3) + l8) * ROWB + (grp & 1) * 16);

    load_stage(0, 0);
    cp_commit();
    load_stage(1, 1);
    cp_commit();

    int stg = 0;
    for (int kt = 0; kt < NKT; ++kt) {
        if (kt + 1 < NKT) cp_wait<1>(); else cp_wait<0>();
        __syncthreads();

        if (kt + 2 < NKT) {
            int s2 = stg + 2; if (s2 >= NSTAGE) s2 -= NSTAGE;
            load_stage(kt + 2, s2);
            cp_commit();
        }

        const uint32_t s0 = sb + stg * STG_BYTES;
#pragma unroll
        for (int ks = 0; ks < 2; ++ks) {
            const uint32_t akoff = s0 + aoffb + ks * 32;
            const uint32_t bkoff = s0 + OFF_B + boffb + ks * 32;

            uint32_t fah[4][4];
#pragma unroll
            for (int mt = 0; mt < 4; ++mt)
                ldsm4(akoff + mt * 16 * ROWB,
                      fah[mt][0], fah[mt][1], fah[mt][2], fah[mt][3]);
            uint32_t fb[8];
            ldsm4(bkoff,             fb[0], fb[1], fb[2], fb[3]);
            ldsm4(bkoff + 16 * ROWB, fb[4], fb[5], fb[6], fb[7]);

#pragma unroll
            for (int mt = 0; mt < 4; ++mt)
#pragma unroll
                for (int nt = 0; nt < 4; ++nt)
                    mma_f16(acc[mt][nt][0], acc[mt][nt][1], acc[mt][nt][2], acc[mt][nt][3],
                            fah[mt][0], fah[mt][1], fah[mt][2], fah[mt][3],
                            fb[nt * 2], fb[nt * 2 + 1]);
            if (ASPLIT) {
                uint32_t fal[4][4];
#pragma unroll
                for (int mt = 0; mt < 4; ++mt)
                    ldsm4(akoff + OFF_ALO + mt * 16 * ROWB,
                          fal[mt][0], fal[mt][1], fal[mt][2], fal[mt][3]);
#pragma unroll
                for (int mt = 0; mt < 4; ++mt)
#pragma unroll
                    for (int nt = 0; nt < 4; ++nt)
                        mma_f16(acc[mt][nt][0], acc[mt][nt][1], acc[mt][nt][2], acc[mt][nt][3],
                                fal[mt][0], fal[mt][1], fal[mt][2], fal[mt][3],
                                fb[nt * 2], fb[nt * 2 + 1]);
            }
        }
        if (++stg >= NSTAGE) stg = 0;
    }

    // epilogue
    const int erow = (lane >> 2);
    const int ecol = (lane & 3) * 2;
#pragma unroll
    for (int mt = 0; mt < 4; ++mt) {
#pragma unroll
        for (int nt = 0; nt < 4; ++nt) {
#pragma unroll
            for (int half = 0; half < 2; ++half) {
                const int row = m0 + wm + mt * 16 + erow + half * 8;
                const int col = n0 + wn + nt * 8 + ecol;
                float v0 = acc[mt][nt][half * 2 + 0] + bias[col];
                float v1 = acc[mt][nt][half * 2 + 1] + bias[col + 1];
                if (MODE == 0) {
                    const int bb = row >> 11, s = row & 2047;
                    const int part = col >> 10;
                    const int dd = col & 1023;
                    const int h = dd >> 6, hd = dd & 63;
                    const int bh = (bb << 4) + h;
                    if (part == 0) {
                        v0 *= 0.125f; v1 *= 0.125f;
                        const size_t base = ((size_t)bh * SEQ + s) * DHEAD + hd;
                        __half h0, l0, h1, l1;
                        split2h(v0, h0, l0); split2h(v1, h1, l1);
                        *(uint32_t*)(s_q_hi + base) = packh(h0, h1);
                        *(uint32_t*)(s_q_lo + base) = packh(l0, l1);
                    } else if (part == 1) {
                        const size_t base = ((size_t)bh * SEQ + s) * DHEAD + hd;
                        *(uint32_t*)(s_k + base) = packh_f(v0, v1);
                    } else {
                        const size_t base = ((size_t)bh * DHEAD + hd) * SEQ + s;
                        s_vt[base]       = __float2half_rn(v0);
                        s_vt[base + SEQ] = __float2half_rn(v1);
                    }
                } else {
                    *(float2*)(outp + (size_t)row * DIM + col) = make_float2(v0, v1);
                }
            }
        }
    }
}

// ---------------------------------------------------------------------------
// Tensor-core flash attention, fp16: QK = Qsplit2 x Ksingle (2 products),
// PV = Psingle x Vsingle (1 product). fp32 softmax. cp.async 2-stage KV,
// 2 CTAs/SM. Finalize writes SINGLE fp16 into s_a_hi (proj uses single A).
// (unchanged from R11)
// ---------------------------------------------------------------------------
#define AROWB 144
#define AQ_H 0
#define AQ_L 18432
#define AKV0 36864
#define AKV_STG 18432          // K (9216) + VT (9216)
#define AV_OFF 9216
#define ASM_BYTES (AKV0 + 2 * AKV_STG)   // 73728; x2 CTAs = 144KB/SM

__global__ __launch_bounds__(128, 2) void attn_tc_kernel()
{
    extern __shared__ char asmem[];
    const uint32_t sb = smem_u32(asmem);
    const int tid  = threadIdx.x;
    const int w    = tid >> 5;
    const int lane = tid & 31;
    const int qt   = blockIdx.x;
    const int bh   = blockIdx.y;
    const int q0   = qt * 128;

    const __half* Qh = s_q_hi + (size_t)bh * SEQ * DHEAD;
    const __half* Ql = s_q_lo + (size_t)bh * SEQ * DHEAD;
    const __half* Kg = s_k    + (size_t)bh * SEQ * DHEAD;
    const __half* Vg = s_vt   + (size_t)bh * DHEAD * SEQ;

    auto load_kv = [&](int kt, int stg) {
        const uint32_t s0 = sb + AKV0 + stg * AKV_STG;
        const int kv0 = kt * 64;
#pragma unroll
        for (int i = 0; i < 4; ++i) {
            const int c = tid + i * 128;
            const int row = c >> 3, seg = c & 7;
            const uint32_t so = row * AROWB + seg * 16;
            const size_t gk = (size_t)(kv0 + row) * DHEAD + seg * 8;
            const size_t gv = (size_t)row * SEQ + kv0 + seg * 8;
            cp16(s0 + so, Kg + gk);
            cp16(s0 + AV_OFF + so, Vg + gv);
        }
    };

    // Q tile (128 rows x 64 fp16) hi/lo
#pragma unroll
    for (int i = 0; i < 8; ++i) {
        const int c = tid + i * 128;
        const int row = c >> 3, seg = c & 7;
        const uint32_t so = row * AROWB + seg * 16;
        const size_t go = (size_t)(q0 + row) * DHEAD + seg * 8;
        *(uint4*)(asmem + AQ_H + so) = *(const uint4*)(Qh + go);
        *(uint4*)(asmem + AQ_L + so) = *(const uint4*)(Ql + go);
    }

    const int ar = lane & 15, ahh = lane >> 4;
    const int grp = lane >> 3, l8 = lane & 7;
    const int row0 = lane >> 2, coll = (lane & 3) * 2;

    float m_run[4], l_run[4];
#pragma unroll
    for (int i = 0; i < 4; ++i) { m_run[i] = -1e30f; l_run[i] = 0.f; }
    float oacc[2][8][4];
#pragma unroll
    for (int mt = 0; mt < 2; ++mt)
#pragma unroll
        for (int nt = 0; nt < 8; ++nt)
#pragma unroll
            for (int e = 0; e < 4; ++e) oacc[mt][nt][e] = 0.f;

    const int ntiles = qt * 2 + 2;
    load_kv(0, 0);
    cp_commit();

    for (int kt = 0; kt < ntiles; ++kt) {
        if (kt + 1 < ntiles) {
            load_kv(kt + 1, (kt + 1) & 1);
            cp_commit();
            cp_wait<1>();
        } else {
            cp_wait<0>();
        }
        __syncthreads();

        const uint32_t kvb = sb + AKV0 + (kt & 1) * AKV_STG;
        const int kv0 = kt * 64;

        // ---- scores: S = Q K^T (Q split-2, K single) ----
        float s[2][8][4];
#pragma unroll
        for (int mt = 0; mt < 2; ++mt)
#pragma unroll
            for (int nt = 0; nt < 8; ++nt)
#pragma unroll
                for (int e = 0; e < 4; ++e) s[mt][nt][e] = 0.f;

#pragma unroll
        for (int ks = 0; ks < 4; ++ks) {
            uint32_t kb[4][4];
#pragma unroll
            for (int nb = 0; nb < 4; ++nb) {
                const uint32_t bo = (uint32_t)(((grp >> 1) * 8 + l8 + nb * 16) * AROWB +
                                               (grp & 1) * 16 + ks * 32);
                ldsm4(kvb + bo, kb[nb][0], kb[nb][1], kb[nb][2], kb[nb][3]);
            }
            uint32_t qh[2][4], ql[2][4];
#pragma unroll
            for (int mt = 0; mt < 2; ++mt) {
                const uint32_t ao = (uint32_t)((w * 32 + mt * 16 + ar) * AROWB +
                                               ahh * 16 + ks * 32);
                ldsm4(sb + AQ_H + ao, qh[mt][0], qh[mt][1], qh[mt][2], qh[mt][3]);
                ldsm4(sb + AQ_L + ao, ql[mt][0], ql[mt][1], ql[mt][2], ql[mt][3]);
            }
#pragma unroll
            for (int mt = 0; mt < 2; ++mt)
#pragma unroll
                for (int nt = 0; nt < 8; ++nt) {
                    const int nb = nt >> 1, p = nt & 1;
                    mma_f16(s[mt][nt][0], s[mt][nt][1], s[mt][nt][2], s[mt][nt][3],
                            qh[mt][0], qh[mt][1], qh[mt][2], qh[mt][3],
                            kb[nb][p * 2], kb[nb][p * 2 + 1]);
                }
#pragma unroll
            for (int mt = 0; mt < 2; ++mt)
#pragma unroll
                for (int nt = 0; nt < 8; ++nt) {
                    const int nb = nt >> 1, p = nt & 1;
                    mma_f16(s[mt][nt][0], s[mt][nt][1], s[mt][nt][2], s[mt][nt][3],
                            ql[mt][0], ql[mt][1], ql[mt][2], ql[mt][3],
                            kb[nb][p * 2], kb[nb][p * 2 + 1]);
                }
        }

        // ---- causal mask ----
        if (kt >= qt * 2) {
#pragma unroll
            for (int mt = 0; mt < 2; ++mt) {
                const int rbase = q0 + w * 32 + mt * 16 + row0;
#pragma unroll
                for (int nt = 0; nt < 8; ++nt) {
                    const int cb = kv0 + nt * 8 + coll;
                    if (cb > rbase)     s[mt][nt][0] = -10000.f;
                    if (cb + 1 > rbase) s[mt][nt][1] = -10000.f;
                    if (cb > rbase + 8)     s[mt][nt][2] = -10000.f;
                    if (cb + 1 > rbase + 8) s[mt][nt][3] = -10000.f;
                }
            }
        }

        // ---- online softmax ----
        float corr[4];
#pragma unroll
        for (int slot = 0; slot < 4; ++slot) {
            const int mt = slot >> 1, h2 = slot & 1;
            float tm = -1e30f;
#pragma unroll
            for (int nt = 0; nt < 8; ++nt)
                tm = fmaxf(tm, fmaxf(s[mt][nt][h2 * 2], s[mt][nt][h2 * 2 + 1]));
            tm = fmaxf(tm, __shfl_xor_sync(0xffffffffu, tm, 1));
            tm = fmaxf(tm, __shfl_xor_sync(0xffffffffu, tm, 2));
            const float mnew = fmaxf(m_run[slot], tm);
            corr[slot] = __expf(m_run[slot] - mnew);
            m_run[slot] = mnew;
            l_run[slot] *= corr[slot];
        }
#pragma unroll
        for (int mt = 0; mt < 2; ++mt)
#pragma unroll
            for (int nt = 0; nt < 8; ++nt) {
                oacc[mt][nt][0] *= corr[mt * 2];
                oacc[mt][nt][1] *= corr[mt * 2];
                oacc[mt][nt][2] *= corr[mt * 2 + 1];
                oacc[mt][nt][3] *= corr[mt * 2 + 1];
            }

        // ---- P = exp(S - m), single fp16 pack ----
        uint32_t pf[2][8][2];
#pragma unroll
        for (int mt = 0; mt < 2; ++mt)
#pragma unroll
            for (int nt = 0; nt < 8; ++nt) {
                const float p0 = __expf(s[mt][nt][0] - m_run[mt * 2]);
                const float p1 = __expf(s[mt][nt][1] - m_run[mt * 2]);
                const float p2 = __expf(s[mt][nt][2] - m_run[mt * 2 + 1]);
                const float p3 = __expf(s[mt][nt][3] - m_run[mt * 2 + 1]);
                l_run[mt * 2]     += p0 + p1;
                l_run[mt * 2 + 1] += p2 + p3;
                pf[mt][nt][0] = packh_f(p0, p1);
                pf[mt][nt][1] = packh_f(p2, p3);
            }

        // ---- O += P V (single product) ----
#pragma unroll
        for (int ks = 0; ks < 4; ++ks) {
            uint32_t vb[4][4];
#pragma unroll
            for (int nb = 0; nb < 4; ++nb) {
                const uint32_t bo = (uint32_t)(((grp >> 1) * 8 + l8 + nb * 16) * AROWB +
                                               (grp & 1) * 16 + ks * 32);
                ldsm4(kvb + AV_OFF + bo, vb[nb][0], vb[nb][1], vb[nb][2], vb[nb][3]);
            }
#pragma unroll
            for (int mt = 0; mt < 2; ++mt)
#pragma unroll
                for (int nt = 0; nt < 8; ++nt) {
                    const int nb = nt >> 1, p = nt & 1;
                    mma_f16(oacc[mt][nt][0], oacc[mt][nt][1], oacc[mt][nt][2], oacc[mt][nt][3],
                            pf[mt][ks * 2][0], pf[mt][ks * 2][1],
                            pf[mt][ks * 2 + 1][0], pf[mt][ks * 2 + 1][1],
                            vb[nb][p * 2], vb[nb][p * 2 + 1]);
                }
        }
        __syncthreads();
    }

    // ---- finalize: divide by row sums, write SINGLE fp16 proj A operand ----
    float inv[4];
#pragma unroll
    for (int slot = 0; slot < 4; ++slot) {
        float lt = l_run[slot];
        lt += __shfl_xor_sync(0xffffffffu, lt, 1);
        lt += __shfl_xor_sync(0xffffffffu, lt, 2);
        inv[slot] = 1.f / lt;
    }
    const int b = bh >> 4, h = bh & 15;
#pragma unroll
    for (int mt = 0; mt < 2; ++mt) {
#pragma unroll
        for (int half = 0; half < 2; ++half) {
            const size_t orow = (size_t)b * SEQ + q0 + w * 32 + mt * 16 + row0 + half * 8;
            const float iv = inv[mt * 2 + half];
#pragma unroll
            for (int nt = 0; nt < 8; ++nt) {
                const int col = h * DHEAD + nt * 8 + coll;
                const float v0 = oacc[mt][nt][half * 2 + 0] * iv;
                const float v1 = oacc[mt][nt][half * 2 + 1] * iv;
                *(uint32_t*)(s_a_hi + orow * DIM + col) = packh_f(v0, v1);
            }
        }
    }
}

// ---------------------------------------------------------------------------
extern "C" void kernel_launch(void* const* d_in, const int* in_sizes, int n_in,
                              void* d_out, int out_size)
{
    const float* x      = (const float*)d_in[0];
    const float* w_attn = (const float*)d_in[1];
    const float* b_attn = (const float*)d_in[2];
    const float* w_proj = (const float*)d_in[3];
    const float* b_proj = (const float*)d_in[4];
    float* out = (float*)d_out;

    __half *xa_hi, *xa_lo, *wq, *wp;
    cudaGetSymbolAddress((void**)&xa_hi, s_a_hi);
    cudaGetSymbolAddress((void**)&xa_lo, s_a_lo);
    cudaGetSymbolAddress((void**)&wq, s_wq);
    cudaGetSymbolAddress((void**)&wp, s_wp);

    cudaFuncSetAttribute(tc_gemm_kernel<0, 0>,
                         cudaFuncAttributeMaxDynamicSharedMemorySize, GSM_BYTES);
    cudaFuncSetAttribute(tc_gemm_kernel<0, 1>,
                         cudaFuncAttributeMaxDynamicSharedMemorySize, GSM_BYTES);
    cudaFuncSetAttribute(attn_tc_kernel,
                         cudaFuncAttributeMaxDynamicSharedMemorySize, ASM_BYTES);

    // 1) convert x -> single fp16 (A operand of QKV GEMM)
    convert_half_kernel<<<(MROWS * KTOT / 4 + 255) / 256, 256>>>(x, xa_hi, MROWS * KTOT / 4);
    // 2) transpose weights -> single fp16
    transp_half_kernel<<<dim3(NQKV / 32, KTOT / 32), dim3(32, 8)>>>(w_attn, KTOT, NQKV, wq);
    transp_half_kernel<<<dim3(DIM / 32, KTOT / 32), dim3(32, 8)>>>(w_proj, KTOT, DIM, wp);
    // 3) QKV GEMM (A single fp16) -> q split-2, k single, vt single
    tc_gemm_kernel<0, 0><<<dim3(NQKV / BN, MROWS / BM), 256, GSM_BYTES>>>(
        xa_hi, xa_lo, wq, b_attn, nullptr);
    // 4) tensor-core flash attention -> writes s_a_hi (single fp16)
    attn_tc_kernel<<<dim3(SEQ / 128, BATCH * NHEAD), 128, ASM_BYTES>>>();
    // 5) output projection (A single fp16)
    tc_gemm_kernel<0, 1><<<dim3(DIM / BN, MROWS / BM), 256, GSM_BYTES>>>(
        xa_hi, xa_lo, wp, b_proj, out);
}

// round 13
// speedup vs baseline: 2.4767x; 1.0924x over previous
#include <cuda_runtime.h>
#include <cuda_fp16.h>
#include <cstdint>

// Problem shape (fixed by the dataset)
#define BATCH 2
#define SEQ   2048
#define DIM   1024
#define NHEAD 16
#define DHEAD 64
#define MROWS (BATCH * SEQ)          // 4096
#define NQKV  (3 * DIM)              // 3072
#define KTOT  1024

// ---------------------------------------------------------------------------
// Scratch (allocation-free rule: __device__ globals), all single fp16 now
// ---------------------------------------------------------------------------
__device__ __half s_a[MROWS * KTOT];      // GEMM A: x, then attention out
__device__ __half s_wq[NQKV * KTOT];      // w_attn^T [3072,1024]
__device__ __half s_wp[DIM * KTOT];       // w_proj^T [1024,1024]
// attention operands, written by QKV epilogue
__device__ __half s_q [BATCH * NHEAD * SEQ * DHEAD];    // [bh,s,dh], q*0.125
__device__ __half s_k [BATCH * NHEAD * SEQ * DHEAD];    // [bh,s,dh]
__device__ __half s_vt[BATCH * NHEAD * DHEAD * SEQ];    // [bh,dh,s]

// ---------------------------------------------------------------------------
// PTX helpers (baseline ISA — compiles for sm_103)
// ---------------------------------------------------------------------------
__device__ __forceinline__ uint32_t smem_u32(const void* p) {
    uint32_t a;
    asm("{ .reg .u64 t; cvta.to.shared.u64 t, %1; cvt.u32.u64 %0, t; }"
        : "=r"(a) : "l"(p));
    return a;
}
__device__ __forceinline__ void ldsm4(uint32_t addr, uint32_t& r0, uint32_t& r1,
                                      uint32_t& r2, uint32_t& r3) {
    asm volatile("ldmatrix.sync.aligned.m8n8.x4.shared.b16 {%0,%1,%2,%3}, [%4];"
                 : "=r"(r0), "=r"(r1), "=r"(r2), "=r"(r3) : "r"(addr));
}
__device__ __forceinline__ void mma_f16(float& c0, float& c1, float& c2, float& c3,
                                        uint32_t a0, uint32_t a1, uint32_t a2, uint32_t a3,
                                        uint32_t b0, uint32_t b1) {
    asm volatile("mma.sync.aligned.m16n8k16.row.col.f32.f16.f16.f32 "
                 "{%0,%1,%2,%3}, {%4,%5,%6,%7}, {%8,%9}, {%0,%1,%2,%3};"
                 : "+f"(c0), "+f"(c1), "+f"(c2), "+f"(c3)
                 : "r"(a0), "r"(a1), "r"(a2), "r"(a3), "r"(b0), "r"(b1));
}
__device__ __forceinline__ void cp16(uint32_t saddr, const void* g) {
    asm volatile("cp.async.cg.shared.global [%0], [%1], 16;"
                 :: "r"(saddr), "l"(g) : "memory");
}
__device__ __forceinline__ void cp_commit() {
    asm volatile("cp.async.commit_group;" ::: "memory");
}
template <int N>
__device__ __forceinline__ void cp_wait() {
    asm volatile("cp.async.wait_group %0;" :: "n"(N) : "memory");
}
__device__ __forceinline__ uint32_t packh_f(float a, float b) {
    __half2 p = __floats2half2_rn(a, b);
    return *(uint32_t*)&p;
}

// ---------------------------------------------------------------------------
// Prep kernels
// ---------------------------------------------------------------------------
__global__ __launch_bounds__(256) void convert_half_kernel(
    const float* __restrict__ src, __half* __restrict__ dst, int n4)
{
    int i = blockIdx.x * 256 + threadIdx.x;
    if (i >= n4) return;
    float4 v = ((const float4*)src)[i];
    uint2 u = make_uint2(packh_f(v.x, v.y), packh_f(v.z, v.w));
    *(uint2*)(dst + (size_t)i * 4) = u;
}

__global__ __launch_bounds__(256) void transp_half_kernel(
    const float* __restrict__ w, int K, int N, __half* __restrict__ outp)
{
    __shared__ float t[32][33];
    const int tx = threadIdx.x, ty = threadIdx.y;
    const int n0 = blockIdx.x * 32, k0 = blockIdx.y * 32;
#pragma unroll
    for (int i = 0; i < 4; ++i)
        t[ty + i * 8][tx] = w[(size_t)(k0 + ty + i * 8) * N + n0 + tx];
    __syncthreads();
#pragma unroll
    for (int i = 0; i < 4; ++i) {
        const int n = n0 + ty + i * 8;
        outp[(size_t)n * K + k0 + tx] = __float2half_rn(t[tx][ty + i * 8]);
    }
}

// ---------------------------------------------------------------------------
// HMMA GEMM, fp16 single x single, 3-stage cp.async, 1 barrier/iter, 2 CTA/SM.
// D[M,N] = A @ B^T + bias.
// MODE 0: QKV epilogue -> q/k single [bh,s,dh], vt single [bh,dh,s]
// MODE 1: plain fp32 out
// ---------------------------------------------------------------------------
#define BM 128
#define BN 128
#define BK 32
#define ROWB 80
#define NKT (KTOT / BK)          // 32
#define OFF_B   10240
#define STG_BYTES 20480
#define NSTAGE 3
#define GSM_BYTES (NSTAGE * STG_BYTES)   // 61440/CTA

template <int MODE>
__global__ __launch_bounds__(256, 2) void tc_gemm_kernel(
    const __half* __restrict__ A, const __half* __restrict__ B,
    const float* __restrict__ bias, float* __restrict__ outp)
{
    extern __shared__ char gsm[];
    const uint32_t sb = smem_u32(gsm);

    const int tid  = threadIdx.x;
    const int w    = tid >> 5;
    const int lane = tid & 31;
    const int m0 = blockIdx.y * BM;
    const int n0 = blockIdx.x * BN;
    const int wm = (w >> 2) * 64;
    const int wn = (w & 3) * 32;

    const int srow = tid >> 2;
    const int sseg = tid & 3;
    const size_t gA = (size_t)(m0 + srow) * KTOT + sseg * 8;
    const size_t gB = (size_t)(n0 + srow) * KTOT + sseg * 8;
    const size_t rstep = (size_t)64 * KTOT;
    const uint32_t soff0 = (uint32_t)(srow * ROWB + sseg * 16);
    const uint32_t soff1 = soff0 + 64 * ROWB;

    auto load_stage = [&](int kt, int stg) {
        const uint32_t s0 = sb + stg * STG_BYTES;
        const __half* pa = A + gA + (size_t)kt * BK;
        const __half* pb = B + gB + (size_t)kt * BK;
        cp16(s0 + soff0, pa);           cp16(s0 + soff1, pa + rstep);
        cp16(s0 + OFF_B + soff0, pb);   cp16(s0 + OFF_B + soff1, pb + rstep);
    };

    float acc[4][4][4];
#pragma unroll
    for (int i = 0; i < 4; ++i)
#pragma unroll
        for (int j = 0; j < 4; ++j)
#pragma unroll
            for (int e = 0; e < 4; ++e) acc[i][j][e] = 0.f;

    const int ar = lane & 15, ah = lane >> 4;
    const uint32_t aoffb = (uint32_t)((wm + ar) * ROWB + ah * 16);
    const int grp = lane >> 3, l8 = lane & 7;
    const uint32_t boffb = (uint32_t)((wn + ((grp >> 1) << 3) + l8) * ROWB + (grp & 1) * 16);

    load_stage(0, 0);
    cp_commit();
    load_stage(1, 1);
    cp_commit();

    int stg = 0;
    for (int kt = 0; kt < NKT; ++kt) {
        if (kt + 1 < NKT) cp_wait<1>(); else cp_wait<0>();
        __syncthreads();

        if (kt + 2 < NKT) {
            int s2 = stg + 2; if (s2 >= NSTAGE) s2 -= NSTAGE;
            load_stage(kt + 2, s2);
            cp_commit();
        }

        const uint32_t s0 = sb + stg * STG_BYTES;
#pragma unroll
        for (int ks = 0; ks < 2; ++ks) {
            const uint32_t akoff = s0 + aoffb + ks * 32;
            const uint32_t bkoff = s0 + OFF_B + boffb + ks * 32;

            uint32_t fa[4][4];
#pragma unroll
            for (int mt = 0; mt < 4; ++mt)
                ldsm4(akoff + mt * 16 * ROWB,
                      fa[mt][0], fa[mt][1], fa[mt][2], fa[mt][3]);
            uint32_t fb[8];
            ldsm4(bkoff,             fb[0], fb[1], fb[2], fb[3]);
            ldsm4(bkoff + 16 * ROWB, fb[4], fb[5], fb[6], fb[7]);

#pragma unroll
            for (int mt = 0; mt < 4; ++mt)
#pragma unroll
                for (int nt = 0; nt < 4; ++nt)
                    mma_f16(acc[mt][nt][0], acc[mt][nt][1], acc[mt][nt][2], acc[mt][nt][3],
                            fa[mt][0], fa[mt][1], fa[mt][2], fa[mt][3],
                            fb[nt * 2], fb[nt * 2 + 1]);
        }
        if (++stg >= NSTAGE) stg = 0;
    }

    // epilogue
    const int erow = (lane >> 2);
    const int ecol = (lane & 3) * 2;
#pragma unroll
    for (int mt = 0; mt < 4; ++mt) {
#pragma unroll
        for (int nt = 0; nt < 4; ++nt) {
#pragma unroll
            for (int half = 0; half < 2; ++half) {
                const int row = m0 + wm + mt * 16 + erow + half * 8;
                const int col = n0 + wn + nt * 8 + ecol;
                float v0 = acc[mt][nt][half * 2 + 0] + bias[col];
                float v1 = acc[mt][nt][half * 2 + 1] + bias[col + 1];
                if (MODE == 0) {
                    const int bb = row >> 11, s = row & 2047;
                    const int part = col >> 10;
                    const int dd = col & 1023;
                    const int h = dd >> 6, hd = dd & 63;
                    const int bh = (bb << 4) + h;
                    if (part == 2) {
                        const size_t base = ((size_t)bh * DHEAD + hd) * SEQ + s;
                        s_vt[base]       = __float2half_rn(v0);
                        s_vt[base + SEQ] = __float2half_rn(v1);
                    } else {
                        if (part == 0) { v0 *= 0.125f; v1 *= 0.125f; }
                        const size_t base = ((size_t)bh * SEQ + s) * DHEAD + hd;
                        __half* dst = (part == 0) ? s_q : s_k;
                        *(uint32_t*)(dst + base) = packh_f(v0, v1);
                    }
                } else {
                    *(float2*)(outp + (size_t)row * DIM + col) = make_float2(v0, v1);
                }
            }
        }
    }
}

// ---------------------------------------------------------------------------
// Tensor-core flash attention, all-single fp16 operands, fp32 softmax.
// cp.async 2-stage KV, 3 CTAs/SM. CTA: 128 q rows x one (b,h); 4 warps.
// Heaviest query tiles scheduled FIRST (reversed qt) for tail balance.
// ---------------------------------------------------------------------------
#define AROWB 144
#define AQ 0
#define AKV0 18432
#define AKV_STG 18432          // K (9216) + VT (9216)
#define AV_OFF 9216
#define ASM_BYTES (AKV0 + 2 * AKV_STG)   // 55296; x3 CTAs = 166KB/SM

__global__ __launch_bounds__(128, 3) void attn_tc_kernel()
{
    extern __shared__ char asmem[];
    const uint32_t sb = smem_u32(asmem);
    const int tid  = threadIdx.x;
    const int w    = tid >> 5;
    const int lane = tid & 31;
    const int qt   = (int)(gridDim.x - 1) - (int)blockIdx.x;  // heavy tiles first
    const int bh   = blockIdx.y;
    const int q0   = qt * 128;

    const __half* Qg = s_q  + (size_t)bh * SEQ * DHEAD;
    const __half* Kg = s_k  + (size_t)bh * SEQ * DHEAD;
    const __half* Vg = s_vt + (size_t)bh * DHEAD * SEQ;

    auto load_kv = [&](int kt, int stg) {
        const uint32_t s0 = sb + AKV0 + stg * AKV_STG;
        const int kv0 = kt * 64;
#pragma unroll
        for (int i = 0; i < 4; ++i) {
            const int c = tid + i * 128;
            const int row = c >> 3, seg = c & 7;
            const uint32_t so = row * AROWB + seg * 16;
            const size_t gk = (size_t)(kv0 + row) * DHEAD + seg * 8;
            const size_t gv = (size_t)row * SEQ + kv0 + seg * 8;
            cp16(s0 + so, Kg + gk);
            cp16(s0 + AV_OFF + so, Vg + gv);
        }
    };

    // Q tile (128 rows x 64 fp16)
#pragma unroll
    for (int i = 0; i < 8; ++i) {
        const int c = tid + i * 128;
        const int row = c >> 3, seg = c & 7;
        const uint32_t so = row * AROWB + seg * 16;
        const size_t go = (size_t)(q0 + row) * DHEAD + seg * 8;
        *(uint4*)(asmem + AQ + so) = *(const uint4*)(Qg + go);
    }

    const int ar = lane & 15, ahh = lane >> 4;
    const int grp = lane >> 3, l8 = lane & 7;
    const int row0 = lane >> 2, coll = (lane & 3) * 2;

    float m_run[4], l_run[4];
#pragma unroll
    for (int i = 0; i < 4; ++i) { m_run[i] = -1e30f; l_run[i] = 0.f; }
    float oacc[2][8][4];
#pragma unroll
    for (int mt = 0; mt < 2; ++mt)
#pragma unroll
        for (int nt = 0; nt < 8; ++nt)
#pragma unroll
            for (int e = 0; e < 4; ++e) oacc[mt][nt][e] = 0.f;

    const int ntiles = qt * 2 + 2;
    load_kv(0, 0);
    cp_commit();

    for (int kt = 0; kt < ntiles; ++kt) {
        if (kt + 1 < ntiles) {
            load_kv(kt + 1, (kt + 1) & 1);
            cp_commit();
            cp_wait<1>();
        } else {
            cp_wait<0>();
        }
        __syncthreads();

        const uint32_t kvb = sb + AKV0 + (kt & 1) * AKV_STG;
        const int kv0 = kt * 64;

        // ---- scores: S = Q K^T (single x single) ----
        float s[2][8][4];
#pragma unroll
        for (int mt = 0; mt < 2; ++mt)
#pragma unroll
            for (int nt = 0; nt < 8; ++nt)
#pragma unroll
                for (int e = 0; e < 4; ++e) s[mt][nt][e] = 0.f;

#pragma unroll
        for (int ks = 0; ks < 4; ++ks) {
            uint32_t kb[4][4];
#pragma unroll
            for (int nb = 0; nb < 4; ++nb) {
                const uint32_t bo = (uint32_t)(((grp >> 1) * 8 + l8 + nb * 16) * AROWB +
                                               (grp & 1) * 16 + ks * 32);
                ldsm4(kvb + bo, kb[nb][0], kb[nb][1], kb[nb][2], kb[nb][3]);
            }
            uint32_t qf[2][4];
#pragma unroll
            for (int mt = 0; mt < 2; ++mt) {
                const uint32_t ao = (uint32_t)((w * 32 + mt * 16 + ar) * AROWB +
                                               ahh * 16 + ks * 32);
                ldsm4(sb + AQ + ao, qf[mt][0], qf[mt][1], qf[mt][2], qf[mt][3]);
            }
#pragma unroll
            for (int mt = 0; mt < 2; ++mt)
#pragma unroll
                for (int nt = 0; nt < 8; ++nt) {
                    const int nb = nt >> 1, p = nt & 1;
                    mma_f16(s[mt][nt][0], s[mt][nt][1], s[mt][nt][2], s[mt][nt][3],
                            qf[mt][0], qf[mt][1], qf[mt][2], qf[mt][3],
                            kb[nb][p * 2], kb[nb][p * 2 + 1]);
                }
        }

        // ---- causal mask (last two tiles only) ----
        if (kt >= qt * 2) {
#pragma unroll
            for (int mt = 0; mt < 2; ++mt) {
                const int rbase = q0 + w * 32 + mt * 16 + row0;
#pragma unroll
                for (int nt = 0; nt < 8; ++nt) {
                    const int cb = kv0 + nt * 8 + coll;
                    if (cb > rbase)     s[mt][nt][0] = -10000.f;
                    if (cb + 1 > rbase) s[mt][nt][1] = -10000.f;
                    if (cb > rbase + 8)     s[mt][nt][2] = -10000.f;
                    if (cb + 1 > rbase + 8) s[mt][nt][3] = -10000.f;
                }
            }
        }

        // ---- online softmax ----
        float corr[4];
#pragma unroll
        for (int slot = 0; slot < 4; ++slot) {
            const int mt = slot >> 1, h2 = slot & 1;
            float tm = -1e30f;
#pragma unroll
            for (int nt = 0; nt < 8; ++nt)
                tm = fmaxf(tm, fmaxf(s[mt][nt][h2 * 2], s[mt][nt][h2 * 2 + 1]));
            tm = fmaxf(tm, __shfl_xor_sync(0xffffffffu, tm, 1));
            tm = fmaxf(tm, __shfl_xor_sync(0xffffffffu, tm, 2));
            const float mnew = fmaxf(m_run[slot], tm);
            corr[slot] = __expf(m_run[slot] - mnew);
            m_run[slot] = mnew;
            l_run[slot] *= corr[slot];
        }
#pragma unroll
        for (int mt = 0; mt < 2; ++mt)
#pragma unroll
            for (int nt = 0; nt < 8; ++nt) {
                oacc[mt][nt][0] *= corr[mt * 2];
                oacc[mt][nt][1] *= corr[mt * 2];
                oacc[mt][nt][2] *= corr[mt * 2 + 1];
                oacc[mt][nt][3] *= corr[mt * 2 + 1];
            }

        // ---- P = exp(S - m), fp16 pack ----
        uint32_t pf[2][8][2];
#pragma unroll
        for (int mt = 0; mt < 2; ++mt)
#pragma unroll
            for (int nt = 0; nt < 8; ++nt) {
                const float p0 = __expf(s[mt][nt][0] - m_run[mt * 2]);
                const float p1 = __expf(s[mt][nt][1] - m_run[mt * 2]);
                const float p2 = __expf(s[mt][nt][2] - m_run[mt * 2 + 1]);
                const float p3 = __expf(s[mt][nt][3] - m_run[mt * 2 + 1]);
                l_run[mt * 2]     += p0 + p1;
                l_run[mt * 2 + 1] += p2 + p3;
                pf[mt][nt][0] = packh_f(p0, p1);
                pf[mt][nt][1] = packh_f(p2, p3);
            }

        // ---- O += P V ----
#pragma unroll
        for (int ks = 0; ks < 4; ++ks) {
            uint32_t vb[4][4];
#pragma unroll
            for (int nb = 0; nb < 4; ++nb) {
                const uint32_t bo = (uint32_t)(((grp >> 1) * 8 + l8 + nb * 16) * AROWB +
                                               (grp & 1) * 16 + ks * 32);
                ldsm4(kvb + AV_OFF + bo, vb[nb][0], vb[nb][1], vb[nb][2], vb[nb][3]);
            }
#pragma unroll
            for (int mt = 0; mt < 2; ++mt)
#pragma unroll
                for (int nt = 0; nt < 8; ++nt) {
                    const int nb = nt >> 1, p = nt & 1;
                    mma_f16(oacc[mt][nt][0], oacc[mt][nt][1], oacc[mt][nt][2], oacc[mt][nt][3],
                            pf[mt][ks * 2][0], pf[mt][ks * 2][1],
                            pf[mt][ks * 2 + 1][0], pf[mt][ks * 2 + 1][1],
                            vb[nb][p * 2], vb[nb][p * 2 + 1]);
                }
        }
        __syncthreads();
    }

    // ---- finalize: divide by row sums, write single-fp16 proj A operand ----
    float inv[4];
#pragma unroll
    for (int slot = 0; slot < 4; ++slot) {
        float lt = l_run[slot];
        lt += __shfl_xor_sync(0xffffffffu, lt, 1);
        lt += __shfl_xor_sync(0xffffffffu, lt, 2);
        inv[slot] = 1.f / lt;
    }
    const int b = bh >> 4, h = bh & 15;
#pragma unroll
    for (int mt = 0; mt < 2; ++mt) {
#pragma unroll
        for (int half = 0; half < 2; ++half) {
            const size_t orow = (size_t)b * SEQ + q0 + w * 32 + mt * 16 + row0 + half * 8;
            const float iv = inv[mt * 2 + half];
#pragma unroll
            for (int nt = 0; nt < 8; ++nt) {
                const int col = h * DHEAD + nt * 8 + coll;
                const float v0 = oacc[mt][nt][half * 2 + 0] * iv;
                const float v1 = oacc[mt][nt][half * 2 + 1] * iv;
                *(uint32_t*)(s_a + orow * DIM + col) = packh_f(v0, v1);
            }
        }
    }
}

// ---------------------------------------------------------------------------
extern "C" void kernel_launch(void* const* d_in, const int* in_sizes, int n_in,
                              void* d_out, int out_size)
{
    const float* x      = (const float*)d_in[0];
    const float* w_attn = (const float*)d_in[1];
    const float* b_attn = (const float*)d_in[2];
    const float* w_proj = (const float*)d_in[3];
    const float* b_proj = (const float*)d_in[4];
    float* out = (float*)d_out;

    __half *xa, *wq, *wp;
    cudaGetSymbolAddress((void**)&xa, s_a);
    cudaGetSymbolAddress((void**)&wq, s_wq);
    cudaGetSymbolAddress((void**)&wp, s_wp);

    cudaFuncSetAttribute(tc_gemm_kernel<0>,
                         cudaFuncAttributeMaxDynamicSharedMemorySize, GSM_BYTES);
    cudaFuncSetAttribute(tc_gemm_kernel<1>,
                         cudaFuncAttributeMaxDynamicSharedMemorySize, GSM_BYTES);
    cudaFuncSetAttribute(attn_tc_kernel,
                         cudaFuncAttributeMaxDynamicSharedMemorySize, ASM_BYTES);

    // 1) convert x -> fp16 (A operand of QKV GEMM)
    convert_half_kernel<<<(MROWS * KTOT / 4 + 255) / 256, 256>>>(x, xa, MROWS * KTOT / 4);
    // 2) transpose weights -> fp16
    transp_half_kernel<<<dim3(NQKV / 32, KTOT / 32), dim3(32, 8)>>>(w_attn, KTOT, NQKV, wq);
    transp_half_kernel<<<dim3(DIM / 32, KTOT / 32), dim3(32, 8)>>>(w_proj, KTOT, DIM, wp);
    // 3) QKV GEMM -> q/k/vt single fp16
    tc_gemm_kernel<0><<<dim3(NQKV / BN, MROWS / BM), 256, GSM_BYTES>>>(
        xa, wq, b_attn, nullptr);
    // 4) tensor-core flash attention -> writes s_a (single fp16)
    attn_tc_kernel<<<dim3(SEQ / 128, BATCH * NHEAD), 128, ASM_BYTES>>>();
    // 5) output projection
    tc_gemm_kernel<1><<<dim3(DIM / BN, MROWS / BM), 256, GSM_BYTES>>>(
        xa, wp, b_proj, out);
}

// round 14
// speedup vs baseline: 2.6479x; 1.0691x over previous
#include <cuda_runtime.h>
#include <cuda_fp16.h>
#include <cstdint>

// Problem shape (fixed by the dataset)
#define BATCH 2
#define SEQ   2048
#define DIM   1024
#define NHEAD 16
#define DHEAD 64
#define MROWS (BATCH * SEQ)          // 4096
#define NQKV  (3 * DIM)              // 3072
#define KTOT  1024

// ---------------------------------------------------------------------------
// Scratch (allocation-free rule: __device__ globals), all single fp16
// ---------------------------------------------------------------------------
__device__ __half s_a[MROWS * KTOT];      // GEMM A: x, then attention out
__device__ __half s_wq[KTOT * NQKV];      // w_attn [1024,3072] natural layout
__device__ __half s_wp[KTOT * DIM];       // w_proj [1024,1024] natural layout
// attention operands, written by QKV epilogue
__device__ __half s_q [BATCH * NHEAD * SEQ * DHEAD];    // [bh,s,dh], q*0.125
__device__ __half s_k [BATCH * NHEAD * SEQ * DHEAD];    // [bh,s,dh]
__device__ __half s_vt[BATCH * NHEAD * DHEAD * SEQ];    // [bh,dh,s]

// ---------------------------------------------------------------------------
// PTX helpers (baseline ISA — compiles for sm_103)
// ---------------------------------------------------------------------------
__device__ __forceinline__ uint32_t smem_u32(const void* p) {
    uint32_t a;
    asm("{ .reg .u64 t; cvta.to.shared.u64 t, %1; cvt.u32.u64 %0, t; }"
        : "=r"(a) : "l"(p));
    return a;
}
__device__ __forceinline__ void ldsm4(uint32_t addr, uint32_t& r0, uint32_t& r1,
                                      uint32_t& r2, uint32_t& r3) {
    asm volatile("ldmatrix.sync.aligned.m8n8.x4.shared.b16 {%0,%1,%2,%3}, [%4];"
                 : "=r"(r0), "=r"(r1), "=r"(r2), "=r"(r3) : "r"(addr));
}
__device__ __forceinline__ void ldsm4t(uint32_t addr, uint32_t& r0, uint32_t& r1,
                                       uint32_t& r2, uint32_t& r3) {
    asm volatile("ldmatrix.sync.aligned.m8n8.x4.trans.shared.b16 {%0,%1,%2,%3}, [%4];"
                 : "=r"(r0), "=r"(r1), "=r"(r2), "=r"(r3) : "r"(addr));
}
__device__ __forceinline__ void mma_f16(float& c0, float& c1, float& c2, float& c3,
                                        uint32_t a0, uint32_t a1, uint32_t a2, uint32_t a3,
                                        uint32_t b0, uint32_t b1) {
    asm volatile("mma.sync.aligned.m16n8k16.row.col.f32.f16.f16.f32 "
                 "{%0,%1,%2,%3}, {%4,%5,%6,%7}, {%8,%9}, {%0,%1,%2,%3};"
                 : "+f"(c0), "+f"(c1), "+f"(c2), "+f"(c3)
                 : "r"(a0), "r"(a1), "r"(a2), "r"(a3), "r"(b0), "r"(b1));
}
__device__ __forceinline__ void cp16(uint32_t saddr, const void* g) {
    asm volatile("cp.async.cg.shared.global [%0], [%1], 16;"
                 :: "r"(saddr), "l"(g) : "memory");
}
__device__ __forceinline__ void cp_commit() {
    asm volatile("cp.async.commit_group;" ::: "memory");
}
template <int N>
__device__ __forceinline__ void cp_wait() {
    asm volatile("cp.async.wait_group %0;" :: "n"(N) : "memory");
}
__device__ __forceinline__ uint32_t packh_f(float a, float b) {
    __half2 p = __floats2half2_rn(a, b);
    return *(uint32_t*)&p;
}

// ---------------------------------------------------------------------------
// Fused prep: convert x, w_attn, w_proj fp32 -> fp16 (elementwise, one kernel)
// ---------------------------------------------------------------------------
#define XN4  (MROWS * KTOT / 4)      // 1048576
#define WAN4 (KTOT * NQKV / 4)       // 786432
#define WPN4 (KTOT * DIM / 4)        // 262144

__global__ __launch_bounds__(256) void convert_all_kernel(
    const float* __restrict__ x, const float* __restrict__ wa,
    const float* __restrict__ wpr, __half* __restrict__ dx,
    __half* __restrict__ dwa, __half* __restrict__ dwp)
{
    int i = blockIdx.x * 256 + threadIdx.x;
    const float* src;
    __half* dst;
    if (i < XN4) {
        src = x; dst = dx;
    } else if (i < XN4 + WAN4) {
        i -= XN4; src = wa; dst = dwa;
    } else {
        i -= XN4 + WAN4;
        if (i >= WPN4) return;
        src = wpr; dst = dwp;
    }
    float4 v = ((const float4*)src)[i];
    uint2 u = make_uint2(packh_f(v.x, v.y), packh_f(v.z, v.w));
    *(uint2*)(dst + (size_t)i * 4) = u;
}

// ---------------------------------------------------------------------------
// HMMA GEMM, fp16, B in natural [K,N] layout via ldmatrix.trans.
// 3-stage cp.async, 1 barrier/iter, 2 CTAs/SM. D[M,N] = A @ B + bias.
// MODE 0: QKV epilogue -> q/k single [bh,s,dh], vt single [bh,dh,s]
// MODE 1: plain fp32 out
// ---------------------------------------------------------------------------
#define BM 128
#define BN 128
#define BK 32
#define ROWB  80                 // A tile row pitch (64B data + 16B pad)
#define ROWBB 272                // B tile row pitch (256B data + 16B pad)
#define NKT (KTOT / BK)          // 32
#define OFF_B   10240            // A tile = 128*80
#define STG_BYTES (10240 + 32 * ROWBB)   // 18944
#define NSTAGE 3
#define GSM_BYTES (NSTAGE * STG_BYTES)   // 56832/CTA; x2 CTAs = 111KB/SM

template <int MODE, int NB>
__global__ __launch_bounds__(256, 2) void tc_gemm_kernel(
    const __half* __restrict__ A, const __half* __restrict__ B,
    const float* __restrict__ bias, float* __restrict__ outp)
{
    extern __shared__ char gsm[];
    const uint32_t sb = smem_u32(gsm);

    const int tid  = threadIdx.x;
    const int w    = tid >> 5;
    const int lane = tid & 31;
    const int m0 = blockIdx.y * BM;
    const int n0 = blockIdx.x * BN;
    const int wm = (w >> 2) * 64;
    const int wn = (w & 3) * 32;

    // A staging: thread covers rows (t>>2, t>>2+64), one 16B seg each
    const int srow = tid >> 2;
    const int sseg = tid & 3;
    const size_t gA = (size_t)(m0 + srow) * KTOT + sseg * 8;
    const size_t rstepA = (size_t)64 * KTOT;
    const uint32_t aoff0 = (uint32_t)(srow * ROWB + sseg * 16);
    const uint32_t aoff1 = aoff0 + 64 * ROWB;
    // B staging: [BK=32 k-rows][BN=128 n]; thread covers k-rows (t>>4, +16), 16B seg
    const int bkr  = tid >> 4;           // 0..15
    const int bseg = tid & 15;           // 0..15
    const size_t gB = (size_t)bkr * NB + n0 + bseg * 8;
    const size_t rstepB = (size_t)16 * NB;
    const uint32_t boff0 = (uint32_t)(bkr * ROWBB + bseg * 16);
    const uint32_t boff1 = boff0 + 16 * ROWBB;

    auto load_stage = [&](int kt, int stg) {
        const uint32_t s0 = sb + stg * STG_BYTES;
        const __half* pa = A + gA + (size_t)kt * BK;
        const __half* pb = B + gB + (size_t)kt * BK * NB;
        cp16(s0 + aoff0, pa);            cp16(s0 + aoff1, pa + rstepA);
        cp16(s0 + OFF_B + boff0, pb);    cp16(s0 + OFF_B + boff1, pb + rstepB);
    };

    float acc[4][4][4];
#pragma unroll
    for (int i = 0; i < 4; ++i)
#pragma unroll
        for (int j = 0; j < 4; ++j)
#pragma unroll
            for (int e = 0; e < 4; ++e) acc[i][j][e] = 0.f;

    const int ar = lane & 15, ah = lane >> 4;
    const uint32_t aoffb = (uint32_t)((wm + ar) * ROWB + ah * 16);
    // trans-ldsm B address: k-row = (l&7) + ((l>>3)&1)*8 ; n-col = wn + ((l>>4)&1)*8
    const uint32_t boffb = (uint32_t)((((lane & 7) + ((lane >> 3) & 1) * 8) * ROWBB) +
                                      (wn + ((lane >> 4) & 1) * 8) * 2);

    load_stage(0, 0);
    cp_commit();
    load_stage(1, 1);
    cp_commit();

    int stg = 0;
    for (int kt = 0; kt < NKT; ++kt) {
        if (kt + 1 < NKT) cp_wait<1>(); else cp_wait<0>();
        __syncthreads();

        if (kt + 2 < NKT) {
            int s2 = stg + 2; if (s2 >= NSTAGE) s2 -= NSTAGE;
            load_stage(kt + 2, s2);
            cp_commit();
        }

        const uint32_t s0 = sb + stg * STG_BYTES;
#pragma unroll
        for (int ks = 0; ks < 2; ++ks) {
            const uint32_t akoff = s0 + aoffb + ks * 32;
            const uint32_t bkoff = s0 + OFF_B + boffb + ks * 16 * ROWBB;

            uint32_t fa[4][4];
#pragma unroll
            for (int mt = 0; mt < 4; ++mt)
                ldsm4(akoff + mt * 16 * ROWB,
                      fa[mt][0], fa[mt][1], fa[mt][2], fa[mt][3]);
            uint32_t fb[8];
            ldsm4t(bkoff,      fb[0], fb[1], fb[2], fb[3]);   // n 0-15 of warp
            ldsm4t(bkoff + 32, fb[4], fb[5], fb[6], fb[7]);   // n 16-31 of warp

#pragma unroll
            for (int mt = 0; mt < 4; ++mt)
#pragma unroll
                for (int nt = 0; nt < 4; ++nt) {
                    // fb layout: [nb*4 + {0,1}] = n-octet 2nb k0-15; [nb*4+{2,3}] octet 2nb+1
                    const int q = (nt >> 1) * 4 + (nt & 1) * 2;
                    mma_f16(acc[mt][nt][0], acc[mt][nt][1], acc[mt][nt][2], acc[mt][nt][3],
                            fa[mt][0], fa[mt][1], fa[mt][2], fa[mt][3],
                            fb[q], fb[q + 1]);
                }
        }
        if (++stg >= NSTAGE) stg = 0;
    }

    // epilogue
    const int erow = (lane >> 2);
    const int ecol = (lane & 3) * 2;
#pragma unroll
    for (int mt = 0; mt < 4; ++mt) {
#pragma unroll
        for (int nt = 0; nt < 4; ++nt) {
#pragma unroll
            for (int half = 0; half < 2; ++half) {
                const int row = m0 + wm + mt * 16 + erow + half * 8;
                const int col = n0 + wn + nt * 8 + ecol;
                float v0 = acc[mt][nt][half * 2 + 0] + bias[col];
                float v1 = acc[mt][nt][half * 2 + 1] + bias[col + 1];
                if (MODE == 0) {
                    const int bb = row >> 11, s = row & 2047;
                    const int part = col >> 10;
                    const int dd = col & 1023;
                    const int h = dd >> 6, hd = dd & 63;
                    const int bh = (bb << 4) + h;
                    if (part == 2) {
                        const size_t base = ((size_t)bh * DHEAD + hd) * SEQ + s;
                        s_vt[base]       = __float2half_rn(v0);
                        s_vt[base + SEQ] = __float2half_rn(v1);
                    } else {
                        if (part == 0) { v0 *= 0.125f; v1 *= 0.125f; }
                        const size_t base = ((size_t)bh * SEQ + s) * DHEAD + hd;
                        __half* dst = (part == 0) ? s_q : s_k;
                        *(uint32_t*)(dst + base) = packh_f(v0, v1);
                    }
                } else {
                    *(float2*)(outp + (size_t)row * DIM + col) = make_float2(v0, v1);
                }
            }
        }
    }
}

// ---------------------------------------------------------------------------
// Tensor-core flash attention, all-single fp16, fp32 softmax.
// cp.async 2-stage KV, 3 CTAs/SM, heavy query tiles first. (unchanged R13)
// ---------------------------------------------------------------------------
#define AROWB 144
#define AQ 0
#define AKV0 18432
#define AKV_STG 18432          // K (9216) + VT (9216)
#define AV_OFF 9216
#define ASM_BYTES (AKV0 + 2 * AKV_STG)   // 55296; x3 CTAs = 166KB/SM

__global__ __launch_bounds__(128, 3) void attn_tc_kernel()
{
    extern __shared__ char asmem[];
    const uint32_t sb = smem_u32(asmem);
    const int tid  = threadIdx.x;
    const int w    = tid >> 5;
    const int lane = tid & 31;
    const int qt   = (int)(gridDim.x - 1) - (int)blockIdx.x;  // heavy tiles first
    const int bh   = blockIdx.y;
    const int q0   = qt * 128;

    const __half* Qg = s_q  + (size_t)bh * SEQ * DHEAD;
    const __half* Kg = s_k  + (size_t)bh * SEQ * DHEAD;
    const __half* Vg = s_vt + (size_t)bh * DHEAD * SEQ;

    auto load_kv = [&](int kt, int stg) {
        const uint32_t s0 = sb + AKV0 + stg * AKV_STG;
        const int kv0 = kt * 64;
#pragma unroll
        for (int i = 0; i < 4; ++i) {
            const int c = tid + i * 128;
            const int row = c >> 3, seg = c & 7;
            const uint32_t so = row * AROWB + seg * 16;
            const size_t gk = (size_t)(kv0 + row) * DHEAD + seg * 8;
            const size_t gv = (size_t)row * SEQ + kv0 + seg * 8;
            cp16(s0 + so, Kg + gk);
            cp16(s0 + AV_OFF + so, Vg + gv);
        }
    };

    // Q tile (128 rows x 64 fp16)
#pragma unroll
    for (int i = 0; i < 8; ++i) {
        const int c = tid + i * 128;
        const int row = c >> 3, seg = c & 7;
        const uint32_t so = row * AROWB + seg * 16;
        const size_t go = (size_t)(q0 + row) * DHEAD + seg * 8;
        *(uint4*)(asmem + AQ + so) = *(const uint4*)(Qg + go);
    }

    const int ar = lane & 15, ahh = lane >> 4;
    const int grp = lane >> 3, l8 = lane & 7;
    const int row0 = lane >> 2, coll = (lane & 3) * 2;

    float m_run[4], l_run[4];
#pragma unroll
    for (int i = 0; i < 4; ++i) { m_run[i] = -1e30f; l_run[i] = 0.f; }
    float oacc[2][8][4];
#pragma unroll
    for (int mt = 0; mt < 2; ++mt)
#pragma unroll
        for (int nt = 0; nt < 8; ++nt)
#pragma unroll
            for (int e = 0; e < 4; ++e) oacc[mt][nt][e] = 0.f;

    const int ntiles = qt * 2 + 2;
    load_kv(0, 0);
    cp_commit();

    for (int kt = 0; kt < ntiles; ++kt) {
        if (kt + 1 < ntiles) {
            load_kv(kt + 1, (kt + 1) & 1);
            cp_commit();
            cp_wait<1>();
        } else {
            cp_wait<0>();
        }
        __syncthreads();

        const uint32_t kvb = sb + AKV0 + (kt & 1) * AKV_STG;
        const int kv0 = kt * 64;

        // ---- scores: S = Q K^T ----
        float s[2][8][4];
#pragma unroll
        for (int mt = 0; mt < 2; ++mt)
#pragma unroll
            for (int nt = 0; nt < 8; ++nt)
#pragma unroll
                for (int e = 0; e < 4; ++e) s[mt][nt][e] = 0.f;

#pragma unroll
        for (int ks = 0; ks < 4; ++ks) {
            uint32_t kb[4][4];
#pragma unroll
            for (int nb = 0; nb < 4; ++nb) {
                const uint32_t bo = (uint32_t)(((grp >> 1) * 8 + l8 + nb * 16) * AROWB +
                                               (grp & 1) * 16 + ks * 32);
                ldsm4(kvb + bo, kb[nb][0], kb[nb][1], kb[nb][2], kb[nb][3]);
            }
            uint32_t qf[2][4];
#pragma unroll
            for (int mt = 0; mt < 2; ++mt) {
                const uint32_t ao = (uint32_t)((w * 32 + mt * 16 + ar) * AROWB +
                                               ahh * 16 + ks * 32);
                ldsm4(sb + AQ + ao, qf[mt][0], qf[mt][1], qf[mt][2], qf[mt][3]);
            }
#pragma unroll
            for (int mt = 0; mt < 2; ++mt)
#pragma unroll
                for (int nt = 0; nt < 8; ++nt) {
                    const int nb = nt >> 1, p = nt & 1;
                    mma_f16(s[mt][nt][0], s[mt][nt][1], s[mt][nt][2], s[mt][nt][3],
                            qf[mt][0], qf[mt][1], qf[mt][2], qf[mt][3],
                            kb[nb][p * 2], kb[nb][p * 2 + 1]);
                }
        }

        // ---- causal mask (last two tiles only) ----
        if (kt >= qt * 2) {
#pragma unroll
            for (int mt = 0; mt < 2; ++mt) {
                const int rbase = q0 + w * 32 + mt * 16 + row0;
#pragma unroll
                for (int nt = 0; nt < 8; ++nt) {
                    const int cb = kv0 + nt * 8 + coll;
                    if (cb > rbase)     s[mt][nt][0] = -10000.f;
                    if (cb + 1 > rbase) s[mt][nt][1] = -10000.f;
                    if (cb > rbase + 8)     s[mt][nt][2] = -10000.f;
                    if (cb + 1 > rbase + 8) s[mt][nt][3] = -10000.f;
                }
            }
        }

        // ---- online softmax ----
        float corr[4];
#pragma unroll
        for (int slot = 0; slot < 4; ++slot) {
            const int mt = slot >> 1, h2 = slot & 1;
            float tm = -1e30f;
#pragma unroll
            for (int nt = 0; nt < 8; ++nt)
                tm = fmaxf(tm, fmaxf(s[mt][nt][h2 * 2], s[mt][nt][h2 * 2 + 1]));
            tm = fmaxf(tm, __shfl_xor_sync(0xffffffffu, tm, 1));
            tm = fmaxf(tm, __shfl_xor_sync(0xffffffffu, tm, 2));
            const float mnew = fmaxf(m_run[slot], tm);
            corr[slot] = __expf(m_run[slot] - mnew);
            m_run[slot] = mnew;
            l_run[slot] *= corr[slot];
        }
#pragma unroll
        for (int mt = 0; mt < 2; ++mt)
#pragma unroll
            for (int nt = 0; nt < 8; ++nt) {
                oacc[mt][nt][0] *= corr[mt * 2];
                oacc[mt][nt][1] *= corr[mt * 2];
                oacc[mt][nt][2] *= corr[mt * 2 + 1];
                oacc[mt][nt][3] *= corr[mt * 2 + 1];
            }

        // ---- P = exp(S - m), fp16 pack ----
        uint32_t pf[2][8][2];
#pragma unroll
        for (int mt = 0; mt < 2; ++mt)
#pragma unroll
            for (int nt = 0; nt < 8; ++nt) {
                const float p0 = __expf(s[mt][nt][0] - m_run[mt * 2]);
                const float p1 = __expf(s[mt][nt][1] - m_run[mt * 2]);
                const float p2 = __expf(s[mt][nt][2] - m_run[mt * 2 + 1]);
                const float p3 = __expf(s[mt][nt][3] - m_run[mt * 2 + 1]);
                l_run[mt * 2]     += p0 + p1;
                l_run[mt * 2 + 1] += p2 + p3;
                pf[mt][nt][0] = packh_f(p0, p1);
                pf[mt][nt][1] = packh_f(p2, p3);
            }

        // ---- O += P V ----
#pragma unroll
        for (int ks = 0; ks < 4; ++ks) {
            uint32_t vb[4][4];
#pragma unroll
            for (int nb = 0; nb < 4; ++nb) {
                const uint32_t bo = (uint32_t)(((grp >> 1) * 8 + l8 + nb * 16) * AROWB +
                                               (grp & 1) * 16 + ks * 32);
                ldsm4(kvb + AV_OFF + bo, vb[nb][0], vb[nb][1], vb[nb][2], vb[nb][3]);
            }
#pragma unroll
            for (int mt = 0; mt < 2; ++mt)
#pragma unroll
                for (int nt = 0; nt < 8; ++nt) {
                    const int nb = nt >> 1, p = nt & 1;
                    mma_f16(oacc[mt][nt][0], oacc[mt][nt][1], oacc[mt][nt][2], oacc[mt][nt][3],
                            pf[mt][ks * 2][0], pf[mt][ks * 2][1],
                            pf[mt][ks * 2 + 1][0], pf[mt][ks * 2 + 1][1],
                            vb[nb][p * 2], vb[nb][p * 2 + 1]);
                }
        }
        __syncthreads();
    }

    // ---- finalize ----
    float inv[4];
#pragma unroll
    for (int slot = 0; slot < 4; ++slot) {
        float lt = l_run[slot];
        lt += __shfl_xor_sync(0xffffffffu, lt, 1);
        lt += __shfl_xor_sync(0xffffffffu, lt, 2);
        inv[slot] = 1.f / lt;
    }
    const int b = bh >> 4, h = bh & 15;
#pragma unroll
    for (int mt = 0; mt < 2; ++mt) {
#pragma unroll
        for (int half = 0; half < 2; ++half) {
            const size_t orow = (size_t)b * SEQ + q0 + w * 32 + mt * 16 + row0 + half * 8;
            const float iv = inv[mt * 2 + half];
#pragma unroll
            for (int nt = 0; nt < 8; ++nt) {
                const int col = h * DHEAD + nt * 8 + coll;
                const float v0 = oacc[mt][nt][half * 2 + 0] * iv;
                const float v1 = oacc[mt][nt][half * 2 + 1] * iv;
                *(uint32_t*)(s_a + orow * DIM + col) = packh_f(v0, v1);
            }
        }
    }
}

// ---------------------------------------------------------------------------
extern "C" void kernel_launch(void* const* d_in, const int* in_sizes, int n_in,
                              void* d_out, int out_size)
{
    const float* x      = (const float*)d_in[0];
    const float* w_attn = (const float*)d_in[1];
    const float* b_attn = (const float*)d_in[2];
    const float* w_proj = (const float*)d_in[3];
    const float* b_proj = (const float*)d_in[4];
    float* out = (float*)d_out;

    __half *xa, *wq, *wp;
    cudaGetSymbolAddress((void**)&xa, s_a);
    cudaGetSymbolAddress((void**)&wq, s_wq);
    cudaGetSymbolAddress((void**)&wp, s_wp);

    cudaFuncSetAttribute((tc_gemm_kernel<0, NQKV>),
                         cudaFuncAttributeMaxDynamicSharedMemorySize, GSM_BYTES);
    cudaFuncSetAttribute((tc_gemm_kernel<1, DIM>),
                         cudaFuncAttributeMaxDynamicSharedMemorySize, GSM_BYTES);
    cudaFuncSetAttribute(attn_tc_kernel,
                         cudaFuncAttributeMaxDynamicSharedMemorySize, ASM_BYTES);

    // 1) fused convert: x, w_attn, w_proj -> fp16 (natural layouts)
    const int total4 = XN4 + WAN4 + WPN4;
    convert_all_kernel<<<(total4 + 255) / 256, 256>>>(x, w_attn, w_proj, xa, wq, wp);
    // 2) QKV GEMM (B = w_attn [K,N] via trans-ldsm) -> q/k/vt fp16
    tc_gemm_kernel<0, NQKV><<<dim3(NQKV / BN, MROWS / BM), 256, GSM_BYTES>>>(
        xa, wq, b_attn, nullptr);
    // 3) tensor-core flash attention -> writes s_a (fp16)
    attn_tc_kernel<<<dim3(SEQ / 128, BATCH * NHEAD), 128, ASM_BYTES>>>();
    // 4) output projection (B = w_proj [K,N] via trans-ldsm)
    tc_gemm_kernel<1, DIM><<<dim3(DIM / BN, MROWS / BM), 256, GSM_BYTES>>>(
        xa, wp, b_proj, out);
}

// round 15
// speedup vs baseline: 2.6627x; 1.0056x over previous
#include <cuda_runtime.h>
#include <cuda_fp16.h>
#include <cstdint>

// Problem shape (fixed by the dataset)
#define BATCH 2
#define SEQ   2048
#define DIM   1024
#define NHEAD 16
#define DHEAD 64
#define MROWS (BATCH * SEQ)          // 4096
#define NQKV  (3 * DIM)              // 3072
#define KTOT  1024

// ---------------------------------------------------------------------------
// Scratch (allocation-free rule: __device__ globals), all single fp16
// ---------------------------------------------------------------------------
__device__ __half s_a[MROWS * KTOT];      // GEMM A: x, then attention out
__device__ __half s_wq[KTOT * NQKV];      // w_attn [1024,3072] natural layout
__device__ __half s_wp[KTOT * DIM];       // w_proj [1024,1024] natural layout
// attention operands, written by QKV epilogue — ALL [bh,s,dh] now
__device__ __half s_q[BATCH * NHEAD * SEQ * DHEAD];     // q*0.125
__device__ __half s_k[BATCH * NHEAD * SEQ * DHEAD];
__device__ __half s_v[BATCH * NHEAD * SEQ * DHEAD];     // natural (trans-ldsm in attn)

// ---------------------------------------------------------------------------
// PTX helpers (baseline ISA — compiles for sm_103)
// ---------------------------------------------------------------------------
__device__ __forceinline__ uint32_t smem_u32(const void* p) {
    uint32_t a;
    asm("{ .reg .u64 t; cvta.to.shared.u64 t, %1; cvt.u32.u64 %0, t; }"
        : "=r"(a) : "l"(p));
    return a;
}
__device__ __forceinline__ void ldsm4(uint32_t addr, uint32_t& r0, uint32_t& r1,
                                      uint32_t& r2, uint32_t& r3) {
    asm volatile("ldmatrix.sync.aligned.m8n8.x4.shared.b16 {%0,%1,%2,%3}, [%4];"
                 : "=r"(r0), "=r"(r1), "=r"(r2), "=r"(r3) : "r"(addr));
}
__device__ __forceinline__ void ldsm4t(uint32_t addr, uint32_t& r0, uint32_t& r1,
                                       uint32_t& r2, uint32_t& r3) {
    asm volatile("ldmatrix.sync.aligned.m8n8.x4.trans.shared.b16 {%0,%1,%2,%3}, [%4];"
                 : "=r"(r0), "=r"(r1), "=r"(r2), "=r"(r3) : "r"(addr));
}
__device__ __forceinline__ void mma_f16(float& c0, float& c1, float& c2, float& c3,
                                        uint32_t a0, uint32_t a1, uint32_t a2, uint32_t a3,
                                        uint32_t b0, uint32_t b1) {
    asm volatile("mma.sync.aligned.m16n8k16.row.col.f32.f16.f16.f32 "
                 "{%0,%1,%2,%3}, {%4,%5,%6,%7}, {%8,%9}, {%0,%1,%2,%3};"
                 : "+f"(c0), "+f"(c1), "+f"(c2), "+f"(c3)
                 : "r"(a0), "r"(a1), "r"(a2), "r"(a3), "r"(b0), "r"(b1));
}
__device__ __forceinline__ void cp16(uint32_t saddr, const void* g) {
    asm volatile("cp.async.cg.shared.global [%0], [%1], 16;"
                 :: "r"(saddr), "l"(g) : "memory");
}
__device__ __forceinline__ void cp_commit() {
    asm volatile("cp.async.commit_group;" ::: "memory");
}
template <int N>
__device__ __forceinline__ void cp_wait() {
    asm volatile("cp.async.wait_group %0;" :: "n"(N) : "memory");
}
__device__ __forceinline__ uint32_t packh_f(float a, float b) {
    __half2 p = __floats2half2_rn(a, b);
    return *(uint32_t*)&p;
}

// ---------------------------------------------------------------------------
// Fused prep: convert x, w_attn, w_proj fp32 -> fp16 (elementwise, one kernel)
// ---------------------------------------------------------------------------
#define XN4  (MROWS * KTOT / 4)
#define WAN4 (KTOT * NQKV / 4)
#define WPN4 (KTOT * DIM / 4)

__global__ __launch_bounds__(256) void convert_all_kernel(
    const float* __restrict__ x, const float* __restrict__ wa,
    const float* __restrict__ wpr, __half* __restrict__ dx,
    __half* __restrict__ dwa, __half* __restrict__ dwp)
{
    int i = blockIdx.x * 256 + threadIdx.x;
    const float* src;
    __half* dst;
    if (i < XN4) {
        src = x; dst = dx;
    } else if (i < XN4 + WAN4) {
        i -= XN4; src = wa; dst = dwa;
    } else {
        i -= XN4 + WAN4;
        if (i >= WPN4) return;
        src = wpr; dst = dwp;
    }
    float4 v = ((const float4*)src)[i];
    uint2 u = make_uint2(packh_f(v.x, v.y), packh_f(v.z, v.w));
    *(uint2*)(dst + (size_t)i * 4) = u;
}

// ---------------------------------------------------------------------------
// HMMA GEMM, fp16, B natural [K,N] via ldmatrix.trans, 3-stage cp.async,
// 1 barrier/iter, 2 CTAs/SM. D[M,N] = A @ B + bias.
// MODE 0: QKV epilogue -> q/k/v ALL coalesced [bh,s,dh] (q*0.125)
// MODE 1: plain fp32 out
// ---------------------------------------------------------------------------
#define BM 128
#define BN 128
#define BK 32
#define ROWB  80
#define ROWBB 272
#define NKT (KTOT / BK)
#define OFF_B   10240
#define STG_BYTES (10240 + 32 * ROWBB)   // 18944
#define NSTAGE 3
#define GSM_BYTES (NSTAGE * STG_BYTES)

template <int MODE, int NB>
__global__ __launch_bounds__(256, 2) void tc_gemm_kernel(
    const __half* __restrict__ A, const __half* __restrict__ B,
    const float* __restrict__ bias, float* __restrict__ outp)
{
    extern __shared__ char gsm[];
    const uint32_t sb = smem_u32(gsm);

    const int tid  = threadIdx.x;
    const int w    = tid >> 5;
    const int lane = tid & 31;
    const int m0 = blockIdx.y * BM;
    const int n0 = blockIdx.x * BN;
    const int wm = (w >> 2) * 64;
    const int wn = (w & 3) * 32;

    const int srow = tid >> 2;
    const int sseg = tid & 3;
    const size_t gA = (size_t)(m0 + srow) * KTOT + sseg * 8;
    const size_t rstepA = (size_t)64 * KTOT;
    const uint32_t aoff0 = (uint32_t)(srow * ROWB + sseg * 16);
    const uint32_t aoff1 = aoff0 + 64 * ROWB;
    const int bkr  = tid >> 4;
    const int bseg = tid & 15;
    const size_t gB = (size_t)bkr * NB + n0 + bseg * 8;
    const size_t rstepB = (size_t)16 * NB;
    const uint32_t boff0 = (uint32_t)(bkr * ROWBB + bseg * 16);
    const uint32_t boff1 = boff0 + 16 * ROWBB;

    auto load_stage = [&](int kt, int stg) {
        const uint32_t s0 = sb + stg * STG_BYTES;
        const __half* pa = A + gA + (size_t)kt * BK;
        const __half* pb = B + gB + (size_t)kt * BK * NB;
        cp16(s0 + aoff0, pa);            cp16(s0 + aoff1, pa + rstepA);
        cp16(s0 + OFF_B + boff0, pb);    cp16(s0 + OFF_B + boff1, pb + rstepB);
    };

    float acc[4][4][4];
#pragma unroll
    for (int i = 0; i < 4; ++i)
#pragma unroll
        for (int j = 0; j < 4; ++j)
#pragma unroll
            for (int e = 0; e < 4; ++e) acc[i][j][e] = 0.f;

    const int ar = lane & 15, ah = lane >> 4;
    const uint32_t aoffb = (uint32_t)((wm + ar) * ROWB + ah * 16);
    const uint32_t boffb = (uint32_t)((((lane & 7) + ((lane >> 3) & 1) * 8) * ROWBB) +
                                      (wn + ((lane >> 4) & 1) * 8) * 2);

    load_stage(0, 0);
    cp_commit();
    load_stage(1, 1);
    cp_commit();

    int stg = 0;
    for (int kt = 0; kt < NKT; ++kt) {
        if (kt + 1 < NKT) cp_wait<1>(); else cp_wait<0>();
        __syncthreads();

        if (kt + 2 < NKT) {
            int s2 = stg + 2; if (s2 >= NSTAGE) s2 -= NSTAGE;
            load_stage(kt + 2, s2);
            cp_commit();
        }

        const uint32_t s0 = sb + stg * STG_BYTES;
#pragma unroll
        for (int ks = 0; ks < 2; ++ks) {
            const uint32_t akoff = s0 + aoffb + ks * 32;
            const uint32_t bkoff = s0 + OFF_B + boffb + ks * 16 * ROWBB;

            uint32_t fa[4][4];
#pragma unroll
            for (int mt = 0; mt < 4; ++mt)
                ldsm4(akoff + mt * 16 * ROWB,
                      fa[mt][0], fa[mt][1], fa[mt][2], fa[mt][3]);
            uint32_t fb[8];
            ldsm4t(bkoff,      fb[0], fb[1], fb[2], fb[3]);
            ldsm4t(bkoff + 32, fb[4], fb[5], fb[6], fb[7]);

#pragma unroll
            for (int mt = 0; mt < 4; ++mt)
#pragma unroll
                for (int nt = 0; nt < 4; ++nt)
                    mma_f16(acc[mt][nt][0], acc[mt][nt][1], acc[mt][nt][2], acc[mt][nt][3],
                            fa[mt][0], fa[mt][1], fa[mt][2], fa[mt][3],
                            fb[nt * 2], fb[nt * 2 + 1]);
        }
        if (++stg >= NSTAGE) stg = 0;
    }

    // epilogue — MODE 0 now fully coalesced for q, k, AND v
    const int erow = (lane >> 2);
    const int ecol = (lane & 3) * 2;
#pragma unroll
    for (int mt = 0; mt < 4; ++mt) {
#pragma unroll
        for (int nt = 0; nt < 4; ++nt) {
#pragma unroll
            for (int half = 0; half < 2; ++half) {
                const int row = m0 + wm + mt * 16 + erow + half * 8;
                const int col = n0 + wn + nt * 8 + ecol;
                float v0 = acc[mt][nt][half * 2 + 0] + bias[col];
                float v1 = acc[mt][nt][half * 2 + 1] + bias[col + 1];
                if (MODE == 0) {
                    const int bb = row >> 11, s = row & 2047;
                    const int part = col >> 10;
                    const int dd = col & 1023;
                    const int h = dd >> 6, hd = dd & 63;
                    const int bh = (bb << 4) + h;
                    if (part == 0) { v0 *= 0.125f; v1 *= 0.125f; }
                    const size_t base = ((size_t)bh * SEQ + s) * DHEAD + hd;
                    __half* dst = (part == 0) ? s_q : ((part == 1) ? s_k : s_v);
                    *(uint32_t*)(dst + base) = packh_f(v0, v1);
                } else {
                    *(float2*)(outp + (size_t)row * DIM + col) = make_float2(v0, v1);
                }
            }
        }
    }
}

// ---------------------------------------------------------------------------
// Tensor-core flash attention, all-single fp16, fp32 softmax.
// V consumed in natural [s,dh] layout via ldmatrix.trans (like GEMM B).
// 3-stage KV cp.async ring, ONE barrier per tile, 3 CTAs/SM, heavy-first.
// ---------------------------------------------------------------------------
#define AROWB 144
#define AQ 0
#define AKV0 18432
#define AKV_STG 18432          // K (9216) + V (9216)
#define AV_OFF 9216
#define ASM_BYTES (AKV0 + 3 * AKV_STG)   // 73728; x3 CTAs = 216KB/SM

__global__ __launch_bounds__(128, 3) void attn_tc_kernel()
{
    extern __shared__ char asmem[];
    const uint32_t sb = smem_u32(asmem);
    const int tid  = threadIdx.x;
    const int w    = tid >> 5;
    const int lane = tid & 31;
    const int qt   = (int)(gridDim.x - 1) - (int)blockIdx.x;  // heavy tiles first
    const int bh   = blockIdx.y;
    const int q0   = qt * 128;

    const __half* Qg = s_q + (size_t)bh * SEQ * DHEAD;
    const __half* Kg = s_k + (size_t)bh * SEQ * DHEAD;
    const __half* Vg = s_v + (size_t)bh * SEQ * DHEAD;

    auto load_kv = [&](int kt, int stg) {
        const uint32_t s0 = sb + AKV0 + stg * AKV_STG;
        const int kv0 = kt * 64;
#pragma unroll
        for (int i = 0; i < 4; ++i) {
            const int c = tid + i * 128;
            const int row = c >> 3, seg = c & 7;
            const uint32_t so = row * AROWB + seg * 16;
            const size_t g = (size_t)(kv0 + row) * DHEAD + seg * 8;
            cp16(s0 + so, Kg + g);
            cp16(s0 + AV_OFF + so, Vg + g);   // V natural layout, same addressing
        }
    };

    // Q tile (128 rows x 64 fp16)
#pragma unroll
    for (int i = 0; i < 8; ++i) {
        const int c = tid + i * 128;
        const int row = c >> 3, seg = c & 7;
        const uint32_t so = row * AROWB + seg * 16;
        const size_t go = (size_t)(q0 + row) * DHEAD + seg * 8;
        *(uint4*)(asmem + AQ + so) = *(const uint4*)(Qg + go);
    }

    const int ar = lane & 15, ahh = lane >> 4;
    const int grp = lane >> 3, l8 = lane & 7;
    const int row0 = lane >> 2, coll = (lane & 3) * 2;
    // trans-ldsm V address components (same mapping as GEMM B)
    const int trow = (lane & 7) + ((lane >> 3) & 1) * 8;
    const uint32_t tcol = ((lane >> 4) & 1) * 16;

    float m_run[4], l_run[4];
#pragma unroll
    for (int i = 0; i < 4; ++i) { m_run[i] = -1e30f; l_run[i] = 0.f; }
    float oacc[2][8][4];
#pragma unroll
    for (int mt = 0; mt < 2; ++mt)
#pragma unroll
        for (int nt = 0; nt < 8; ++nt)
#pragma unroll
            for (int e = 0; e < 4; ++e) oacc[mt][nt][e] = 0.f;

    const int ntiles = qt * 2 + 2;
    load_kv(0, 0);
    cp_commit();
    if (1 < ntiles) { load_kv(1, 1); cp_commit(); }

    int stg = 0;
    for (int kt = 0; kt < ntiles; ++kt) {
        if (kt + 1 < ntiles) cp_wait<1>(); else cp_wait<0>();
        __syncthreads();

        if (kt + 2 < ntiles) {
            int s2 = stg + 2; if (s2 >= NSTAGE) s2 -= NSTAGE;
            load_kv(kt + 2, s2);
            cp_commit();
        }

        const uint32_t kvb = sb + AKV0 + stg * AKV_STG;
        const int kv0 = kt * 64;

        // ---- scores: S = Q K^T ----
        float s[2][8][4];
#pragma unroll
        for (int mt = 0; mt < 2; ++mt)
#pragma unroll
            for (int nt = 0; nt < 8; ++nt)
#pragma unroll
                for (int e = 0; e < 4; ++e) s[mt][nt][e] = 0.f;

#pragma unroll
        for (int ks = 0; ks < 4; ++ks) {
            uint32_t kb[4][4];
#pragma unroll
            for (int nb = 0; nb < 4; ++nb) {
                const uint32_t bo = (uint32_t)(((grp >> 1) * 8 + l8 + nb * 16) * AROWB +
                                               (grp & 1) * 16 + ks * 32);
                ldsm4(kvb + bo, kb[nb][0], kb[nb][1], kb[nb][2], kb[nb][3]);
            }
            uint32_t qf[2][4];
#pragma unroll
            for (int mt = 0; mt < 2; ++mt) {
                const uint32_t ao = (uint32_t)((w * 32 + mt * 16 + ar) * AROWB +
                                               ahh * 16 + ks * 32);
                ldsm4(sb + AQ + ao, qf[mt][0], qf[mt][1], qf[mt][2], qf[mt][3]);
            }
#pragma unroll
            for (int mt = 0; mt < 2; ++mt)
#pragma unroll
                for (int nt = 0; nt < 8; ++nt) {
                    const int nb = nt >> 1, p = nt & 1;
                    mma_f16(s[mt][nt][0], s[mt][nt][1], s[mt][nt][2], s[mt][nt][3],
                            qf[mt][0], qf[mt][1], qf[mt][2], qf[mt][3],
                            kb[nb][p * 2], kb[nb][p * 2 + 1]);
                }
        }

        // ---- causal mask (last two tiles only) ----
        if (kt >= qt * 2) {
#pragma unroll
            for (int mt = 0; mt < 2; ++mt) {
                const int rbase = q0 + w * 32 + mt * 16 + row0;
#pragma unroll
                for (int nt = 0; nt < 8; ++nt) {
                    const int cb = kv0 + nt * 8 + coll;
                    if (cb > rbase)     s[mt][nt][0] = -10000.f;
                    if (cb + 1 > rbase) s[mt][nt][1] = -10000.f;
                    if (cb > rbase + 8)     s[mt][nt][2] = -10000.f;
                    if (cb + 1 > rbase + 8) s[mt][nt][3] = -10000.f;
                }
            }
        }

        // ---- online softmax ----
        float corr[4];
#pragma unroll
        for (int slot = 0; slot < 4; ++slot) {
            const int mt = slot >> 1, h2 = slot & 1;
            float tm = -1e30f;
#pragma unroll
            for (int nt = 0; nt < 8; ++nt)
                tm = fmaxf(tm, fmaxf(s[mt][nt][h2 * 2], s[mt][nt][h2 * 2 + 1]));
            tm = fmaxf(tm, __shfl_xor_sync(0xffffffffu, tm, 1));
            tm = fmaxf(tm, __shfl_xor_sync(0xffffffffu, tm, 2));
            const float mnew = fmaxf(m_run[slot], tm);
            corr[slot] = __expf(m_run[slot] - mnew);
            m_run[slot] = mnew;
            l_run[slot] *= corr[slot];
        }
#pragma unroll
        for (int mt = 0; mt < 2; ++mt)
#pragma unroll
            for (int nt = 0; nt < 8; ++nt) {
                oacc[mt][nt][0] *= corr[mt * 2];
                oacc[mt][nt][1] *= corr[mt * 2];
                oacc[mt][nt][2] *= corr[mt * 2 + 1];
                oacc[mt][nt][3] *= corr[mt * 2 + 1];
            }

        // ---- P = exp(S - m), fp16 pack ----
        uint32_t pf[2][8][2];
#pragma unroll
        for (int mt = 0; mt < 2; ++mt)
#pragma unroll
            for (int nt = 0; nt < 8; ++nt) {
                const float p0 = __expf(s[mt][nt][0] - m_run[mt * 2]);
                const float p1 = __expf(s[mt][nt][1] - m_run[mt * 2]);
                const float p2 = __expf(s[mt][nt][2] - m_run[mt * 2 + 1]);
                const float p3 = __expf(s[mt][nt][3] - m_run[mt * 2 + 1]);
                l_run[mt * 2]     += p0 + p1;
                l_run[mt * 2 + 1] += p2 + p3;
                pf[mt][nt][0] = packh_f(p0, p1);
                pf[mt][nt][1] = packh_f(p2, p3);
            }

        // ---- O += P V  (V natural [s,dh]; trans-ldsm -> B fragments) ----
#pragma unroll
        for (int ks = 0; ks < 4; ++ks) {
            uint32_t vb[4][4];
#pragma unroll
            for (int nb = 0; nb < 4; ++nb) {
                const uint32_t bo = (uint32_t)((trow + ks * 16) * AROWB + tcol + nb * 32);
                ldsm4t(kvb + AV_OFF + bo, vb[nb][0], vb[nb][1], vb[nb][2], vb[nb][3]);
            }
#pragma unroll
            for (int mt = 0; mt < 2; ++mt)
#pragma unroll
                for (int nt = 0; nt < 8; ++nt) {
                    const int nb = nt >> 1, p = nt & 1;
                    mma_f16(oacc[mt][nt][0], oacc[mt][nt][1], oacc[mt][nt][2], oacc[mt][nt][3],
                            pf[mt][ks * 2][0], pf[mt][ks * 2][1],
                            pf[mt][ks * 2 + 1][0], pf[mt][ks * 2 + 1][1],
                            vb[nb][p * 2], vb[nb][p * 2 + 1]);
                }
        }
        if (++stg >= NSTAGE) stg = 0;
    }

    // ---- finalize ----
    float inv[4];
#pragma unroll
    for (int slot = 0; slot < 4; ++slot) {
        float lt = l_run[slot];
        lt += __shfl_xor_sync(0xffffffffu, lt, 1);
        lt += __shfl_xor_sync(0xffffffffu, lt, 2);
        inv[slot] = 1.f / lt;
    }
    const int b = bh >> 4, h = bh & 15;
#pragma unroll
    for (int mt = 0; mt < 2; ++mt) {
#pragma unroll
        for (int half = 0; half < 2; ++half) {
            const size_t orow = (size_t)b * SEQ + q0 + w * 32 + mt * 16 + row0 + half * 8;
            const float iv = inv[mt * 2 + half];
#pragma unroll
            for (int nt = 0; nt < 8; ++nt) {
                const int col = h * DHEAD + nt * 8 + coll;
                const float v0 = oacc[mt][nt][half * 2 + 0] * iv;
                const float v1 = oacc[mt][nt][half * 2 + 1] * iv;
                *(uint32_t*)(s_a + orow * DIM + col) = packh_f(v0, v1);
            }
        }
    }
}

// ---------------------------------------------------------------------------
extern "C" void kernel_launch(void* const* d_in, const int* in_sizes, int n_in,
                              void* d_out, int out_size)
{
    const float* x      = (const float*)d_in[0];
    const float* w_attn = (const float*)d_in[1];
    const float* b_attn = (const float*)d_in[2];
    const float* w_proj = (const float*)d_in[3];
    const float* b_proj = (const float*)d_in[4];
    float* out = (float*)d_out;

    __half *xa, *wq, *wp;
    cudaGetSymbolAddress((void**)&xa, s_a);
    cudaGetSymbolAddress((void**)&wq, s_wq);
    cudaGetSymbolAddress((void**)&wp, s_wp);

    cudaFuncSetAttribute((tc_gemm_kernel<0, NQKV>),
                         cudaFuncAttributeMaxDynamicSharedMemorySize, GSM_BYTES);
    cudaFuncSetAttribute((tc_gemm_kernel<1, DIM>),
                         cudaFuncAttributeMaxDynamicSharedMemorySize, GSM_BYTES);
    cudaFuncSetAttribute(attn_tc_kernel,
                         cudaFuncAttributeMaxDynamicSharedMemorySize, ASM_BYTES);

    // 1) fused convert: x, w_attn, w_proj -> fp16 (natural layouts)
    const int total4 = XN4 + WAN4 + WPN4;
    convert_all_kernel<<<(total4 + 255) / 256, 256>>>(x, w_attn, w_proj, xa, wq, wp);
    // 2) QKV GEMM -> q/k/v fp16, all coalesced [bh,s,dh]
    tc_gemm_kernel<0, NQKV><<<dim3(NQKV / BN, MROWS / BM), 256, GSM_BYTES>>>(
        xa, wq, b_attn, nullptr);
    // 3) tensor-core flash attention -> writes s_a (fp16)
    attn_tc_kernel<<<dim3(SEQ / 128, BATCH * NHEAD), 128, ASM_BYTES>>>();
    // 4) output projection
    tc_gemm_kernel<1, DIM><<<dim3(DIM / BN, MROWS / BM), 256, GSM_BYTES>>>(
        xa, wp, b_proj, out);
}

// round 16
// speedup vs baseline: 2.7559x; 1.0350x over previous
#include <cuda_runtime.h>
#include <cuda_fp16.h>
#include <cstdint>

// Problem shape (fixed by the dataset)
#define BATCH 2
#define SEQ   2048
#define DIM   1024
#define NHEAD 16
#define DHEAD 64
#define MROWS (BATCH * SEQ)          // 4096
#define NQKV  (3 * DIM)              // 3072
#define KTOT  1024

// ---------------------------------------------------------------------------
// Scratch (allocation-free rule: __device__ globals), all single fp16
// ---------------------------------------------------------------------------
__device__ __half s_a[MROWS * KTOT];      // GEMM A: x, then attention out
__device__ __half s_wq[KTOT * NQKV];      // w_attn [1024,3072] natural layout
__device__ __half s_wp[KTOT * DIM];       // w_proj [1024,1024] natural layout
// attention operands, written by QKV epilogue — all [bh,s,dh]
__device__ __half s_q[BATCH * NHEAD * SEQ * DHEAD];     // q*0.125
__device__ __half s_k[BATCH * NHEAD * SEQ * DHEAD];
__device__ __half s_v[BATCH * NHEAD * SEQ * DHEAD];

// ---------------------------------------------------------------------------
// PTX helpers (baseline ISA — compiles for sm_103)
// ---------------------------------------------------------------------------
__device__ __forceinline__ uint32_t smem_u32(const void* p) {
    uint32_t a;
    asm("{ .reg .u64 t; cvta.to.shared.u64 t, %1; cvt.u32.u64 %0, t; }"
        : "=r"(a) : "l"(p));
    return a;
}
__device__ __forceinline__ void ldsm4(uint32_t addr, uint32_t& r0, uint32_t& r1,
                                      uint32_t& r2, uint32_t& r3) {
    asm volatile("ldmatrix.sync.aligned.m8n8.x4.shared.b16 {%0,%1,%2,%3}, [%4];"
                 : "=r"(r0), "=r"(r1), "=r"(r2), "=r"(r3) : "r"(addr));
}
__device__ __forceinline__ void ldsm4t(uint32_t addr, uint32_t& r0, uint32_t& r1,
                                       uint32_t& r2, uint32_t& r3) {
    asm volatile("ldmatrix.sync.aligned.m8n8.x4.trans.shared.b16 {%0,%1,%2,%3}, [%4];"
                 : "=r"(r0), "=r"(r1), "=r"(r2), "=r"(r3) : "r"(addr));
}
__device__ __forceinline__ void mma_f16(float& c0, float& c1, float& c2, float& c3,
                                        uint32_t a0, uint32_t a1, uint32_t a2, uint32_t a3,
                                        uint32_t b0, uint32_t b1) {
    asm volatile("mma.sync.aligned.m16n8k16.row.col.f32.f16.f16.f32 "
                 "{%0,%1,%2,%3}, {%4,%5,%6,%7}, {%8,%9}, {%0,%1,%2,%3};"
                 : "+f"(c0), "+f"(c1), "+f"(c2), "+f"(c3)
                 : "r"(a0), "r"(a1), "r"(a2), "r"(a3), "r"(b0), "r"(b1));
}
__device__ __forceinline__ void cp16(uint32_t saddr, const void* g) {
    asm volatile("cp.async.cg.shared.global [%0], [%1], 16;"
                 :: "r"(saddr), "l"(g) : "memory");
}
__device__ __forceinline__ void cp_commit() {
    asm volatile("cp.async.commit_group;" ::: "memory");
}
template <int N>
__device__ __forceinline__ void cp_wait() {
    asm volatile("cp.async.wait_group %0;" :: "n"(N) : "memory");
}
__device__ __forceinline__ uint32_t packh_f(float a, float b) {
    __half2 p = __floats2half2_rn(a, b);
    return *(uint32_t*)&p;
}

// ---------------------------------------------------------------------------
// Fused prep: convert x, w_attn, w_proj fp32 -> fp16
// ---------------------------------------------------------------------------
#define XN4  (MROWS * KTOT / 4)
#define WAN4 (KTOT * NQKV / 4)
#define WPN4 (KTOT * DIM / 4)

__global__ __launch_bounds__(256) void convert_all_kernel(
    const float* __restrict__ x, const float* __restrict__ wa,
    const float* __restrict__ wpr, __half* __restrict__ dx,
    __half* __restrict__ dwa, __half* __restrict__ dwp)
{
    int i = blockIdx.x * 256 + threadIdx.x;
    const float* src;
    __half* dst;
    if (i < XN4) {
        src = x; dst = dx;
    } else if (i < XN4 + WAN4) {
        i -= XN4; src = wa; dst = dwa;
    } else {
        i -= XN4 + WAN4;
        if (i >= WPN4) return;
        src = wpr; dst = dwp;
    }
    float4 v = ((const float4*)src)[i];
    uint2 u = make_uint2(packh_f(v.x, v.y), packh_f(v.z, v.w));
    *(uint2*)(dst + (size_t)i * 4) = u;
}

// ---------------------------------------------------------------------------
// HMMA GEMM, fp16, BK=64 (64 MMAs per barrier interval), B natural [K,N] via
// ldmatrix.trans, 3-stage cp.async, 1 barrier/iter, 2 CTAs/SM.
// D[M,N] = A @ B + bias.
// MODE 0: QKV epilogue -> q/k/v coalesced [bh,s,dh] (q*0.125)
// MODE 1: plain fp32 out
// ---------------------------------------------------------------------------
#define BM 128
#define BN 128
#define BK 64
#define ROWB  144                // A: 128B data + 16B pad
#define ROWBB 272                // B: 256B data + 16B pad
#define NKT (KTOT / BK)          // 16
#define OFF_B   (128 * ROWB)     // 18432
#define STG_BYTES (OFF_B + 64 * ROWBB)   // 35840
#define NSTAGE 3
#define GSM_BYTES (NSTAGE * STG_BYTES)   // 107520/CTA; x2 CTAs = 215KB/SM

template <int MODE, int NB>
__global__ __launch_bounds__(256, 2) void tc_gemm_kernel(
    const __half* __restrict__ A, const __half* __restrict__ B,
    const float* __restrict__ bias, float* __restrict__ outp)
{
    extern __shared__ char gsm[];
    const uint32_t sb = smem_u32(gsm);

    const int tid  = threadIdx.x;
    const int w    = tid >> 5;
    const int lane = tid & 31;
    const int m0 = blockIdx.y * BM;
    const int n0 = blockIdx.x * BN;
    const int wm = (w >> 2) * 64;
    const int wn = (w & 3) * 32;

    // A staging: 1024 16B-segments (128 rows x 8), 4 per thread
    const int arow_s = tid >> 1;                 // handled via loop below
    (void)arow_s;
    // B staging: 1024 16B-segments (64 k-rows x 16), 4 per thread

    auto load_stage = [&](int kt, int stg) {
        const uint32_t s0 = sb + stg * STG_BYTES;
#pragma unroll
        for (int i = 0; i < 4; ++i) {
            const int c = tid + i * 256;          // 0..1023
            const int row = c >> 3, seg = c & 7;  // A: 128 rows x 8 segs
            cp16(s0 + row * ROWB + seg * 16,
                 A + (size_t)(m0 + row) * KTOT + kt * BK + seg * 8);
            const int kr = c >> 4, bs = c & 15;   // B: 64 k-rows x 16 segs
            cp16(s0 + OFF_B + kr * ROWBB + bs * 16,
                 B + (size_t)(kt * BK + kr) * NB + n0 + bs * 8);
        }
    };

    float acc[4][4][4];
#pragma unroll
    for (int i = 0; i < 4; ++i)
#pragma unroll
        for (int j = 0; j < 4; ++j)
#pragma unroll
            for (int e = 0; e < 4; ++e) acc[i][j][e] = 0.f;

    const int ar = lane & 15, ah = lane >> 4;
    const uint32_t aoffb = (uint32_t)((wm + ar) * ROWB + ah * 16);
    const uint32_t boffb = (uint32_t)((((lane & 7) + ((lane >> 3) & 1) * 8) * ROWBB) +
                                      (wn + ((lane >> 4) & 1) * 8) * 2);

    load_stage(0, 0);
    cp_commit();
    load_stage(1, 1);
    cp_commit();

    int stg = 0;
    for (int kt = 0; kt < NKT; ++kt) {
        if (kt + 1 < NKT) cp_wait<1>(); else cp_wait<0>();
        __syncthreads();

        if (kt + 2 < NKT) {
            int s2 = stg + 2; if (s2 >= NSTAGE) s2 -= NSTAGE;
            load_stage(kt + 2, s2);
            cp_commit();
        }

        const uint32_t s0 = sb + stg * STG_BYTES;
#pragma unroll
        for (int ks = 0; ks < 4; ++ks) {          // 4 x k16 inside BK=64
            const uint32_t akoff = s0 + aoffb + ks * 32;
            const uint32_t bkoff = s0 + OFF_B + boffb + ks * 16 * ROWBB;

            uint32_t fa[4][4];
#pragma unroll
            for (int mt = 0; mt < 4; ++mt)
                ldsm4(akoff + mt * 16 * ROWB,
                      fa[mt][0], fa[mt][1], fa[mt][2], fa[mt][3]);
            uint32_t fb[8];
            ldsm4t(bkoff,      fb[0], fb[1], fb[2], fb[3]);
            ldsm4t(bkoff + 32, fb[4], fb[5], fb[6], fb[7]);

#pragma unroll
            for (int mt = 0; mt < 4; ++mt)
#pragma unroll
                for (int nt = 0; nt < 4; ++nt)
                    mma_f16(acc[mt][nt][0], acc[mt][nt][1], acc[mt][nt][2], acc[mt][nt][3],
                            fa[mt][0], fa[mt][1], fa[mt][2], fa[mt][3],
                            fb[nt * 2], fb[nt * 2 + 1]);
        }
        if (++stg >= NSTAGE) stg = 0;
    }

    // epilogue
    const int erow = (lane >> 2);
    const int ecol = (lane & 3) * 2;
#pragma unroll
    for (int mt = 0; mt < 4; ++mt) {
#pragma unroll
        for (int nt = 0; nt < 4; ++nt) {
#pragma unroll
            for (int half = 0; half < 2; ++half) {
                const int row = m0 + wm + mt * 16 + erow + half * 8;
                const int col = n0 + wn + nt * 8 + ecol;
                float v0 = acc[mt][nt][half * 2 + 0] + bias[col];
                float v1 = acc[mt][nt][half * 2 + 1] + bias[col + 1];
                if (MODE == 0) {
                    const int bb = row >> 11, s = row & 2047;
                    const int part = col >> 10;
                    const int dd = col & 1023;
                    const int h = dd >> 6, hd = dd & 63;
                    const int bh = (bb << 4) + h;
                    if (part == 0) { v0 *= 0.125f; v1 *= 0.125f; }
                    const size_t base = ((size_t)bh * SEQ + s) * DHEAD + hd;
                    __half* dst = (part == 0) ? s_q : ((part == 1) ? s_k : s_v);
                    *(uint32_t*)(dst + base) = packh_f(v0, v1);
                } else {
                    *(float2*)(outp + (size_t)row * DIM + col) = make_float2(v0, v1);
                }
            }
        }
    }
}

// ---------------------------------------------------------------------------
// Tensor-core flash attention (unchanged from R15 — validated).
// All-single fp16, fp32 softmax; V natural [s,dh] via trans-ldsm;
// 3-stage KV ring, 1 barrier/tile, 3 CTAs/SM, heavy-first scheduling.
// ---------------------------------------------------------------------------
#define AROWB 144
#define AQ 0
#define AKV0 18432
#define AKV_STG 18432
#define AV_OFF 9216
#define ASM_BYTES (AKV0 + 3 * AKV_STG)   // 73728; x3 CTAs = 216KB/SM

__global__ __launch_bounds__(128, 3) void attn_tc_kernel()
{
    extern __shared__ char asmem[];
    const uint32_t sb = smem_u32(asmem);
    const int tid  = threadIdx.x;
    const int w    = tid >> 5;
    const int lane = tid & 31;
    const int qt   = (int)(gridDim.x - 1) - (int)blockIdx.x;
    const int bh   = blockIdx.y;
    const int q0   = qt * 128;

    const __half* Qg = s_q + (size_t)bh * SEQ * DHEAD;
    const __half* Kg = s_k + (size_t)bh * SEQ * DHEAD;
    const __half* Vg = s_v + (size_t)bh * SEQ * DHEAD;

    auto load_kv = [&](int kt, int stg) {
        const uint32_t s0 = sb + AKV0 + stg * AKV_STG;
        const int kv0 = kt * 64;
#pragma unroll
        for (int i = 0; i < 4; ++i) {
            const int c = tid + i * 128;
            const int row = c >> 3, seg = c & 7;
            const uint32_t so = row * AROWB + seg * 16;
            const size_t g = (size_t)(kv0 + row) * DHEAD + seg * 8;
            cp16(s0 + so, Kg + g);
            cp16(s0 + AV_OFF + so, Vg + g);
        }
    };

#pragma unroll
    for (int i = 0; i < 8; ++i) {
        const int c = tid + i * 128;
        const int row = c >> 3, seg = c & 7;
        const uint32_t so = row * AROWB + seg * 16;
        const size_t go = (size_t)(q0 + row) * DHEAD + seg * 8;
        *(uint4*)(asmem + AQ + so) = *(const uint4*)(Qg + go);
    }

    const int ar = lane & 15, ahh = lane >> 4;
    const int grp = lane >> 3, l8 = lane & 7;
    const int row0 = lane >> 2, coll = (lane & 3) * 2;
    const int trow = (lane & 7) + ((lane >> 3) & 1) * 8;
    const uint32_t tcol = ((lane >> 4) & 1) * 16;

    float m_run[4], l_run[4];
#pragma unroll
    for (int i = 0; i < 4; ++i) { m_run[i] = -1e30f; l_run[i] = 0.f; }
    float oacc[2][8][4];
#pragma unroll
    for (int mt = 0; mt < 2; ++mt)
#pragma unroll
        for (int nt = 0; nt < 8; ++nt)
#pragma unroll
            for (int e = 0; e < 4; ++e) oacc[mt][nt][e] = 0.f;

    const int ntiles = qt * 2 + 2;
    load_kv(0, 0);
    cp_commit();
    if (1 < ntiles) { load_kv(1, 1); cp_commit(); }

    int stg = 0;
    for (int kt = 0; kt < ntiles; ++kt) {
        if (kt + 1 < ntiles) cp_wait<1>(); else cp_wait<0>();
        __syncthreads();

        if (kt + 2 < ntiles) {
            int s2 = stg + 2; if (s2 >= NSTAGE) s2 -= NSTAGE;
            load_kv(kt + 2, s2);
            cp_commit();
        }

        const uint32_t kvb = sb + AKV0 + stg * AKV_STG;
        const int kv0 = kt * 64;

        float s[2][8][4];
#pragma unroll
        for (int mt = 0; mt < 2; ++mt)
#pragma unroll
            for (int nt = 0; nt < 8; ++nt)
#pragma unroll
                for (int e = 0; e < 4; ++e) s[mt][nt][e] = 0.f;

#pragma unroll
        for (int ks = 0; ks < 4; ++ks) {
            uint32_t kb[4][4];
#pragma unroll
            for (int nb = 0; nb < 4; ++nb) {
                const uint32_t bo = (uint32_t)(((grp >> 1) * 8 + l8 + nb * 16) * AROWB +
                                               (grp & 1) * 16 + ks * 32);
                ldsm4(kvb + bo, kb[nb][0], kb[nb][1], kb[nb][2], kb[nb][3]);
            }
            uint32_t qf[2][4];
#pragma unroll
            for (int mt = 0; mt < 2; ++mt) {
                const uint32_t ao = (uint32_t)((w * 32 + mt * 16 + ar) * AROWB +
                                               ahh * 16 + ks * 32);
                ldsm4(sb + AQ + ao, qf[mt][0], qf[mt][1], qf[mt][2], qf[mt][3]);
            }
#pragma unroll
            for (int mt = 0; mt < 2; ++mt)
#pragma unroll
                for (int nt = 0; nt < 8; ++nt) {
                    const int nb = nt >> 1, p = nt & 1;
                    mma_f16(s[mt][nt][0], s[mt][nt][1], s[mt][nt][2], s[mt][nt][3],
                            qf[mt][0], qf[mt][1], qf[mt][2], qf[mt][3],
                            kb[nb][p * 2], kb[nb][p * 2 + 1]);
                }
        }

        if (kt >= qt * 2) {
#pragma unroll
            for (int mt = 0; mt < 2; ++mt) {
                const int rbase = q0 + w * 32 + mt * 16 + row0;
#pragma unroll
                for (int nt = 0; nt < 8; ++nt) {
                    const int cb = kv0 + nt * 8 + coll;
                    if (cb > rbase)     s[mt][nt][0] = -10000.f;
                    if (cb + 1 > rbase) s[mt][nt][1] = -10000.f;
                    if (cb > rbase + 8)     s[mt][nt][2] = -10000.f;
                    if (cb + 1 > rbase + 8) s[mt][nt][3] = -10000.f;
                }
            }
        }

        float corr[4];
#pragma unroll
        for (int slot = 0; slot < 4; ++slot) {
            const int mt = slot >> 1, h2 = slot & 1;
            float tm = -1e30f;
#pragma unroll
            for (int nt = 0; nt < 8; ++nt)
                tm = fmaxf(tm, fmaxf(s[mt][nt][h2 * 2], s[mt][nt][h2 * 2 + 1]));
            tm = fmaxf(tm, __shfl_xor_sync(0xffffffffu, tm, 1));
            tm = fmaxf(tm, __shfl_xor_sync(0xffffffffu, tm, 2));
            const float mnew = fmaxf(m_run[slot], tm);
            corr[slot] = __expf(m_run[slot] - mnew);
            m_run[slot] = mnew;
            l_run[slot] *= corr[slot];
        }
#pragma unroll
        for (int mt = 0; mt < 2; ++mt)
#pragma unroll
            for (int nt = 0; nt < 8; ++nt) {
                oacc[mt][nt][0] *= corr[mt * 2];
                oacc[mt][nt][1] *= corr[mt * 2];
                oacc[mt][nt][2] *= corr[mt * 2 + 1];
                oacc[mt][nt][3] *= corr[mt * 2 + 1];
            }

        uint32_t pf[2][8][2];
#pragma unroll
        for (int mt = 0; mt < 2; ++mt)
#pragma unroll
            for (int nt = 0; nt < 8; ++nt) {
                const float p0 = __expf(s[mt][nt][0] - m_run[mt * 2]);
                const float p1 = __expf(s[mt][nt][1] - m_run[mt * 2]);
                const float p2 = __expf(s[mt][nt][2] - m_run[mt * 2 + 1]);
                const float p3 = __expf(s[mt][nt][3] - m_run[mt * 2 + 1]);
                l_run[mt * 2]     += p0 + p1;
                l_run[mt * 2 + 1] += p2 + p3;
                pf[mt][nt][0] = packh_f(p0, p1);
                pf[mt][nt][1] = packh_f(p2, p3);
            }

#pragma unroll
        for (int ks = 0; ks < 4; ++ks) {
            uint32_t vb[4][4];
#pragma unroll
            for (int nb = 0; nb < 4; ++nb) {
                const uint32_t bo = (uint32_t)((trow + ks * 16) * AROWB + tcol + nb * 32);
                ldsm4t(kvb + AV_OFF + bo, vb[nb][0], vb[nb][1], vb[nb][2], vb[nb][3]);
            }
#pragma unroll
            for (int mt = 0; mt < 2; ++mt)
#pragma unroll
                for (int nt = 0; nt < 8; ++nt) {
                    const int nb = nt >> 1, p = nt & 1;
                    mma_f16(oacc[mt][nt][0], oacc[mt][nt][1], oacc[mt][nt][2], oacc[mt][nt][3],
                            pf[mt][ks * 2][0], pf[mt][ks * 2][1],
                            pf[mt][ks * 2 + 1][0], pf[mt][ks * 2 + 1][1],
                            vb[nb][p * 2], vb[nb][p * 2 + 1]);
                }
        }
        if (++stg >= NSTAGE) stg = 0;
    }

    float inv[4];
#pragma unroll
    for (int slot = 0; slot < 4; ++slot) {
        float lt = l_run[slot];
        lt += __shfl_xor_sync(0xffffffffu, lt, 1);
        lt += __shfl_xor_sync(0xffffffffu, lt, 2);
        inv[slot] = 1.f / lt;
    }
    const int b = bh >> 4, h = bh & 15;
#pragma unroll
    for (int mt = 0; mt < 2; ++mt) {
#pragma unroll
        for (int half = 0; half < 2; ++half) {
            const size_t orow = (size_t)b * SEQ + q0 + w * 32 + mt * 16 + row0 + half * 8;
            const float iv = inv[mt * 2 + half];
#pragma unroll
            for (int nt = 0; nt < 8; ++nt) {
                const int col = h * DHEAD + nt * 8 + coll;
                const float v0 = oacc[mt][nt][half * 2 + 0] * iv;
                const float v1 = oacc[mt][nt][half * 2 + 1] * iv;
                *(uint32_t*)(s_a + orow * DIM + col) = packh_f(v0, v1);
            }
        }
    }
}

// ---------------------------------------------------------------------------
extern "C" void kernel_launch(void* const* d_in, const int* in_sizes, int n_in,
                              void* d_out, int out_size)
{
    const float* x      = (const float*)d_in[0];
    const float* w_attn = (const float*)d_in[1];
    const float* b_attn = (const float*)d_in[2];
    const float* w_proj = (const float*)d_in[3];
    const float* b_proj = (const float*)d_in[4];
    float* out = (float*)d_out;

    __half *xa, *wq, *wp;
    cudaGetSymbolAddress((void**)&xa, s_a);
    cudaGetSymbolAddress((void**)&wq, s_wq);
    cudaGetSymbolAddress((void**)&wp, s_wp);

    cudaFuncSetAttribute((tc_gemm_kernel<0, NQKV>),
                         cudaFuncAttributeMaxDynamicSharedMemorySize, GSM_BYTES);
    cudaFuncSetAttribute((tc_gemm_kernel<1, DIM>),
                         cudaFuncAttributeMaxDynamicSharedMemorySize, GSM_BYTES);
    cudaFuncSetAttribute(attn_tc_kernel,
                         cudaFuncAttributeMaxDynamicSharedMemorySize, ASM_BYTES);

    // 1) fused convert: x, w_attn, w_proj -> fp16
    const int total4 = XN4 + WAN4 + WPN4;
    convert_all_kernel<<<(total4 + 255) / 256, 256>>>(x, w_attn, w_proj, xa, wq, wp);
    // 2) QKV GEMM (BK=64) -> q/k/v fp16 [bh,s,dh]
    tc_gemm_kernel<0, NQKV><<<dim3(NQKV / BN, MROWS / BM), 256, GSM_BYTES>>>(
        xa, wq, b_attn, nullptr);
    // 3) tensor-core flash attention -> writes s_a (fp16)
    attn_tc_kernel<<<dim3(SEQ / 128, BATCH * NHEAD), 128, ASM_BYTES>>>();
    // 4) output projection (BK=64)
    tc_gemm_kernel<1, DIM><<<dim3(DIM / BN, MROWS / BM), 256, GSM_BYTES>>>(
        xa, wp, b_proj, out);
}